// round 4
// baseline (speedup 1.0000x reference)
#include <cuda_runtime.h>
#include <cuda_bf16.h>
#include <math.h>
#include <stdint.h>

#define M_TOK   100352
#define C_DIM   192
#define NHEADS  6
#define HDIM    32
#define HIDDEN  768

// GEMM tiling: CTA 128x96, BK=32, 512 threads (16 warps 4x4), warp tile 32x24
#define BM 128
#define BN 96
#define BK 32
#define RPB 80                 // smem row pitch bytes (40 bf16)
#define OFF_AH 0
#define OFF_AL (BM*RPB)                 // 10240
#define OFF_BH (2*BM*RPB)               // 20480
#define OFF_BL (2*BM*RPB + BN*RPB)      // 28160
#define STAGE_BYTES (2*BM*RPB + 2*BN*RPB)   // 35840

// ---------------- scratch ----------------
__device__ __nv_bfloat16 g_xw_h [(size_t)M_TOK * C_DIM];
__device__ __nv_bfloat16 g_xw_l [(size_t)M_TOK * C_DIM];
__device__ float         g_qkv  [(size_t)M_TOK * 3 * C_DIM];
__device__ __nv_bfloat16 g_att_h[(size_t)M_TOK * C_DIM];
__device__ __nv_bfloat16 g_att_l[(size_t)M_TOK * C_DIM];
__device__ float         g_x    [(size_t)M_TOK * C_DIM];
__device__ __nv_bfloat16 g_ln2_h[(size_t)M_TOK * C_DIM];
__device__ __nv_bfloat16 g_ln2_l[(size_t)M_TOK * C_DIM];
__device__ __nv_bfloat16 g_h_h  [(size_t)M_TOK * HIDDEN];
__device__ __nv_bfloat16 g_h_l  [(size_t)M_TOK * HIDDEN];
__device__ __nv_bfloat16 g_wqkv_h[576 * 192], g_wqkv_l[576 * 192];
__device__ __nv_bfloat16 g_wprj_h[192 * 192], g_wprj_l[192 * 192];
__device__ __nv_bfloat16 g_wfc1_h[768 * 192], g_wfc1_l[768 * 192];
__device__ __nv_bfloat16 g_wfc2_h[192 * 768], g_wfc2_l[192 * 768];

// ---------------- helpers ----------------
__device__ __forceinline__ uint32_t smem_u32(const void* p) {
    uint32_t a;
    asm("{ .reg .u64 t; cvta.to.shared.u64 t, %1; cvt.u32.u64 %0, t; }" : "=r"(a) : "l"(p));
    return a;
}
__device__ __forceinline__ void cp16(uint32_t sa, const void* g) {
    asm volatile("cp.async.cg.shared.global [%0], [%1], 16;" :: "r"(sa), "l"(g));
}
__device__ __forceinline__ void cp_commit() { asm volatile("cp.async.commit_group;"); }
template <int N>
__device__ __forceinline__ void cp_wait() { asm volatile("cp.async.wait_group %0;" :: "n"(N)); }

__device__ __forceinline__ void ldsm_x4(uint32_t* r, uint32_t addr) {
    asm volatile("ldmatrix.sync.aligned.m8n8.x4.shared.b16 {%0,%1,%2,%3}, [%4];"
        : "=r"(r[0]), "=r"(r[1]), "=r"(r[2]), "=r"(r[3]) : "r"(addr));
}
__device__ __forceinline__ void ldsm_x2(uint32_t* r, uint32_t addr) {
    asm volatile("ldmatrix.sync.aligned.m8n8.x2.shared.b16 {%0,%1}, [%2];"
        : "=r"(r[0]), "=r"(r[1]) : "r"(addr));
}
__device__ __forceinline__ void mma16816(float* c, const uint32_t* a, const uint32_t* b) {
    asm volatile("mma.sync.aligned.m16n8k16.row.col.f32.bf16.bf16.f32 "
        "{%0,%1,%2,%3}, {%4,%5,%6,%7}, {%8,%9}, {%0,%1,%2,%3};"
        : "+f"(c[0]), "+f"(c[1]), "+f"(c[2]), "+f"(c[3])
        : "r"(a[0]), "r"(a[1]), "r"(a[2]), "r"(a[3]), "r"(b[0]), "r"(b[1]));
}
__device__ __forceinline__ void split2(float v, __nv_bfloat16& h, __nv_bfloat16& l) {
    h = __float2bfloat16(v);
    l = __float2bfloat16(v - __bfloat162float(h));
}
__device__ __forceinline__ float gelu_exact(float v) {
    return 0.5f * v * (1.0f + erff(v * 0.70710678118654752f));
}
__device__ __forceinline__ float warp_sum(float v) {
#pragma unroll
    for (int o = 16; o > 0; o >>= 1) v += __shfl_xor_sync(0xffffffffu, v, o);
    return v;
}
__device__ __forceinline__ float warp_max(float v) {
#pragma unroll
    for (int o = 16; o > 0; o >>= 1) v = fmaxf(v, __shfl_xor_sync(0xffffffffu, v, o));
    return v;
}
__device__ __forceinline__ int scatter_dst(int row) {
    int w = row / 49, n = row % 49;
    int bb = w >> 8, rr = w & 255;
    int wi = rr >> 4, wj = rr & 15;
    int i = n / 7, j = n % 7;
    int hh = wi * 7 + i + 3; if (hh >= 112) hh -= 112;
    int ww = wj * 7 + j + 3; if (ww >= 112) ww -= 112;
    return bb * 12544 + hh * 112 + ww;
}

// ---------------- weight transpose + split ----------------
__global__ void wprep_kernel(const float* __restrict__ W, __nv_bfloat16* __restrict__ Th,
                             __nv_bfloat16* __restrict__ Tl, int K, int N) {
    int i = blockIdx.x * 256 + threadIdx.x;
    if (i >= K * N) return;
    int k = i / N, n = i - k * N;
    __nv_bfloat16 h, l;
    split2(W[i], h, l);
    Th[(size_t)n * K + k] = h;
    Tl[(size_t)n * K + k] = l;
}

// ---------------- LayerNorm (+ optional shift/window gather) ----------------
template <bool GATHER>
__global__ void ln_kernel(const float* __restrict__ in,
                          const float* __restrict__ gamma, const float* __restrict__ beta,
                          __nv_bfloat16* __restrict__ oh, __nv_bfloat16* __restrict__ ol) {
    int t = blockIdx.x, c = threadIdx.x;
    int src = GATHER ? scatter_dst(t) : t;
    float v = in[(size_t)src * C_DIM + c];
    __shared__ float s1[6], s2[6];
    int wid = c >> 5, lid = c & 31;
    float s = warp_sum(v);
    if (lid == 0) s1[wid] = s;
    __syncthreads();
    float mean = (s1[0] + s1[1] + s1[2] + s1[3] + s1[4] + s1[5]) * (1.0f / 192.0f);
    float d = v - mean;
    float sq = warp_sum(d * d);
    if (lid == 0) s2[wid] = sq;
    __syncthreads();
    float var = (s2[0] + s2[1] + s2[2] + s2[3] + s2[4] + s2[5]) * (1.0f / 192.0f);
    float o = d * rsqrtf(var + 1e-5f) * gamma[c] + beta[c];
    __nv_bfloat16 h, l;
    split2(o, h, l);
    oh[(size_t)t * C_DIM + c] = h;
    ol[(size_t)t * C_DIM + c] = l;
}

// ---------------- HMMA split-bf16 GEMM (128x96 CTA, 512 thr, ldmatrix) ----------------
enum { EPI_F32 = 0, EPI_GELU = 1, EPI_SCATTER = 2, EPI_RES = 3 };

template <int EPI>
__global__ __launch_bounds__(512, 1)
void gemm_mma(const __nv_bfloat16* __restrict__ Ah, const __nv_bfloat16* __restrict__ Al,
              const __nv_bfloat16* __restrict__ Bh, const __nv_bfloat16* __restrict__ Bl,
              const float* __restrict__ bias, const float* __restrict__ res,
              float* __restrict__ outf, __nv_bfloat16* __restrict__ outh,
              __nv_bfloat16* __restrict__ outl, int K, int Nout) {
    extern __shared__ __align__(16) char smem[];
    int tid = threadIdx.x;
    int wid = tid >> 5, lid = tid & 31;
    int wm = wid & 3, wn = wid >> 2;            // 4 x 4 warps
    int mBase = blockIdx.y * BM;
    int nBase = blockIdx.x * BN;
    uint32_t sb = smem_u32(smem);

    float acc[2][3][4];
#pragma unroll
    for (int a = 0; a < 2; a++)
#pragma unroll
        for (int b = 0; b < 3; b++)
#pragma unroll
            for (int c = 0; c < 4; c++) acc[a][b][c] = 0.0f;

    int nch = K / BK;

    auto issue = [&](int c) {
        uint32_t sbase = sb + (c & 1) * STAGE_BYTES;
        int k0 = c * BK;
#pragma unroll
        for (int u = 0; u < 4; u++) {
            int ch = tid + u * 512;
            if (ch >= 1792) break;
            if (ch < 512) {
                int r = ch >> 2, cc = ch & 3;
                cp16(sbase + OFF_AH + r * RPB + cc * 16,
                     Ah + (size_t)(mBase + r) * K + k0 + cc * 8);
            } else if (ch < 1024) {
                int q = ch - 512, r = q >> 2, cc = q & 3;
                cp16(sbase + OFF_AL + r * RPB + cc * 16,
                     Al + (size_t)(mBase + r) * K + k0 + cc * 8);
            } else if (ch < 1408) {
                int q = ch - 1024, r = q >> 2, cc = q & 3;
                cp16(sbase + OFF_BH + r * RPB + cc * 16,
                     Bh + (size_t)(nBase + r) * K + k0 + cc * 8);
            } else {
                int q = ch - 1408, r = q >> 2, cc = q & 3;
                cp16(sbase + OFF_BL + r * RPB + cc * 16,
                     Bl + (size_t)(nBase + r) * K + k0 + cc * 8);
            }
        }
        cp_commit();
    };

    // per-lane ldmatrix address components
    int aRow = wm * 32 + (lid & 7) + ((lid >> 3) & 1) * 8;     // + mt*16
    int aKof = (lid >> 4) * 16;                                 // + kb
    int bRow4 = wn * 24 + (lid & 7) + ((lid >> 4) & 1) * 8;     // x4: nt0/nt1
    int bRow2 = wn * 24 + 16 + (lid & 7);                       // x2: nt2 (lanes<16)
    int bKof4 = ((lid >> 3) & 1) * 16;
    int bKof2 = (((lid & 15) >> 3) & 1) * 16;

    issue(0);
    for (int c = 0; c < nch; c++) {
        if (c + 1 < nch) { issue(c + 1); cp_wait<1>(); }
        else             { cp_wait<0>(); }
        __syncthreads();

        uint32_t buf = sb + (c & 1) * STAGE_BYTES;
#pragma unroll
        for (int kb = 0; kb < 64; kb += 32) {   // two k16 steps (bytes)
            uint32_t ahf[2][4], alf[2][4], bh4[4], bl4[4], bh2[2], bl2[2];
#pragma unroll
            for (int mt = 0; mt < 2; mt++) {
                uint32_t ad = buf + (aRow + mt * 16) * RPB + kb + aKof;
                ldsm_x4(ahf[mt], ad + OFF_AH);
                ldsm_x4(alf[mt], ad + OFF_AL);
            }
            {
                uint32_t bd4 = buf + bRow4 * RPB + kb + bKof4;
                uint32_t bd2 = buf + bRow2 * RPB + kb + bKof2;
                ldsm_x4(bh4, bd4 + OFF_BH);
                ldsm_x2(bh2, bd2 + OFF_BH);
                ldsm_x4(bl4, bd4 + OFF_BL);
                ldsm_x2(bl2, bd2 + OFF_BL);
            }
            uint32_t* bhf[3] = { bh4, bh4 + 2, bh2 };
            uint32_t* blf[3] = { bl4, bl4 + 2, bl2 };
#pragma unroll
            for (int mt = 0; mt < 2; mt++)
#pragma unroll
                for (int nt = 0; nt < 3; nt++) {
                    mma16816(acc[mt][nt], ahf[mt], bhf[nt]);
                    mma16816(acc[mt][nt], ahf[mt], blf[nt]);
                    mma16816(acc[mt][nt], alf[mt], bhf[nt]);
                }
        }
        __syncthreads();
    }

    // ---- epilogue ----
    int g = lid >> 2, tq = lid & 3;
#pragma unroll
    for (int mt = 0; mt < 2; mt++) {
#pragma unroll
        for (int half = 0; half < 2; half++) {
            int row = mBase + wm * 32 + mt * 16 + g + half * 8;
            int dst = (EPI == EPI_SCATTER) ? scatter_dst(row) : row;
#pragma unroll
            for (int nt = 0; nt < 3; nt++) {
                int col = nBase + wn * 24 + nt * 8 + tq * 2;
                float v0 = acc[mt][nt][half * 2 + 0] + bias[col];
                float v1 = acc[mt][nt][half * 2 + 1] + bias[col + 1];
                if (EPI == EPI_GELU) {
                    v0 = gelu_exact(v0); v1 = gelu_exact(v1);
                    __nv_bfloat16 h0, l0, h1, l1;
                    split2(v0, h0, l0); split2(v1, h1, l1);
                    __nv_bfloat162 hp; hp.x = h0; hp.y = h1;
                    __nv_bfloat162 lp; lp.x = l0; lp.y = l1;
                    *(__nv_bfloat162*)(outh + (size_t)row * Nout + col) = hp;
                    *(__nv_bfloat162*)(outl + (size_t)row * Nout + col) = lp;
                } else if (EPI == EPI_SCATTER || EPI == EPI_RES) {
                    size_t o = (size_t)dst * Nout + col;
                    float2 rv = *(const float2*)(res + o);
                    float2 w; w.x = v0 + rv.x; w.y = v1 + rv.y;
                    *(float2*)(outf + o) = w;
                } else {
                    float2 w; w.x = v0; w.y = v1;
                    *(float2*)(outf + (size_t)row * Nout + col) = w;
                }
            }
        }
    }
}

// ---------------- Windowed attention ----------------
__global__ void attn_kernel(const float* __restrict__ qkv,
                            const float* __restrict__ rpb,
                            __nv_bfloat16* __restrict__ oh, __nv_bfloat16* __restrict__ ol) {
    int blk = blockIdx.x;
    int w = blk / NHEADS;
    int h = blk - w * NHEADS;

    __shared__ float sq[49][36], sk[49][36], sv[49][36];
    __shared__ float sa[49][49];

    int tid = threadIdx.x;
    const float scale = 0.17677669529663687f;

    for (int idx = tid; idx < 49 * 32; idx += 256) {
        int n = idx >> 5, d = idx & 31;
        size_t base = ((size_t)(w * 49 + n)) * (3 * C_DIM) + h * HDIM + d;
        sq[n][d] = qkv[base] * scale;
        sk[n][d] = qkv[base + C_DIM];
        sv[n][d] = qkv[base + 2 * C_DIM];
    }
    __syncthreads();

    int r = w & 255;
    int wi = r >> 4, wj = r & 15;

    for (int e = tid; e < 49 * 49; e += 256) {
        int n = e / 49, m = e - n * 49;
        const float4* q4 = (const float4*)sq[n];
        const float4* k4 = (const float4*)sk[m];
        float dot = 0.0f;
#pragma unroll
        for (int d = 0; d < 8; d++) {
            float4 qa = q4[d], ka = k4[d];
            dot = fmaf(qa.x, ka.x, dot);
            dot = fmaf(qa.y, ka.y, dot);
            dot = fmaf(qa.z, ka.z, dot);
            dot = fmaf(qa.w, ka.w, dot);
        }
        int i1 = n / 7, j1 = n % 7, i2 = m / 7, j2 = m % 7;
        float b = rpb[((i1 - i2 + 6) * 13 + (j1 - j2 + 6)) * NHEADS + h];
        int hp1 = wi * 7 + i1, wp1 = wj * 7 + j1;
        int hp2 = wi * 7 + i2, wp2 = wj * 7 + j2;
        int reg1 = (hp1 < 105 ? 0 : (hp1 < 109 ? 1 : 2)) * 3 + (wp1 < 105 ? 0 : (wp1 < 109 ? 1 : 2));
        int reg2 = (hp2 < 105 ? 0 : (hp2 < 109 ? 1 : 2)) * 3 + (wp2 < 105 ? 0 : (wp2 < 109 ? 1 : 2));
        sa[n][m] = dot + b + (reg1 == reg2 ? 0.0f : -100.0f);
    }
    __syncthreads();

    int wid = tid >> 5, lid = tid & 31;
    for (int n = wid; n < 49; n += 8) {
        float v1 = sa[n][lid];
        float v2 = (lid < 17) ? sa[n][lid + 32] : -1e30f;
        float mx = warp_max(fmaxf(v1, v2));
        float e1 = __expf(v1 - mx);
        float e2 = (lid < 17) ? __expf(v2 - mx) : 0.0f;
        float s = warp_sum(e1 + e2);
        float inv = 1.0f / s;
        sa[n][lid] = e1 * inv;
        if (lid < 17) sa[n][lid + 32] = e2 * inv;
    }
    __syncthreads();

    for (int idx = tid; idx < 49 * 8; idx += 256) {
        int n = idx >> 3, d4 = idx & 7;
        float4 o = make_float4(0.f, 0.f, 0.f, 0.f);
#pragma unroll 7
        for (int m = 0; m < 49; m++) {
            float a = sa[n][m];
            float4 v = ((const float4*)sv[m])[d4];
            o.x = fmaf(a, v.x, o.x);
            o.y = fmaf(a, v.y, o.y);
            o.z = fmaf(a, v.z, o.z);
            o.w = fmaf(a, v.w, o.w);
        }
        size_t oidx = ((size_t)(w * 49 + n)) * C_DIM + h * HDIM + d4 * 4;
        __nv_bfloat16 h0, l0, h1, l1, h2, l2, h3, l3;
        split2(o.x, h0, l0); split2(o.y, h1, l1);
        split2(o.z, h2, l2); split2(o.w, h3, l3);
        __nv_bfloat162 hp0; hp0.x = h0; hp0.y = h1;
        __nv_bfloat162 hp1; hp1.x = h2; hp1.y = h3;
        __nv_bfloat162 lp0; lp0.x = l0; lp0.y = l1;
        __nv_bfloat162 lp1; lp1.x = l2; lp1.y = l3;
        *(__nv_bfloat162*)(oh + oidx) = hp0;
        *(__nv_bfloat162*)(oh + oidx + 2) = hp1;
        *(__nv_bfloat162*)(ol + oidx) = lp0;
        *(__nv_bfloat162*)(ol + oidx + 2) = lp1;
    }
}

// ---------------- launch ----------------
extern "C" void kernel_launch(void* const* d_in, const int* in_sizes, int n_in,
                              void* d_out, int out_size) {
    const float* query   = (const float*)d_in[0];
    const float* norm1_g = (const float*)d_in[1];
    const float* norm1_b = (const float*)d_in[2];
    const float* qkv_w   = (const float*)d_in[3];
    const float* qkv_b   = (const float*)d_in[4];
    const float* rpb     = (const float*)d_in[5];
    const float* proj_w  = (const float*)d_in[6];
    const float* proj_b  = (const float*)d_in[7];
    const float* norm2_g = (const float*)d_in[8];
    const float* norm2_b = (const float*)d_in[9];
    const float* fc1_w   = (const float*)d_in[10];
    const float* fc1_b   = (const float*)d_in[11];
    const float* fc2_w   = (const float*)d_in[12];
    const float* fc2_b   = (const float*)d_in[13];
    float* out = (float*)d_out;

    __nv_bfloat16 *xwh, *xwl, *atth, *attl, *ln2h, *ln2l, *hh, *hl;
    __nv_bfloat16 *wqh, *wql, *wph, *wpl, *w1h, *w1l, *w2h, *w2l;
    float *qkvp, *x;
    cudaGetSymbolAddress((void**)&xwh, g_xw_h);   cudaGetSymbolAddress((void**)&xwl, g_xw_l);
    cudaGetSymbolAddress((void**)&qkvp, g_qkv);
    cudaGetSymbolAddress((void**)&atth, g_att_h); cudaGetSymbolAddress((void**)&attl, g_att_l);
    cudaGetSymbolAddress((void**)&x, g_x);
    cudaGetSymbolAddress((void**)&ln2h, g_ln2_h); cudaGetSymbolAddress((void**)&ln2l, g_ln2_l);
    cudaGetSymbolAddress((void**)&hh, g_h_h);     cudaGetSymbolAddress((void**)&hl, g_h_l);
    cudaGetSymbolAddress((void**)&wqh, g_wqkv_h); cudaGetSymbolAddress((void**)&wql, g_wqkv_l);
    cudaGetSymbolAddress((void**)&wph, g_wprj_h); cudaGetSymbolAddress((void**)&wpl, g_wprj_l);
    cudaGetSymbolAddress((void**)&w1h, g_wfc1_h); cudaGetSymbolAddress((void**)&w1l, g_wfc1_l);
    cudaGetSymbolAddress((void**)&w2h, g_wfc2_h); cudaGetSymbolAddress((void**)&w2l, g_wfc2_l);

    const int SMEM = 2 * STAGE_BYTES;   // 71680
    cudaFuncSetAttribute(gemm_mma<EPI_F32>,     cudaFuncAttributeMaxDynamicSharedMemorySize, SMEM);
    cudaFuncSetAttribute(gemm_mma<EPI_GELU>,    cudaFuncAttributeMaxDynamicSharedMemorySize, SMEM);
    cudaFuncSetAttribute(gemm_mma<EPI_SCATTER>, cudaFuncAttributeMaxDynamicSharedMemorySize, SMEM);
    cudaFuncSetAttribute(gemm_mma<EPI_RES>,     cudaFuncAttributeMaxDynamicSharedMemorySize, SMEM);

    wprep_kernel<<<(192 * 576 + 255) / 256, 256>>>(qkv_w,  wqh, wql, 192, 576);
    wprep_kernel<<<(192 * 192 + 255) / 256, 256>>>(proj_w, wph, wpl, 192, 192);
    wprep_kernel<<<(192 * 768 + 255) / 256, 256>>>(fc1_w,  w1h, w1l, 192, 768);
    wprep_kernel<<<(768 * 192 + 255) / 256, 256>>>(fc2_w,  w2h, w2l, 768, 192);

    // 1) LN1 + shift + window partition
    ln_kernel<true><<<M_TOK, 192>>>(query, norm1_g, norm1_b, xwh, xwl);

    // 2) qkv  [100352,192] x [192,576]
    gemm_mma<EPI_F32><<<dim3(576 / BN, M_TOK / BM), 512, SMEM>>>(
        xwh, xwl, wqh, wql, qkv_b, nullptr, qkvp, nullptr, nullptr, 192, 576);

    // 3) windowed attention
    attn_kernel<<<2048 * NHEADS, 256>>>(qkvp, rpb, atth, attl);

    // 4) proj + window reverse + unshift + residual(query)
    gemm_mma<EPI_SCATTER><<<dim3(192 / BN, M_TOK / BM), 512, SMEM>>>(
        atth, attl, wph, wpl, proj_b, query, x, nullptr, nullptr, 192, 192);

    // 5) LN2
    ln_kernel<false><<<M_TOK, 192>>>(x, norm2_g, norm2_b, ln2h, ln2l);

    // 6) fc1 + GELU
    gemm_mma<EPI_GELU><<<dim3(768 / BN, M_TOK / BM), 512, SMEM>>>(
        ln2h, ln2l, w1h, w1l, fc1_b, nullptr, nullptr, hh, hl, 192, 768);

    // 7) fc2 + residual(x) -> out
    gemm_mma<EPI_RES><<<dim3(192 / BN, M_TOK / BM), 512, SMEM>>>(
        hh, hl, w2h, w2l, fc2_b, x, out, nullptr, nullptr, 768, 192);
}

// round 5
// speedup vs baseline: 1.1287x; 1.1287x over previous
#include <cuda_runtime.h>
#include <cuda_bf16.h>
#include <math.h>
#include <stdint.h>

#define M_TOK   100352
#define C_DIM   192
#define NHEADS  6
#define HDIM    32
#define HIDDEN  768

// GEMM tiling: CTA 128x64, BK=32, 256 threads (8 warps 4x2), warp tile 32x32
#define BM 128
#define BN 64
#define BK 32
#define RPB 80                 // smem row pitch bytes (40 bf16)
#define OFF_AH 0
#define OFF_AL (BM*RPB)                 // 10240
#define OFF_BH (2*BM*RPB)               // 20480
#define OFF_BL (2*BM*RPB + BN*RPB)      // 25600
#define STAGE_BYTES (2*BM*RPB + 2*BN*RPB)   // 30720
#define NSTAGE 3

// ---------------- scratch ----------------
__device__ __nv_bfloat16 g_xw_h [(size_t)M_TOK * C_DIM];
__device__ __nv_bfloat16 g_xw_l [(size_t)M_TOK * C_DIM];
__device__ float         g_qkv  [(size_t)M_TOK * 3 * C_DIM];
__device__ __nv_bfloat16 g_att_h[(size_t)M_TOK * C_DIM];
__device__ __nv_bfloat16 g_att_l[(size_t)M_TOK * C_DIM];
__device__ float         g_x    [(size_t)M_TOK * C_DIM];
__device__ __nv_bfloat16 g_ln2_h[(size_t)M_TOK * C_DIM];
__device__ __nv_bfloat16 g_ln2_l[(size_t)M_TOK * C_DIM];
__device__ __nv_bfloat16 g_h_h  [(size_t)M_TOK * HIDDEN];
__device__ __nv_bfloat16 g_h_l  [(size_t)M_TOK * HIDDEN];
__device__ __nv_bfloat16 g_wqkv_h[576 * 192], g_wqkv_l[576 * 192];
__device__ __nv_bfloat16 g_wprj_h[192 * 192], g_wprj_l[192 * 192];
__device__ __nv_bfloat16 g_wfc1_h[768 * 192], g_wfc1_l[768 * 192];
__device__ __nv_bfloat16 g_wfc2_h[192 * 768], g_wfc2_l[192 * 768];

// ---------------- helpers ----------------
__device__ __forceinline__ uint32_t smem_u32(const void* p) {
    uint32_t a;
    asm("{ .reg .u64 t; cvta.to.shared.u64 t, %1; cvt.u32.u64 %0, t; }" : "=r"(a) : "l"(p));
    return a;
}
__device__ __forceinline__ void cp16(uint32_t sa, const void* g) {
    asm volatile("cp.async.cg.shared.global [%0], [%1], 16;" :: "r"(sa), "l"(g));
}
__device__ __forceinline__ void cp_commit() { asm volatile("cp.async.commit_group;"); }
template <int N>
__device__ __forceinline__ void cp_wait() { asm volatile("cp.async.wait_group %0;" :: "n"(N)); }

__device__ __forceinline__ void ldsm_x4(uint32_t* r, uint32_t addr) {
    asm volatile("ldmatrix.sync.aligned.m8n8.x4.shared.b16 {%0,%1,%2,%3}, [%4];"
        : "=r"(r[0]), "=r"(r[1]), "=r"(r[2]), "=r"(r[3]) : "r"(addr));
}
__device__ __forceinline__ void mma16816(float* c, const uint32_t* a, const uint32_t* b) {
    asm volatile("mma.sync.aligned.m16n8k16.row.col.f32.bf16.bf16.f32 "
        "{%0,%1,%2,%3}, {%4,%5,%6,%7}, {%8,%9}, {%0,%1,%2,%3};"
        : "+f"(c[0]), "+f"(c[1]), "+f"(c[2]), "+f"(c[3])
        : "r"(a[0]), "r"(a[1]), "r"(a[2]), "r"(a[3]), "r"(b[0]), "r"(b[1]));
}
__device__ __forceinline__ void split2(float v, __nv_bfloat16& h, __nv_bfloat16& l) {
    h = __float2bfloat16(v);
    l = __float2bfloat16(v - __bfloat162float(h));
}
__device__ __forceinline__ float gelu_exact(float v) {
    return 0.5f * v * (1.0f + erff(v * 0.70710678118654752f));
}
__device__ __forceinline__ float warp_sum(float v) {
#pragma unroll
    for (int o = 16; o > 0; o >>= 1) v += __shfl_xor_sync(0xffffffffu, v, o);
    return v;
}
__device__ __forceinline__ float warp_max(float v) {
#pragma unroll
    for (int o = 16; o > 0; o >>= 1) v = fmaxf(v, __shfl_xor_sync(0xffffffffu, v, o));
    return v;
}
__device__ __forceinline__ int scatter_dst(int row) {
    int w = row / 49, n = row % 49;
    int bb = w >> 8, rr = w & 255;
    int wi = rr >> 4, wj = rr & 15;
    int i = n / 7, j = n % 7;
    int hh = wi * 7 + i + 3; if (hh >= 112) hh -= 112;
    int ww = wj * 7 + j + 3; if (ww >= 112) ww -= 112;
    return bb * 12544 + hh * 112 + ww;
}

// ---------------- weight transpose + split ----------------
__global__ void wprep_kernel(const float* __restrict__ W, __nv_bfloat16* __restrict__ Th,
                             __nv_bfloat16* __restrict__ Tl, int K, int N) {
    int i = blockIdx.x * 256 + threadIdx.x;
    if (i >= K * N) return;
    int k = i / N, n = i - k * N;
    __nv_bfloat16 h, l;
    split2(W[i], h, l);
    Th[(size_t)n * K + k] = h;
    Tl[(size_t)n * K + k] = l;
}

// ---------------- LayerNorm (+ optional shift/window gather) ----------------
template <bool GATHER>
__global__ void ln_kernel(const float* __restrict__ in,
                          const float* __restrict__ gamma, const float* __restrict__ beta,
                          __nv_bfloat16* __restrict__ oh, __nv_bfloat16* __restrict__ ol) {
    int t = blockIdx.x, c = threadIdx.x;
    int src = GATHER ? scatter_dst(t) : t;
    float v = in[(size_t)src * C_DIM + c];
    __shared__ float s1[6], s2[6];
    int wid = c >> 5, lid = c & 31;
    float s = warp_sum(v);
    if (lid == 0) s1[wid] = s;
    __syncthreads();
    float mean = (s1[0] + s1[1] + s1[2] + s1[3] + s1[4] + s1[5]) * (1.0f / 192.0f);
    float d = v - mean;
    float sq = warp_sum(d * d);
    if (lid == 0) s2[wid] = sq;
    __syncthreads();
    float var = (s2[0] + s2[1] + s2[2] + s2[3] + s2[4] + s2[5]) * (1.0f / 192.0f);
    float o = d * rsqrtf(var + 1e-5f) * gamma[c] + beta[c];
    __nv_bfloat16 h, l;
    split2(o, h, l);
    oh[(size_t)t * C_DIM + c] = h;
    ol[(size_t)t * C_DIM + c] = l;
}

// ---------------- HMMA split-bf16 GEMM (128x64 CTA, 256 thr, ldmatrix, 3-stage) ----------------
enum { EPI_F32 = 0, EPI_GELU = 1, EPI_SCATTER = 2, EPI_RES = 3 };

template <int EPI>
__global__ __launch_bounds__(256, 2)
void gemm_mma(const __nv_bfloat16* __restrict__ Ah, const __nv_bfloat16* __restrict__ Al,
              const __nv_bfloat16* __restrict__ Bh, const __nv_bfloat16* __restrict__ Bl,
              const float* __restrict__ bias, const float* __restrict__ res,
              float* __restrict__ outf, __nv_bfloat16* __restrict__ outh,
              __nv_bfloat16* __restrict__ outl, int K, int Nout) {
    extern __shared__ __align__(16) char smem[];
    int tid = threadIdx.x;
    int wid = tid >> 5, lid = tid & 31;
    int wm = wid & 3, wn = wid >> 2;            // 4 x 2 warps
    int mBase = blockIdx.y * BM;
    int nBase = blockIdx.x * BN;
    uint32_t sb = smem_u32(smem);

    float acc[2][4][4];
#pragma unroll
    for (int a = 0; a < 2; a++)
#pragma unroll
        for (int b = 0; b < 4; b++)
#pragma unroll
            for (int c = 0; c < 4; c++) acc[a][b][c] = 0.0f;

    int nch = K / BK;

    auto issue = [&](int c) {
        uint32_t sbase = sb + (c % NSTAGE) * STAGE_BYTES;
        int k0 = c * BK;
        // 1536 16B chunks: [0,512) Ah, [512,1024) Al, [1024,1280) Bh, [1280,1536) Bl
#pragma unroll
        for (int u = 0; u < 6; u++) {
            int ch = tid + u * 256;
            if (ch < 512) {
                int r = ch >> 2, cc = ch & 3;
                cp16(sbase + OFF_AH + r * RPB + cc * 16,
                     Ah + (size_t)(mBase + r) * K + k0 + cc * 8);
            } else if (ch < 1024) {
                int q = ch - 512, r = q >> 2, cc = q & 3;
                cp16(sbase + OFF_AL + r * RPB + cc * 16,
                     Al + (size_t)(mBase + r) * K + k0 + cc * 8);
            } else if (ch < 1280) {
                int q = ch - 1024, r = q >> 2, cc = q & 3;
                cp16(sbase + OFF_BH + r * RPB + cc * 16,
                     Bh + (size_t)(nBase + r) * K + k0 + cc * 8);
            } else {
                int q = ch - 1280, r = q >> 2, cc = q & 3;
                cp16(sbase + OFF_BL + r * RPB + cc * 16,
                     Bl + (size_t)(nBase + r) * K + k0 + cc * 8);
            }
        }
        cp_commit();
    };

    // ldmatrix per-lane address components
    int aRow = wm * 32 + (lid & 7) + ((lid >> 3) & 1) * 8;   // + mt*16
    int aKof = (lid >> 4) * 16;                               // bytes
    int bRow = wn * 32 + (lid & 7) + ((lid >> 4) & 1) * 8;    // + half*16
    int bKof = ((lid >> 3) & 1) * 16;                         // bytes

    issue(0);
    issue(1);
    for (int c = 0; c < nch; c++) {
        if (c + 2 < nch) { issue(c + 2); cp_wait<2>(); }
        else if (c + 1 < nch) { cp_wait<1>(); }
        else { cp_wait<0>(); }
        __syncthreads();

        uint32_t buf = sb + (c % NSTAGE) * STAGE_BYTES;
#pragma unroll
        for (int kb = 0; kb < 64; kb += 32) {   // two k16 steps (byte offset)
            uint32_t ahf[2][4], alf[2][4], bhf[2][4], blf[2][4];
#pragma unroll
            for (int mt = 0; mt < 2; mt++) {
                uint32_t ad = buf + (aRow + mt * 16) * RPB + kb + aKof;
                ldsm_x4(ahf[mt], ad + OFF_AH);
                ldsm_x4(alf[mt], ad + OFF_AL);
            }
#pragma unroll
            for (int half = 0; half < 2; half++) {
                uint32_t bd = buf + (bRow + half * 16) * RPB + kb + bKof;
                ldsm_x4(bhf[half], bd + OFF_BH);
                ldsm_x4(blf[half], bd + OFF_BL);
            }
#pragma unroll
            for (int mt = 0; mt < 2; mt++)
#pragma unroll
                for (int nt = 0; nt < 4; nt++) {
                    const uint32_t* bh = bhf[nt >> 1] + (nt & 1) * 2;
                    const uint32_t* bl = blf[nt >> 1] + (nt & 1) * 2;
                    mma16816(acc[mt][nt], ahf[mt], bh);
                    mma16816(acc[mt][nt], ahf[mt], bl);
                    mma16816(acc[mt][nt], alf[mt], bh);
                }
        }
        __syncthreads();
    }

    // ---- epilogue ----
    int g = lid >> 2, tq = lid & 3;
#pragma unroll
    for (int mt = 0; mt < 2; mt++) {
#pragma unroll
        for (int half = 0; half < 2; half++) {
            int row = mBase + wm * 32 + mt * 16 + g + half * 8;
            int dst = (EPI == EPI_SCATTER) ? scatter_dst(row) : row;
#pragma unroll
            for (int nt = 0; nt < 4; nt++) {
                int col = nBase + wn * 32 + nt * 8 + tq * 2;
                float v0 = acc[mt][nt][half * 2 + 0] + bias[col];
                float v1 = acc[mt][nt][half * 2 + 1] + bias[col + 1];
                if (EPI == EPI_GELU) {
                    v0 = gelu_exact(v0); v1 = gelu_exact(v1);
                    __nv_bfloat16 h0, l0, h1, l1;
                    split2(v0, h0, l0); split2(v1, h1, l1);
                    __nv_bfloat162 hp; hp.x = h0; hp.y = h1;
                    __nv_bfloat162 lp; lp.x = l0; lp.y = l1;
                    *(__nv_bfloat162*)(outh + (size_t)row * Nout + col) = hp;
                    *(__nv_bfloat162*)(outl + (size_t)row * Nout + col) = lp;
                } else if (EPI == EPI_SCATTER || EPI == EPI_RES) {
                    size_t o = (size_t)dst * Nout + col;
                    float2 rv = *(const float2*)(res + o);
                    float2 w; w.x = v0 + rv.x; w.y = v1 + rv.y;
                    *(float2*)(outf + o) = w;
                } else {
                    float2 w; w.x = v0; w.y = v1;
                    *(float2*)(outf + (size_t)row * Nout + col) = w;
                }
            }
        }
    }
}

// ---------------- Windowed attention (round-3 proven version) ----------------
__global__ void attn_kernel(const float* __restrict__ qkv,
                            const float* __restrict__ rpb,
                            __nv_bfloat16* __restrict__ oh, __nv_bfloat16* __restrict__ ol) {
    int blk = blockIdx.x;
    int w = blk / NHEADS;
    int h = blk - w * NHEADS;

    __shared__ float sq[49][32], sk[49][33], sv[49][32];
    __shared__ float sa[49][49];

    int tid = threadIdx.x;
    const float scale = 0.17677669529663687f;

    for (int idx = tid; idx < 49 * 32; idx += 256) {
        int n = idx >> 5, d = idx & 31;
        size_t base = ((size_t)(w * 49 + n)) * (3 * C_DIM) + h * HDIM + d;
        sq[n][d] = qkv[base] * scale;
        sk[n][d] = qkv[base + C_DIM];
        sv[n][d] = qkv[base + 2 * C_DIM];
    }
    __syncthreads();

    int r = w & 255;
    int wi = r >> 4, wj = r & 15;

    for (int e = tid; e < 49 * 49; e += 256) {
        int n = e / 49, m = e - n * 49;
        float dot = 0.0f;
#pragma unroll
        for (int d = 0; d < 32; d++) dot = fmaf(sq[n][d], sk[m][d], dot);
        int i1 = n / 7, j1 = n % 7, i2 = m / 7, j2 = m % 7;
        float b = rpb[((i1 - i2 + 6) * 13 + (j1 - j2 + 6)) * NHEADS + h];
        int hp1 = wi * 7 + i1, wp1 = wj * 7 + j1;
        int hp2 = wi * 7 + i2, wp2 = wj * 7 + j2;
        int reg1 = (hp1 < 105 ? 0 : (hp1 < 109 ? 1 : 2)) * 3 + (wp1 < 105 ? 0 : (wp1 < 109 ? 1 : 2));
        int reg2 = (hp2 < 105 ? 0 : (hp2 < 109 ? 1 : 2)) * 3 + (wp2 < 105 ? 0 : (wp2 < 109 ? 1 : 2));
        sa[n][m] = dot + b + (reg1 == reg2 ? 0.0f : -100.0f);
    }
    __syncthreads();

    int wid = tid >> 5, lid = tid & 31;
    for (int n = wid; n < 49; n += 8) {
        float v1 = sa[n][lid];
        float v2 = (lid < 17) ? sa[n][lid + 32] : -1e30f;
        float mx = warp_max(fmaxf(v1, v2));
        float e1 = __expf(v1 - mx);
        float e2 = (lid < 17) ? __expf(v2 - mx) : 0.0f;
        float s = warp_sum(e1 + e2);
        float inv = 1.0f / s;
        sa[n][lid] = e1 * inv;
        if (lid < 17) sa[n][lid + 32] = e2 * inv;
    }
    __syncthreads();

    for (int idx = tid; idx < 49 * 32; idx += 256) {
        int n = idx >> 5, d = idx & 31;
        float o = 0.0f;
#pragma unroll
        for (int m = 0; m < 49; m++) o = fmaf(sa[n][m], sv[m][d], o);
        size_t oidx = ((size_t)(w * 49 + n)) * C_DIM + h * HDIM + d;
        __nv_bfloat16 hh, ll;
        split2(o, hh, ll);
        oh[oidx] = hh;
        ol[oidx] = ll;
    }
}

// ---------------- launch ----------------
extern "C" void kernel_launch(void* const* d_in, const int* in_sizes, int n_in,
                              void* d_out, int out_size) {
    const float* query   = (const float*)d_in[0];
    const float* norm1_g = (const float*)d_in[1];
    const float* norm1_b = (const float*)d_in[2];
    const float* qkv_w   = (const float*)d_in[3];
    const float* qkv_b   = (const float*)d_in[4];
    const float* rpb     = (const float*)d_in[5];
    const float* proj_w  = (const float*)d_in[6];
    const float* proj_b  = (const float*)d_in[7];
    const float* norm2_g = (const float*)d_in[8];
    const float* norm2_b = (const float*)d_in[9];
    const float* fc1_w   = (const float*)d_in[10];
    const float* fc1_b   = (const float*)d_in[11];
    const float* fc2_w   = (const float*)d_in[12];
    const float* fc2_b   = (const float*)d_in[13];
    float* out = (float*)d_out;

    __nv_bfloat16 *xwh, *xwl, *atth, *attl, *ln2h, *ln2l, *hh, *hl;
    __nv_bfloat16 *wqh, *wql, *wph, *wpl, *w1h, *w1l, *w2h, *w2l;
    float *qkvp, *x;
    cudaGetSymbolAddress((void**)&xwh, g_xw_h);   cudaGetSymbolAddress((void**)&xwl, g_xw_l);
    cudaGetSymbolAddress((void**)&qkvp, g_qkv);
    cudaGetSymbolAddress((void**)&atth, g_att_h); cudaGetSymbolAddress((void**)&attl, g_att_l);
    cudaGetSymbolAddress((void**)&x, g_x);
    cudaGetSymbolAddress((void**)&ln2h, g_ln2_h); cudaGetSymbolAddress((void**)&ln2l, g_ln2_l);
    cudaGetSymbolAddress((void**)&hh, g_h_h);     cudaGetSymbolAddress((void**)&hl, g_h_l);
    cudaGetSymbolAddress((void**)&wqh, g_wqkv_h); cudaGetSymbolAddress((void**)&wql, g_wqkv_l);
    cudaGetSymbolAddress((void**)&wph, g_wprj_h); cudaGetSymbolAddress((void**)&wpl, g_wprj_l);
    cudaGetSymbolAddress((void**)&w1h, g_wfc1_h); cudaGetSymbolAddress((void**)&w1l, g_wfc1_l);
    cudaGetSymbolAddress((void**)&w2h, g_wfc2_h); cudaGetSymbolAddress((void**)&w2l, g_wfc2_l);

    const int SMEM = NSTAGE * STAGE_BYTES;   // 92160
    cudaFuncSetAttribute(gemm_mma<EPI_F32>,     cudaFuncAttributeMaxDynamicSharedMemorySize, SMEM);
    cudaFuncSetAttribute(gemm_mma<EPI_GELU>,    cudaFuncAttributeMaxDynamicSharedMemorySize, SMEM);
    cudaFuncSetAttribute(gemm_mma<EPI_SCATTER>, cudaFuncAttributeMaxDynamicSharedMemorySize, SMEM);
    cudaFuncSetAttribute(gemm_mma<EPI_RES>,     cudaFuncAttributeMaxDynamicSharedMemorySize, SMEM);

    wprep_kernel<<<(192 * 576 + 255) / 256, 256>>>(qkv_w,  wqh, wql, 192, 576);
    wprep_kernel<<<(192 * 192 + 255) / 256, 256>>>(proj_w, wph, wpl, 192, 192);
    wprep_kernel<<<(192 * 768 + 255) / 256, 256>>>(fc1_w,  w1h, w1l, 192, 768);
    wprep_kernel<<<(768 * 192 + 255) / 256, 256>>>(fc2_w,  w2h, w2l, 768, 192);

    // 1) LN1 + shift + window partition
    ln_kernel<true><<<M_TOK, 192>>>(query, norm1_g, norm1_b, xwh, xwl);

    // 2) qkv  [100352,192] x [192,576]
    gemm_mma<EPI_F32><<<dim3(576 / BN, M_TOK / BM), 256, SMEM>>>(
        xwh, xwl, wqh, wql, qkv_b, nullptr, qkvp, nullptr, nullptr, 192, 576);

    // 3) windowed attention
    attn_kernel<<<2048 * NHEADS, 256>>>(qkvp, rpb, atth, attl);

    // 4) proj + window reverse + unshift + residual(query)
    gemm_mma<EPI_SCATTER><<<dim3(192 / BN, M_TOK / BM), 256, SMEM>>>(
        atth, attl, wph, wpl, proj_b, query, x, nullptr, nullptr, 192, 192);

    // 5) LN2
    ln_kernel<false><<<M_TOK, 192>>>(x, norm2_g, norm2_b, ln2h, ln2l);

    // 6) fc1 + GELU
    gemm_mma<EPI_GELU><<<dim3(768 / BN, M_TOK / BM), 256, SMEM>>>(
        ln2h, ln2l, w1h, w1l, fc1_b, nullptr, nullptr, hh, hl, 192, 768);

    // 7) fc2 + residual(x) -> out
    gemm_mma<EPI_RES><<<dim3(192 / BN, M_TOK / BM), 256, SMEM>>>(
        hh, hl, w2h, w2l, fc2_b, x, out, nullptr, nullptr, 768, 192);
}

// round 6
// speedup vs baseline: 1.3775x; 1.2205x over previous
#include <cuda_runtime.h>
#include <cuda_bf16.h>
#include <math.h>
#include <stdint.h>

#define M_TOK   100352
#define C_DIM   192
#define NHEADS  6
#define HDIM    32
#define HIDDEN  768

// GEMM tiling: CTA 128x64, BK=32, 256 threads (8 warps 4x2), warp tile 32x32
#define BM 128
#define BN 64
#define BK 32
#define RPB 80                 // smem row pitch bytes (40 bf16)
#define OFF_A  0
#define OFF_BH (BM*RPB)                 // 10240
#define OFF_BL (BM*RPB + BN*RPB)        // 15360
#define STAGE_BYTES (BM*RPB + 2*BN*RPB) // 20480
#define NSTAGE 4

// ---------------- scratch ----------------
__device__ __nv_bfloat16 g_xw  [(size_t)M_TOK * C_DIM];
__device__ float         g_qkv [(size_t)M_TOK * 3 * C_DIM];
__device__ __nv_bfloat16 g_att [(size_t)M_TOK * C_DIM];
__device__ float         g_x   [(size_t)M_TOK * C_DIM];
__device__ __nv_bfloat16 g_ln2 [(size_t)M_TOK * C_DIM];
__device__ __nv_bfloat16 g_h   [(size_t)M_TOK * HIDDEN];
// transposed bf16 weights [N, K] hi/lo
__device__ __nv_bfloat16 g_wqkv_h[576 * 192], g_wqkv_l[576 * 192];
__device__ __nv_bfloat16 g_wprj_h[192 * 192], g_wprj_l[192 * 192];
__device__ __nv_bfloat16 g_wfc1_h[768 * 192], g_wfc1_l[768 * 192];
__device__ __nv_bfloat16 g_wfc2_h[192 * 768], g_wfc2_l[192 * 768];

// ---------------- helpers ----------------
__device__ __forceinline__ uint32_t smem_u32(const void* p) {
    uint32_t a;
    asm("{ .reg .u64 t; cvta.to.shared.u64 t, %1; cvt.u32.u64 %0, t; }" : "=r"(a) : "l"(p));
    return a;
}
__device__ __forceinline__ void cp16(uint32_t sa, const void* g) {
    asm volatile("cp.async.cg.shared.global [%0], [%1], 16;" :: "r"(sa), "l"(g));
}
__device__ __forceinline__ void cp_commit() { asm volatile("cp.async.commit_group;"); }
template <int N>
__device__ __forceinline__ void cp_wait() { asm volatile("cp.async.wait_group %0;" :: "n"(N)); }

__device__ __forceinline__ void ldsm_x4(uint32_t* r, uint32_t addr) {
    asm volatile("ldmatrix.sync.aligned.m8n8.x4.shared.b16 {%0,%1,%2,%3}, [%4];"
        : "=r"(r[0]), "=r"(r[1]), "=r"(r[2]), "=r"(r[3]) : "r"(addr));
}
__device__ __forceinline__ void mma16816(float* c, const uint32_t* a, const uint32_t* b) {
    asm volatile("mma.sync.aligned.m16n8k16.row.col.f32.bf16.bf16.f32 "
        "{%0,%1,%2,%3}, {%4,%5,%6,%7}, {%8,%9}, {%0,%1,%2,%3};"
        : "+f"(c[0]), "+f"(c[1]), "+f"(c[2]), "+f"(c[3])
        : "r"(a[0]), "r"(a[1]), "r"(a[2]), "r"(a[3]), "r"(b[0]), "r"(b[1]));
}
__device__ __forceinline__ void split2(float v, __nv_bfloat16& h, __nv_bfloat16& l) {
    h = __float2bfloat16(v);
    l = __float2bfloat16(v - __bfloat162float(h));
}
__device__ __forceinline__ float gelu_exact(float v) {
    return 0.5f * v * (1.0f + erff(v * 0.70710678118654752f));
}
__device__ __forceinline__ float warp_sum(float v) {
#pragma unroll
    for (int o = 16; o > 0; o >>= 1) v += __shfl_xor_sync(0xffffffffu, v, o);
    return v;
}
__device__ __forceinline__ float warp_max(float v) {
#pragma unroll
    for (int o = 16; o > 0; o >>= 1) v = fmaxf(v, __shfl_xor_sync(0xffffffffu, v, o));
    return v;
}
__device__ __forceinline__ int scatter_dst(int row) {
    int w = row / 49, n = row % 49;
    int bb = w >> 8, rr = w & 255;
    int wi = rr >> 4, wj = rr & 15;
    int i = n / 7, j = n % 7;
    int hh = wi * 7 + i + 3; if (hh >= 112) hh -= 112;
    int ww = wj * 7 + j + 3; if (ww >= 112) ww -= 112;
    return bb * 12544 + hh * 112 + ww;
}

// ---------------- weight transpose + split ----------------
__global__ void wprep_kernel(const float* __restrict__ W, __nv_bfloat16* __restrict__ Th,
                             __nv_bfloat16* __restrict__ Tl, int K, int N) {
    int i = blockIdx.x * 256 + threadIdx.x;
    if (i >= K * N) return;
    int k = i / N, n = i - k * N;
    __nv_bfloat16 h, l;
    split2(W[i], h, l);
    Th[(size_t)n * K + k] = h;
    Tl[(size_t)n * K + k] = l;
}

// ---------------- LayerNorm (+ optional shift/window gather) ----------------
template <bool GATHER>
__global__ void ln_kernel(const float* __restrict__ in,
                          const float* __restrict__ gamma, const float* __restrict__ beta,
                          __nv_bfloat16* __restrict__ oh) {
    int t = blockIdx.x, c = threadIdx.x;
    int src = GATHER ? scatter_dst(t) : t;
    float v = in[(size_t)src * C_DIM + c];
    __shared__ float s1[6], s2[6];
    int wid = c >> 5, lid = c & 31;
    float s = warp_sum(v);
    if (lid == 0) s1[wid] = s;
    __syncthreads();
    float mean = (s1[0] + s1[1] + s1[2] + s1[3] + s1[4] + s1[5]) * (1.0f / 192.0f);
    float d = v - mean;
    float sq = warp_sum(d * d);
    if (lid == 0) s2[wid] = sq;
    __syncthreads();
    float var = (s2[0] + s2[1] + s2[2] + s2[3] + s2[4] + s2[5]) * (1.0f / 192.0f);
    float o = d * rsqrtf(var + 1e-5f) * gamma[c] + beta[c];
    oh[(size_t)t * C_DIM + c] = __float2bfloat16(o);
}

// ---------------- HMMA GEMM: A bf16, W split hi/lo (2 MMA/tile), 4-stage ----------------
enum { EPI_F32 = 0, EPI_GELU = 1, EPI_SCATTER = 2, EPI_RES = 3 };

template <int EPI>
__global__ __launch_bounds__(256, 2)
void gemm_mma(const __nv_bfloat16* __restrict__ Aact,
              const __nv_bfloat16* __restrict__ Bh, const __nv_bfloat16* __restrict__ Bl,
              const float* __restrict__ bias, const float* __restrict__ res,
              float* __restrict__ outf, __nv_bfloat16* __restrict__ outb,
              int K, int Nout) {
    extern __shared__ __align__(16) char smem[];
    int tid = threadIdx.x;
    int wid = tid >> 5, lid = tid & 31;
    int wm = wid & 3, wn = wid >> 2;            // 4 x 2 warps
    int mBase = blockIdx.y * BM;
    int nBase = blockIdx.x * BN;
    uint32_t sb = smem_u32(smem);

    float acc[2][4][4];
#pragma unroll
    for (int a = 0; a < 2; a++)
#pragma unroll
        for (int b = 0; b < 4; b++)
#pragma unroll
            for (int c = 0; c < 4; c++) acc[a][b][c] = 0.0f;

    int nch = K / BK;

    auto issue = [&](int c) {
        uint32_t sbase = sb + (c % NSTAGE) * STAGE_BYTES;
        int k0 = c * BK;
        // 1024 16B chunks: [0,512) A, [512,768) Bh, [768,1024) Bl
#pragma unroll
        for (int u = 0; u < 4; u++) {
            int ch = tid + u * 256;
            if (ch < 512) {
                int r = ch >> 2, cc = ch & 3;
                cp16(sbase + OFF_A + r * RPB + cc * 16,
                     Aact + (size_t)(mBase + r) * K + k0 + cc * 8);
            } else if (ch < 768) {
                int q = ch - 512, r = q >> 2, cc = q & 3;
                cp16(sbase + OFF_BH + r * RPB + cc * 16,
                     Bh + (size_t)(nBase + r) * K + k0 + cc * 8);
            } else {
                int q = ch - 768, r = q >> 2, cc = q & 3;
                cp16(sbase + OFF_BL + r * RPB + cc * 16,
                     Bl + (size_t)(nBase + r) * K + k0 + cc * 8);
            }
        }
        cp_commit();
    };

    // ldmatrix per-lane address components (proven round-5 mapping)
    int aRow = wm * 32 + (lid & 7) + ((lid >> 3) & 1) * 8;   // + mt*16
    int aKof = (lid >> 4) * 16;                               // bytes
    int bRow = wn * 32 + (lid & 7) + ((lid >> 4) & 1) * 8;    // + half*16
    int bKof = ((lid >> 3) & 1) * 16;                         // bytes

    issue(0);
    if (nch > 1) issue(1);
    if (nch > 2) issue(2);
    for (int c = 0; c < nch; c++) {
        int rem = nch - 1 - c;
        if (c + 3 < nch) issue(c + 3);
        if (rem >= 3)      cp_wait<3>();
        else if (rem == 2) cp_wait<2>();
        else if (rem == 1) cp_wait<1>();
        else               cp_wait<0>();
        __syncthreads();

        uint32_t buf = sb + (c % NSTAGE) * STAGE_BYTES;
#pragma unroll
        for (int kb = 0; kb < 64; kb += 32) {   // two k16 steps (byte offset)
            uint32_t ahf[2][4], bhf[2][4], blf[2][4];
#pragma unroll
            for (int mt = 0; mt < 2; mt++) {
                uint32_t ad = buf + OFF_A + (aRow + mt * 16) * RPB + kb + aKof;
                ldsm_x4(ahf[mt], ad);
            }
#pragma unroll
            for (int half = 0; half < 2; half++) {
                uint32_t bd = buf + (bRow + half * 16) * RPB + kb + bKof;
                ldsm_x4(bhf[half], bd + OFF_BH);
                ldsm_x4(blf[half], bd + OFF_BL);
            }
#pragma unroll
            for (int mt = 0; mt < 2; mt++)
#pragma unroll
                for (int nt = 0; nt < 4; nt++) {
                    const uint32_t* bh = bhf[nt >> 1] + (nt & 1) * 2;
                    const uint32_t* bl = blf[nt >> 1] + (nt & 1) * 2;
                    mma16816(acc[mt][nt], ahf[mt], bh);
                    mma16816(acc[mt][nt], ahf[mt], bl);
                }
        }
        __syncthreads();
    }

    // ---- epilogue ----
    int g = lid >> 2, tq = lid & 3;
#pragma unroll
    for (int mt = 0; mt < 2; mt++) {
#pragma unroll
        for (int half = 0; half < 2; half++) {
            int row = mBase + wm * 32 + mt * 16 + g + half * 8;
            int dst = (EPI == EPI_SCATTER) ? scatter_dst(row) : row;
#pragma unroll
            for (int nt = 0; nt < 4; nt++) {
                int col = nBase + wn * 32 + nt * 8 + tq * 2;
                float v0 = acc[mt][nt][half * 2 + 0] + bias[col];
                float v1 = acc[mt][nt][half * 2 + 1] + bias[col + 1];
                if (EPI == EPI_GELU) {
                    v0 = gelu_exact(v0); v1 = gelu_exact(v1);
                    __nv_bfloat162 hp;
                    hp.x = __float2bfloat16(v0); hp.y = __float2bfloat16(v1);
                    *(__nv_bfloat162*)(outb + (size_t)row * Nout + col) = hp;
                } else if (EPI == EPI_SCATTER || EPI == EPI_RES) {
                    size_t o = (size_t)dst * Nout + col;
                    float2 rv = *(const float2*)(res + o);
                    float2 w; w.x = v0 + rv.x; w.y = v1 + rv.y;
                    *(float2*)(outf + o) = w;
                } else {
                    float2 w; w.x = v0; w.y = v1;
                    *(float2*)(outf + (size_t)row * Nout + col) = w;
                }
            }
        }
    }
}

// ---------------- Windowed attention ----------------
__global__ void attn_kernel(const float* __restrict__ qkv,
                            const float* __restrict__ rpb,
                            __nv_bfloat16* __restrict__ oh) {
    int blk = blockIdx.x;
    int w = blk / NHEADS;
    int h = blk - w * NHEADS;

    __shared__ float sq[49][32], sk[49][33], sv[49][32];
    __shared__ float sa[49][49];

    int tid = threadIdx.x;
    const float scale = 0.17677669529663687f;

    for (int idx = tid; idx < 49 * 32; idx += 256) {
        int n = idx >> 5, d = idx & 31;
        size_t base = ((size_t)(w * 49 + n)) * (3 * C_DIM) + h * HDIM + d;
        sq[n][d] = qkv[base] * scale;
        sk[n][d] = qkv[base + C_DIM];
        sv[n][d] = qkv[base + 2 * C_DIM];
    }
    __syncthreads();

    int r = w & 255;
    int wi = r >> 4, wj = r & 15;

    for (int e = tid; e < 49 * 49; e += 256) {
        int n = e / 49, m = e - n * 49;
        float dot = 0.0f;
#pragma unroll
        for (int d = 0; d < 32; d++) dot = fmaf(sq[n][d], sk[m][d], dot);
        int i1 = n / 7, j1 = n % 7, i2 = m / 7, j2 = m % 7;
        float b = rpb[((i1 - i2 + 6) * 13 + (j1 - j2 + 6)) * NHEADS + h];
        int hp1 = wi * 7 + i1, wp1 = wj * 7 + j1;
        int hp2 = wi * 7 + i2, wp2 = wj * 7 + j2;
        int reg1 = (hp1 < 105 ? 0 : (hp1 < 109 ? 1 : 2)) * 3 + (wp1 < 105 ? 0 : (wp1 < 109 ? 1 : 2));
        int reg2 = (hp2 < 105 ? 0 : (hp2 < 109 ? 1 : 2)) * 3 + (wp2 < 105 ? 0 : (wp2 < 109 ? 1 : 2));
        sa[n][m] = dot + b + (reg1 == reg2 ? 0.0f : -100.0f);
    }
    __syncthreads();

    int wid = tid >> 5, lid = tid & 31;
    for (int n = wid; n < 49; n += 8) {
        float v1 = sa[n][lid];
        float v2 = (lid < 17) ? sa[n][lid + 32] : -1e30f;
        float mx = warp_max(fmaxf(v1, v2));
        float e1 = __expf(v1 - mx);
        float e2 = (lid < 17) ? __expf(v2 - mx) : 0.0f;
        float s = warp_sum(e1 + e2);
        float inv = 1.0f / s;
        sa[n][lid] = e1 * inv;
        if (lid < 17) sa[n][lid + 32] = e2 * inv;
    }
    __syncthreads();

    for (int idx = tid; idx < 49 * 32; idx += 256) {
        int n = idx >> 5, d = idx & 31;
        float o = 0.0f;
#pragma unroll
        for (int m = 0; m < 49; m++) o = fmaf(sa[n][m], sv[m][d], o);
        size_t oidx = ((size_t)(w * 49 + n)) * C_DIM + h * HDIM + d;
        oh[oidx] = __float2bfloat16(o);
    }
}

// ---------------- launch ----------------
extern "C" void kernel_launch(void* const* d_in, const int* in_sizes, int n_in,
                              void* d_out, int out_size) {
    const float* query   = (const float*)d_in[0];
    const float* norm1_g = (const float*)d_in[1];
    const float* norm1_b = (const float*)d_in[2];
    const float* qkv_w   = (const float*)d_in[3];
    const float* qkv_b   = (const float*)d_in[4];
    const float* rpb     = (const float*)d_in[5];
    const float* proj_w  = (const float*)d_in[6];
    const float* proj_b  = (const float*)d_in[7];
    const float* norm2_g = (const float*)d_in[8];
    const float* norm2_b = (const float*)d_in[9];
    const float* fc1_w   = (const float*)d_in[10];
    const float* fc1_b   = (const float*)d_in[11];
    const float* fc2_w   = (const float*)d_in[12];
    const float* fc2_b   = (const float*)d_in[13];
    float* out = (float*)d_out;

    __nv_bfloat16 *xw, *att, *ln2, *hbuf;
    __nv_bfloat16 *wqh, *wql, *wph, *wpl, *w1h, *w1l, *w2h, *w2l;
    float *qkvp, *x;
    cudaGetSymbolAddress((void**)&xw, g_xw);
    cudaGetSymbolAddress((void**)&qkvp, g_qkv);
    cudaGetSymbolAddress((void**)&att, g_att);
    cudaGetSymbolAddress((void**)&x, g_x);
    cudaGetSymbolAddress((void**)&ln2, g_ln2);
    cudaGetSymbolAddress((void**)&hbuf, g_h);
    cudaGetSymbolAddress((void**)&wqh, g_wqkv_h); cudaGetSymbolAddress((void**)&wql, g_wqkv_l);
    cudaGetSymbolAddress((void**)&wph, g_wprj_h); cudaGetSymbolAddress((void**)&wpl, g_wprj_l);
    cudaGetSymbolAddress((void**)&w1h, g_wfc1_h); cudaGetSymbolAddress((void**)&w1l, g_wfc1_l);
    cudaGetSymbolAddress((void**)&w2h, g_wfc2_h); cudaGetSymbolAddress((void**)&w2l, g_wfc2_l);

    const int SMEM = NSTAGE * STAGE_BYTES;   // 81920
    cudaFuncSetAttribute(gemm_mma<EPI_F32>,     cudaFuncAttributeMaxDynamicSharedMemorySize, SMEM);
    cudaFuncSetAttribute(gemm_mma<EPI_GELU>,    cudaFuncAttributeMaxDynamicSharedMemorySize, SMEM);
    cudaFuncSetAttribute(gemm_mma<EPI_SCATTER>, cudaFuncAttributeMaxDynamicSharedMemorySize, SMEM);
    cudaFuncSetAttribute(gemm_mma<EPI_RES>,     cudaFuncAttributeMaxDynamicSharedMemorySize, SMEM);

    wprep_kernel<<<(192 * 576 + 255) / 256, 256>>>(qkv_w,  wqh, wql, 192, 576);
    wprep_kernel<<<(192 * 192 + 255) / 256, 256>>>(proj_w, wph, wpl, 192, 192);
    wprep_kernel<<<(192 * 768 + 255) / 256, 256>>>(fc1_w,  w1h, w1l, 192, 768);
    wprep_kernel<<<(768 * 192 + 255) / 256, 256>>>(fc2_w,  w2h, w2l, 768, 192);

    // 1) LN1 + shift + window partition
    ln_kernel<true><<<M_TOK, 192>>>(query, norm1_g, norm1_b, xw);

    // 2) qkv  [100352,192] x [192,576]
    gemm_mma<EPI_F32><<<dim3(576 / BN, M_TOK / BM), 256, SMEM>>>(
        xw, wqh, wql, qkv_b, nullptr, qkvp, nullptr, 192, 576);

    // 3) windowed attention
    attn_kernel<<<2048 * NHEADS, 256>>>(qkvp, rpb, att);

    // 4) proj + window reverse + unshift + residual(query)
    gemm_mma<EPI_SCATTER><<<dim3(192 / BN, M_TOK / BM), 256, SMEM>>>(
        att, wph, wpl, proj_b, query, x, nullptr, 192, 192);

    // 5) LN2
    ln_kernel<false><<<M_TOK, 192>>>(x, norm2_g, norm2_b, ln2);

    // 6) fc1 + GELU
    gemm_mma<EPI_GELU><<<dim3(768 / BN, M_TOK / BM), 256, SMEM>>>(
        ln2, w1h, w1l, fc1_b, nullptr, nullptr, hbuf, 192, 768);

    // 7) fc2 + residual(x) -> out
    gemm_mma<EPI_RES><<<dim3(192 / BN, M_TOK / BM), 256, SMEM>>>(
        hbuf, w2h, w2l, fc2_b, x, out, nullptr, 768, 192);
}

// round 7
// speedup vs baseline: 1.6005x; 1.1619x over previous
#include <cuda_runtime.h>
#include <cuda_bf16.h>
#include <math.h>
#include <stdint.h>

#define M_TOK   100352
#define C_DIM   192
#define NHEADS  6
#define HDIM    32
#define HIDDEN  768

// GEMM tiling: CTA 128x64, BK=32, 256 threads (8 warps 4x2), warp tile 32x32
#define BM 128
#define BN 64
#define BK 32
#define RPB 80                 // smem row pitch bytes (40 bf16)
#define OFF_A  0
#define OFF_B  (BM*RPB)                 // 10240
#define STAGE_BYTES (BM*RPB + BN*RPB)   // 15360
#define NSTAGE 4

// ---------------- scratch ----------------
__device__ __nv_bfloat16 g_xw  [(size_t)M_TOK * C_DIM];
__device__ __nv_bfloat16 g_qkv [(size_t)M_TOK * 3 * C_DIM];
__device__ __nv_bfloat16 g_att [(size_t)M_TOK * C_DIM];
__device__ float         g_x   [(size_t)M_TOK * C_DIM];
__device__ __nv_bfloat16 g_ln2 [(size_t)M_TOK * C_DIM];
__device__ __nv_bfloat16 g_h   [(size_t)M_TOK * HIDDEN];
// transposed bf16 weights [N, K]
__device__ __nv_bfloat16 g_wqkv[576 * 192];
__device__ __nv_bfloat16 g_wprj[192 * 192];
__device__ __nv_bfloat16 g_wfc1[768 * 192];
__device__ __nv_bfloat16 g_wfc2[192 * 768];

// ---------------- helpers ----------------
__device__ __forceinline__ uint32_t smem_u32(const void* p) {
    uint32_t a;
    asm("{ .reg .u64 t; cvta.to.shared.u64 t, %1; cvt.u32.u64 %0, t; }" : "=r"(a) : "l"(p));
    return a;
}
__device__ __forceinline__ void cp16(uint32_t sa, const void* g) {
    asm volatile("cp.async.cg.shared.global [%0], [%1], 16;" :: "r"(sa), "l"(g));
}
__device__ __forceinline__ void cp_commit() { asm volatile("cp.async.commit_group;"); }
template <int N>
__device__ __forceinline__ void cp_wait() { asm volatile("cp.async.wait_group %0;" :: "n"(N)); }

__device__ __forceinline__ void ldsm_x4(uint32_t* r, uint32_t addr) {
    asm volatile("ldmatrix.sync.aligned.m8n8.x4.shared.b16 {%0,%1,%2,%3}, [%4];"
        : "=r"(r[0]), "=r"(r[1]), "=r"(r[2]), "=r"(r[3]) : "r"(addr));
}
__device__ __forceinline__ void mma16816(float* c, const uint32_t* a, const uint32_t* b) {
    asm volatile("mma.sync.aligned.m16n8k16.row.col.f32.bf16.bf16.f32 "
        "{%0,%1,%2,%3}, {%4,%5,%6,%7}, {%8,%9}, {%0,%1,%2,%3};"
        : "+f"(c[0]), "+f"(c[1]), "+f"(c[2]), "+f"(c[3])
        : "r"(a[0]), "r"(a[1]), "r"(a[2]), "r"(a[3]), "r"(b[0]), "r"(b[1]));
}
__device__ __forceinline__ float gelu_exact(float v) {
    return 0.5f * v * (1.0f + erff(v * 0.70710678118654752f));
}
__device__ __forceinline__ float warp_sum(float v) {
#pragma unroll
    for (int o = 16; o > 0; o >>= 1) v += __shfl_xor_sync(0xffffffffu, v, o);
    return v;
}
__device__ __forceinline__ float warp_max(float v) {
#pragma unroll
    for (int o = 16; o > 0; o >>= 1) v = fmaxf(v, __shfl_xor_sync(0xffffffffu, v, o));
    return v;
}
__device__ __forceinline__ int scatter_dst(int row) {
    int w = row / 49, n = row % 49;
    int bb = w >> 8, rr = w & 255;
    int wi = rr >> 4, wj = rr & 15;
    int i = n / 7, j = n % 7;
    int hh = wi * 7 + i + 3; if (hh >= 112) hh -= 112;
    int ww = wj * 7 + j + 3; if (ww >= 112) ww -= 112;
    return bb * 12544 + hh * 112 + ww;
}

// ---------------- weight transpose: W[K,N] -> Wt [N,K] bf16 ----------------
__global__ void wprep_kernel(const float* __restrict__ W, __nv_bfloat16* __restrict__ T,
                             int K, int N) {
    int i = blockIdx.x * 256 + threadIdx.x;
    if (i >= K * N) return;
    int k = i / N, n = i - k * N;
    T[(size_t)n * K + k] = __float2bfloat16(W[i]);
}

// ---------------- LayerNorm (+ optional shift/window gather) ----------------
template <bool GATHER>
__global__ void ln_kernel(const float* __restrict__ in,
                          const float* __restrict__ gamma, const float* __restrict__ beta,
                          __nv_bfloat16* __restrict__ oh) {
    int t = blockIdx.x, c = threadIdx.x;
    int src = GATHER ? scatter_dst(t) : t;
    float v = in[(size_t)src * C_DIM + c];
    __shared__ float s1[6], s2[6];
    int wid = c >> 5, lid = c & 31;
    float s = warp_sum(v);
    if (lid == 0) s1[wid] = s;
    __syncthreads();
    float mean = (s1[0] + s1[1] + s1[2] + s1[3] + s1[4] + s1[5]) * (1.0f / 192.0f);
    float d = v - mean;
    float sq = warp_sum(d * d);
    if (lid == 0) s2[wid] = sq;
    __syncthreads();
    float var = (s2[0] + s2[1] + s2[2] + s2[3] + s2[4] + s2[5]) * (1.0f / 192.0f);
    float o = d * rsqrtf(var + 1e-5f) * gamma[c] + beta[c];
    oh[(size_t)t * C_DIM + c] = __float2bfloat16(o);
}

// ---------------- HMMA GEMM: A bf16, W bf16 (1 MMA/tile), 4-stage ----------------
enum { EPI_BF16 = 0, EPI_GELU = 1, EPI_SCATTER = 2, EPI_RES = 3 };

template <int EPI>
__global__ __launch_bounds__(256, 2)
void gemm_mma(const __nv_bfloat16* __restrict__ Aact,
              const __nv_bfloat16* __restrict__ Bw,
              const float* __restrict__ bias, const float* __restrict__ res,
              float* __restrict__ outf, __nv_bfloat16* __restrict__ outb,
              int K, int Nout) {
    extern __shared__ __align__(16) char smem[];
    int tid = threadIdx.x;
    int wid = tid >> 5, lid = tid & 31;
    int wm = wid & 3, wn = wid >> 2;            // 4 x 2 warps
    int mBase = blockIdx.y * BM;
    int nBase = blockIdx.x * BN;
    uint32_t sb = smem_u32(smem);

    float acc[2][4][4];
#pragma unroll
    for (int a = 0; a < 2; a++)
#pragma unroll
        for (int b = 0; b < 4; b++)
#pragma unroll
            for (int c = 0; c < 4; c++) acc[a][b][c] = 0.0f;

    int nch = K / BK;

    auto issue = [&](int c) {
        uint32_t sbase = sb + (c % NSTAGE) * STAGE_BYTES;
        int k0 = c * BK;
        // 768 16B chunks: [0,512) A, [512,768) B
#pragma unroll
        for (int u = 0; u < 3; u++) {
            int ch = tid + u * 256;
            if (ch < 512) {
                int r = ch >> 2, cc = ch & 3;
                cp16(sbase + OFF_A + r * RPB + cc * 16,
                     Aact + (size_t)(mBase + r) * K + k0 + cc * 8);
            } else {
                int q = ch - 512, r = q >> 2, cc = q & 3;
                cp16(sbase + OFF_B + r * RPB + cc * 16,
                     Bw + (size_t)(nBase + r) * K + k0 + cc * 8);
            }
        }
        cp_commit();
    };

    // ldmatrix per-lane address components
    int aRow = wm * 32 + (lid & 7) + ((lid >> 3) & 1) * 8;   // + mt*16
    int aKof = (lid >> 4) * 16;                               // bytes
    int bRow = wn * 32 + (lid & 7) + ((lid >> 4) & 1) * 8;    // + half*16
    int bKof = ((lid >> 3) & 1) * 16;                         // bytes

    issue(0);
    if (nch > 1) issue(1);
    if (nch > 2) issue(2);
    for (int c = 0; c < nch; c++) {
        int rem = nch - 1 - c;
        if (c + 3 < nch) issue(c + 3);
        if (rem >= 3)      cp_wait<3>();
        else if (rem == 2) cp_wait<2>();
        else if (rem == 1) cp_wait<1>();
        else               cp_wait<0>();
        __syncthreads();

        uint32_t buf = sb + (c % NSTAGE) * STAGE_BYTES;
#pragma unroll
        for (int kb = 0; kb < 64; kb += 32) {   // two k16 steps (byte offset)
            uint32_t ahf[2][4], bhf[2][4];
#pragma unroll
            for (int mt = 0; mt < 2; mt++) {
                uint32_t ad = buf + OFF_A + (aRow + mt * 16) * RPB + kb + aKof;
                ldsm_x4(ahf[mt], ad);
            }
#pragma unroll
            for (int half = 0; half < 2; half++) {
                uint32_t bd = buf + OFF_B + (bRow + half * 16) * RPB + kb + bKof;
                ldsm_x4(bhf[half], bd);
            }
#pragma unroll
            for (int mt = 0; mt < 2; mt++)
#pragma unroll
                for (int nt = 0; nt < 4; nt++) {
                    const uint32_t* bh = bhf[nt >> 1] + (nt & 1) * 2;
                    mma16816(acc[mt][nt], ahf[mt], bh);
                }
        }
        __syncthreads();
    }

    // ---- epilogue ----
    int g = lid >> 2, tq = lid & 3;
#pragma unroll
    for (int mt = 0; mt < 2; mt++) {
#pragma unroll
        for (int half = 0; half < 2; half++) {
            int row = mBase + wm * 32 + mt * 16 + g + half * 8;
            int dst = (EPI == EPI_SCATTER) ? scatter_dst(row) : row;
#pragma unroll
            for (int nt = 0; nt < 4; nt++) {
                int col = nBase + wn * 32 + nt * 8 + tq * 2;
                float v0 = acc[mt][nt][half * 2 + 0] + bias[col];
                float v1 = acc[mt][nt][half * 2 + 1] + bias[col + 1];
                if (EPI == EPI_GELU) {
                    v0 = gelu_exact(v0); v1 = gelu_exact(v1);
                }
                if (EPI == EPI_GELU || EPI == EPI_BF16) {
                    __nv_bfloat162 hp;
                    hp.x = __float2bfloat16(v0); hp.y = __float2bfloat16(v1);
                    *(__nv_bfloat162*)(outb + (size_t)row * Nout + col) = hp;
                } else {
                    size_t o = (size_t)dst * Nout + col;
                    float2 rv = *(const float2*)(res + o);
                    float2 w; w.x = v0 + rv.x; w.y = v1 + rv.y;
                    *(float2*)(outf + o) = w;
                }
            }
        }
    }
}

// ---------------- Windowed attention (bf16 qkv in) ----------------
__global__ void attn_kernel(const __nv_bfloat16* __restrict__ qkv,
                            const float* __restrict__ rpb,
                            __nv_bfloat16* __restrict__ oh) {
    int blk = blockIdx.x;
    int w = blk / NHEADS;
    int h = blk - w * NHEADS;

    __shared__ float sq[49][32], sk[49][33], sv[49][32];
    __shared__ float sa[49][49];

    int tid = threadIdx.x;
    const float scale = 0.17677669529663687f;

    for (int idx = tid; idx < 49 * 32; idx += 256) {
        int n = idx >> 5, d = idx & 31;
        size_t base = ((size_t)(w * 49 + n)) * (3 * C_DIM) + h * HDIM + d;
        sq[n][d] = __bfloat162float(qkv[base]) * scale;
        sk[n][d] = __bfloat162float(qkv[base + C_DIM]);
        sv[n][d] = __bfloat162float(qkv[base + 2 * C_DIM]);
    }
    __syncthreads();

    int r = w & 255;
    int wi = r >> 4, wj = r & 15;

    for (int e = tid; e < 49 * 49; e += 256) {
        int n = e / 49, m = e - n * 49;
        float dot = 0.0f;
#pragma unroll
        for (int d = 0; d < 32; d++) dot = fmaf(sq[n][d], sk[m][d], dot);
        int i1 = n / 7, j1 = n % 7, i2 = m / 7, j2 = m % 7;
        float b = rpb[((i1 - i2 + 6) * 13 + (j1 - j2 + 6)) * NHEADS + h];
        int hp1 = wi * 7 + i1, wp1 = wj * 7 + j1;
        int hp2 = wi * 7 + i2, wp2 = wj * 7 + j2;
        int reg1 = (hp1 < 105 ? 0 : (hp1 < 109 ? 1 : 2)) * 3 + (wp1 < 105 ? 0 : (wp1 < 109 ? 1 : 2));
        int reg2 = (hp2 < 105 ? 0 : (hp2 < 109 ? 1 : 2)) * 3 + (wp2 < 105 ? 0 : (wp2 < 109 ? 1 : 2));
        sa[n][m] = dot + b + (reg1 == reg2 ? 0.0f : -100.0f);
    }
    __syncthreads();

    int wid = tid >> 5, lid = tid & 31;
    for (int n = wid; n < 49; n += 8) {
        float v1 = sa[n][lid];
        float v2 = (lid < 17) ? sa[n][lid + 32] : -1e30f;
        float mx = warp_max(fmaxf(v1, v2));
        float e1 = __expf(v1 - mx);
        float e2 = (lid < 17) ? __expf(v2 - mx) : 0.0f;
        float s = warp_sum(e1 + e2);
        float inv = 1.0f / s;
        sa[n][lid] = e1 * inv;
        if (lid < 17) sa[n][lid + 32] = e2 * inv;
    }
    __syncthreads();

    for (int idx = tid; idx < 49 * 32; idx += 256) {
        int n = idx >> 5, d = idx & 31;
        float o = 0.0f;
#pragma unroll
        for (int m = 0; m < 49; m++) o = fmaf(sa[n][m], sv[m][d], o);
        size_t oidx = ((size_t)(w * 49 + n)) * C_DIM + h * HDIM + d;
        oh[oidx] = __float2bfloat16(o);
    }
}

// ---------------- launch ----------------
extern "C" void kernel_launch(void* const* d_in, const int* in_sizes, int n_in,
                              void* d_out, int out_size) {
    const float* query   = (const float*)d_in[0];
    const float* norm1_g = (const float*)d_in[1];
    const float* norm1_b = (const float*)d_in[2];
    const float* qkv_w   = (const float*)d_in[3];
    const float* qkv_b   = (const float*)d_in[4];
    const float* rpb     = (const float*)d_in[5];
    const float* proj_w  = (const float*)d_in[6];
    const float* proj_b  = (const float*)d_in[7];
    const float* norm2_g = (const float*)d_in[8];
    const float* norm2_b = (const float*)d_in[9];
    const float* fc1_w   = (const float*)d_in[10];
    const float* fc1_b   = (const float*)d_in[11];
    const float* fc2_w   = (const float*)d_in[12];
    const float* fc2_b   = (const float*)d_in[13];
    float* out = (float*)d_out;

    __nv_bfloat16 *xw, *qkvp, *att, *ln2, *hbuf;
    __nv_bfloat16 *wq, *wp, *w1, *w2;
    float *x;
    cudaGetSymbolAddress((void**)&xw, g_xw);
    cudaGetSymbolAddress((void**)&qkvp, g_qkv);
    cudaGetSymbolAddress((void**)&att, g_att);
    cudaGetSymbolAddress((void**)&x, g_x);
    cudaGetSymbolAddress((void**)&ln2, g_ln2);
    cudaGetSymbolAddress((void**)&hbuf, g_h);
    cudaGetSymbolAddress((void**)&wq, g_wqkv);
    cudaGetSymbolAddress((void**)&wp, g_wprj);
    cudaGetSymbolAddress((void**)&w1, g_wfc1);
    cudaGetSymbolAddress((void**)&w2, g_wfc2);

    const int SMEM = NSTAGE * STAGE_BYTES;   // 61440
    cudaFuncSetAttribute(gemm_mma<EPI_BF16>,    cudaFuncAttributeMaxDynamicSharedMemorySize, SMEM);
    cudaFuncSetAttribute(gemm_mma<EPI_GELU>,    cudaFuncAttributeMaxDynamicSharedMemorySize, SMEM);
    cudaFuncSetAttribute(gemm_mma<EPI_SCATTER>, cudaFuncAttributeMaxDynamicSharedMemorySize, SMEM);
    cudaFuncSetAttribute(gemm_mma<EPI_RES>,     cudaFuncAttributeMaxDynamicSharedMemorySize, SMEM);

    wprep_kernel<<<(192 * 576 + 255) / 256, 256>>>(qkv_w,  wq, 192, 576);
    wprep_kernel<<<(192 * 192 + 255) / 256, 256>>>(proj_w, wp, 192, 192);
    wprep_kernel<<<(192 * 768 + 255) / 256, 256>>>(fc1_w,  w1, 192, 768);
    wprep_kernel<<<(768 * 192 + 255) / 256, 256>>>(fc2_w,  w2, 768, 192);

    // 1) LN1 + shift + window partition
    ln_kernel<true><<<M_TOK, 192>>>(query, norm1_g, norm1_b, xw);

    // 2) qkv  [100352,192] x [192,576] -> bf16
    gemm_mma<EPI_BF16><<<dim3(576 / BN, M_TOK / BM), 256, SMEM>>>(
        xw, wq, qkv_b, nullptr, nullptr, qkvp, 192, 576);

    // 3) windowed attention
    attn_kernel<<<2048 * NHEADS, 256>>>(qkvp, rpb, att);

    // 4) proj + window reverse + unshift + residual(query)
    gemm_mma<EPI_SCATTER><<<dim3(192 / BN, M_TOK / BM), 256, SMEM>>>(
        att, wp, proj_b, query, x, nullptr, 192, 192);

    // 5) LN2
    ln_kernel<false><<<M_TOK, 192>>>(x, norm2_g, norm2_b, ln2);

    // 6) fc1 + GELU
    gemm_mma<EPI_GELU><<<dim3(768 / BN, M_TOK / BM), 256, SMEM>>>(
        ln2, w1, fc1_b, nullptr, nullptr, hbuf, 192, 768);

    // 7) fc2 + residual(x) -> out
    gemm_mma<EPI_RES><<<dim3(192 / BN, M_TOK / BM), 256, SMEM>>>(
        hbuf, w2, fc2_b, x, out, nullptr, 768, 192);
}

// round 8
// speedup vs baseline: 1.6233x; 1.0142x over previous
#include <cuda_runtime.h>
#include <cuda_bf16.h>
#include <math.h>
#include <stdint.h>

#define M_TOK   100352
#define C_DIM   192
#define NHEADS  6
#define HDIM    32
#define HIDDEN  768

// GEMM tiling: CTA 128x64, BK=32, 256 threads (8 warps 4x2), warp tile 32x32
#define BM 128
#define BN 64
#define BK 32
#define RPB 80                 // smem row pitch bytes (40 bf16)
#define OFF_A  0
#define OFF_B  (BM*RPB)                 // 10240
#define STAGE_BYTES (BM*RPB + BN*RPB)   // 15360
#define NSTAGE 4

typedef unsigned long long ull;

// ---------------- scratch ----------------
__device__ __nv_bfloat16 g_xw  [(size_t)M_TOK * C_DIM];
__device__ __nv_bfloat16 g_qkv [(size_t)M_TOK * 3 * C_DIM];
__device__ __nv_bfloat16 g_att [(size_t)M_TOK * C_DIM];
__device__ float         g_x   [(size_t)M_TOK * C_DIM];
__device__ __nv_bfloat16 g_ln2 [(size_t)M_TOK * C_DIM];
__device__ __nv_bfloat16 g_h   [(size_t)M_TOK * HIDDEN];
// transposed bf16 weights [N, K]
__device__ __nv_bfloat16 g_wqkv[576 * 192];
__device__ __nv_bfloat16 g_wprj[192 * 192];
__device__ __nv_bfloat16 g_wfc1[768 * 192];
__device__ __nv_bfloat16 g_wfc2[192 * 768];

// ---------------- helpers ----------------
__device__ __forceinline__ uint32_t smem_u32(const void* p) {
    uint32_t a;
    asm("{ .reg .u64 t; cvta.to.shared.u64 t, %1; cvt.u32.u64 %0, t; }" : "=r"(a) : "l"(p));
    return a;
}
__device__ __forceinline__ void cp16(uint32_t sa, const void* g) {
    asm volatile("cp.async.cg.shared.global [%0], [%1], 16;" :: "r"(sa), "l"(g));
}
__device__ __forceinline__ void cp_commit() { asm volatile("cp.async.commit_group;"); }
template <int N>
__device__ __forceinline__ void cp_wait() { asm volatile("cp.async.wait_group %0;" :: "n"(N)); }

__device__ __forceinline__ void ldsm_x4(uint32_t* r, uint32_t addr) {
    asm volatile("ldmatrix.sync.aligned.m8n8.x4.shared.b16 {%0,%1,%2,%3}, [%4];"
        : "=r"(r[0]), "=r"(r[1]), "=r"(r[2]), "=r"(r[3]) : "r"(addr));
}
__device__ __forceinline__ void mma16816(float* c, const uint32_t* a, const uint32_t* b) {
    asm volatile("mma.sync.aligned.m16n8k16.row.col.f32.bf16.bf16.f32 "
        "{%0,%1,%2,%3}, {%4,%5,%6,%7}, {%8,%9}, {%0,%1,%2,%3};"
        : "+f"(c[0]), "+f"(c[1]), "+f"(c[2]), "+f"(c[3])
        : "r"(a[0]), "r"(a[1]), "r"(a[2]), "r"(a[3]), "r"(b[0]), "r"(b[1]));
}
// packed fp32x2 FMA (FFMA2) — full fp32 precision, 2x FFMA throughput
__device__ __forceinline__ void fma2(ull& acc, ull a, ull b) {
    asm("fma.rn.f32x2 %0, %1, %2, %0;" : "+l"(acc) : "l"(a), "l"(b));
}
__device__ __forceinline__ ull pack2(float x, float y) {
    ull r;
    asm("mov.b64 %0, {%1, %2};" : "=l"(r) : "f"(x), "f"(y));
    return r;
}
__device__ __forceinline__ void unpack2(ull v, float& x, float& y) {
    asm("mov.b64 {%0, %1}, %2;" : "=f"(x), "=f"(y) : "l"(v));
}
__device__ __forceinline__ float gelu_exact(float v) {
    return 0.5f * v * (1.0f + erff(v * 0.70710678118654752f));
}
__device__ __forceinline__ float warp_sum(float v) {
#pragma unroll
    for (int o = 16; o > 0; o >>= 1) v += __shfl_xor_sync(0xffffffffu, v, o);
    return v;
}
__device__ __forceinline__ float warp_max(float v) {
#pragma unroll
    for (int o = 16; o > 0; o >>= 1) v = fmaxf(v, __shfl_xor_sync(0xffffffffu, v, o));
    return v;
}
__device__ __forceinline__ int scatter_dst(int row) {
    int w = row / 49, n = row % 49;
    int bb = w >> 8, rr = w & 255;
    int wi = rr >> 4, wj = rr & 15;
    int i = n / 7, j = n % 7;
    int hh = wi * 7 + i + 3; if (hh >= 112) hh -= 112;
    int ww = wj * 7 + j + 3; if (ww >= 112) ww -= 112;
    return bb * 12544 + hh * 112 + ww;
}

// ---------------- weight transpose: W[K,N] -> Wt [N,K] bf16 ----------------
__global__ void wprep_kernel(const float* __restrict__ W, __nv_bfloat16* __restrict__ T,
                             int K, int N) {
    int i = blockIdx.x * 256 + threadIdx.x;
    if (i >= K * N) return;
    int k = i / N, n = i - k * N;
    T[(size_t)n * K + k] = __float2bfloat16(W[i]);
}

// ---------------- LayerNorm (+ optional shift/window gather) ----------------
template <bool GATHER>
__global__ void ln_kernel(const float* __restrict__ in,
                          const float* __restrict__ gamma, const float* __restrict__ beta,
                          __nv_bfloat16* __restrict__ oh) {
    int t = blockIdx.x, c = threadIdx.x;
    int src = GATHER ? scatter_dst(t) : t;
    float v = in[(size_t)src * C_DIM + c];
    __shared__ float s1[6], s2[6];
    int wid = c >> 5, lid = c & 31;
    float s = warp_sum(v);
    if (lid == 0) s1[wid] = s;
    __syncthreads();
    float mean = (s1[0] + s1[1] + s1[2] + s1[3] + s1[4] + s1[5]) * (1.0f / 192.0f);
    float d = v - mean;
    float sq = warp_sum(d * d);
    if (lid == 0) s2[wid] = sq;
    __syncthreads();
    float var = (s2[0] + s2[1] + s2[2] + s2[3] + s2[4] + s2[5]) * (1.0f / 192.0f);
    float o = d * rsqrtf(var + 1e-5f) * gamma[c] + beta[c];
    oh[(size_t)t * C_DIM + c] = __float2bfloat16(o);
}

// ---------------- HMMA GEMM: A bf16, W bf16, 4-stage ----------------
enum { EPI_BF16 = 0, EPI_GELU = 1, EPI_SCATTER = 2, EPI_RES = 3 };

template <int EPI>
__global__ __launch_bounds__(256, 2)
void gemm_mma(const __nv_bfloat16* __restrict__ Aact,
              const __nv_bfloat16* __restrict__ Bw,
              const float* __restrict__ bias, const float* __restrict__ res,
              float* __restrict__ outf, __nv_bfloat16* __restrict__ outb,
              int K, int Nout) {
    extern __shared__ __align__(16) char smem[];
    int tid = threadIdx.x;
    int wid = tid >> 5, lid = tid & 31;
    int wm = wid & 3, wn = wid >> 2;            // 4 x 2 warps
    int mBase = blockIdx.y * BM;
    int nBase = blockIdx.x * BN;
    uint32_t sb = smem_u32(smem);

    float acc[2][4][4];
#pragma unroll
    for (int a = 0; a < 2; a++)
#pragma unroll
        for (int b = 0; b < 4; b++)
#pragma unroll
            for (int c = 0; c < 4; c++) acc[a][b][c] = 0.0f;

    int nch = K / BK;

    auto issue = [&](int c) {
        uint32_t sbase = sb + (c % NSTAGE) * STAGE_BYTES;
        int k0 = c * BK;
#pragma unroll
        for (int u = 0; u < 3; u++) {
            int ch = tid + u * 256;
            if (ch < 512) {
                int r = ch >> 2, cc = ch & 3;
                cp16(sbase + OFF_A + r * RPB + cc * 16,
                     Aact + (size_t)(mBase + r) * K + k0 + cc * 8);
            } else {
                int q = ch - 512, r = q >> 2, cc = q & 3;
                cp16(sbase + OFF_B + r * RPB + cc * 16,
                     Bw + (size_t)(nBase + r) * K + k0 + cc * 8);
            }
        }
        cp_commit();
    };

    int aRow = wm * 32 + (lid & 7) + ((lid >> 3) & 1) * 8;
    int aKof = (lid >> 4) * 16;
    int bRow = wn * 32 + (lid & 7) + ((lid >> 4) & 1) * 8;
    int bKof = ((lid >> 3) & 1) * 16;

    issue(0);
    if (nch > 1) issue(1);
    if (nch > 2) issue(2);
    for (int c = 0; c < nch; c++) {
        int rem = nch - 1 - c;
        if (c + 3 < nch) issue(c + 3);
        if (rem >= 3)      cp_wait<3>();
        else if (rem == 2) cp_wait<2>();
        else if (rem == 1) cp_wait<1>();
        else               cp_wait<0>();
        __syncthreads();

        uint32_t buf = sb + (c % NSTAGE) * STAGE_BYTES;
#pragma unroll
        for (int kb = 0; kb < 64; kb += 32) {
            uint32_t ahf[2][4], bhf[2][4];
#pragma unroll
            for (int mt = 0; mt < 2; mt++) {
                uint32_t ad = buf + OFF_A + (aRow + mt * 16) * RPB + kb + aKof;
                ldsm_x4(ahf[mt], ad);
            }
#pragma unroll
            for (int half = 0; half < 2; half++) {
                uint32_t bd = buf + OFF_B + (bRow + half * 16) * RPB + kb + bKof;
                ldsm_x4(bhf[half], bd);
            }
#pragma unroll
            for (int mt = 0; mt < 2; mt++)
#pragma unroll
                for (int nt = 0; nt < 4; nt++) {
                    const uint32_t* bh = bhf[nt >> 1] + (nt & 1) * 2;
                    mma16816(acc[mt][nt], ahf[mt], bh);
                }
        }
        __syncthreads();
    }

    int g = lid >> 2, tq = lid & 3;
#pragma unroll
    for (int mt = 0; mt < 2; mt++) {
#pragma unroll
        for (int half = 0; half < 2; half++) {
            int row = mBase + wm * 32 + mt * 16 + g + half * 8;
            int dst = (EPI == EPI_SCATTER) ? scatter_dst(row) : row;
#pragma unroll
            for (int nt = 0; nt < 4; nt++) {
                int col = nBase + wn * 32 + nt * 8 + tq * 2;
                float v0 = acc[mt][nt][half * 2 + 0] + bias[col];
                float v1 = acc[mt][nt][half * 2 + 1] + bias[col + 1];
                if (EPI == EPI_GELU) {
                    v0 = gelu_exact(v0); v1 = gelu_exact(v1);
                }
                if (EPI == EPI_GELU || EPI == EPI_BF16) {
                    __nv_bfloat162 hp;
                    hp.x = __float2bfloat16(v0); hp.y = __float2bfloat16(v1);
                    *(__nv_bfloat162*)(outb + (size_t)row * Nout + col) = hp;
                } else {
                    size_t o = (size_t)dst * Nout + col;
                    float2 rv = *(const float2*)(res + o);
                    float2 w; w.x = v0 + rv.x; w.y = v1 + rv.y;
                    *(float2*)(outf + o) = w;
                }
            }
        }
    }
}

// ---------------- Windowed attention (bf16 qkv, f32x2 math) ----------------
__global__ void attn_kernel(const __nv_bfloat16* __restrict__ qkv,
                            const float* __restrict__ rpb,
                            __nv_bfloat16* __restrict__ oh) {
    int blk = blockIdx.x;
    int w = blk / NHEADS;
    int h = blk - w * NHEADS;

    // pitch 34 floats = 17 x 8B units/row -> conflict-free LDS.64 (17m+d distinct mod 16)
    __shared__ float sq[49][34], sk[49][34], sv[49][34];
    __shared__ float sa[49][49];

    int tid = threadIdx.x;
    const float scale = 0.17677669529663687f;

    for (int idx = tid; idx < 49 * 32; idx += 256) {
        int n = idx >> 5, d = idx & 31;
        size_t base = ((size_t)(w * 49 + n)) * (3 * C_DIM) + h * HDIM + d;
        sq[n][d] = __bfloat162float(qkv[base]) * scale;
        sk[n][d] = __bfloat162float(qkv[base + C_DIM]);
        sv[n][d] = __bfloat162float(qkv[base + 2 * C_DIM]);
    }
    __syncthreads();

    int r = w & 255;
    int wi = r >> 4, wj = r & 15;

    for (int e = tid; e < 49 * 49; e += 256) {
        int n = e / 49, m = e - n * 49;
        const ull* q2 = (const ull*)sq[n];
        const ull* k2 = (const ull*)sk[m];
        ull acc2 = pack2(0.0f, 0.0f);
#pragma unroll
        for (int d = 0; d < 16; d++) fma2(acc2, q2[d], k2[d]);
        float lo, hi;
        unpack2(acc2, lo, hi);
        float dot = lo + hi;
        int i1 = n / 7, j1 = n % 7, i2 = m / 7, j2 = m % 7;
        float b = rpb[((i1 - i2 + 6) * 13 + (j1 - j2 + 6)) * NHEADS + h];
        int hp1 = wi * 7 + i1, wp1 = wj * 7 + j1;
        int hp2 = wi * 7 + i2, wp2 = wj * 7 + j2;
        int reg1 = (hp1 < 105 ? 0 : (hp1 < 109 ? 1 : 2)) * 3 + (wp1 < 105 ? 0 : (wp1 < 109 ? 1 : 2));
        int reg2 = (hp2 < 105 ? 0 : (hp2 < 109 ? 1 : 2)) * 3 + (wp2 < 105 ? 0 : (wp2 < 109 ? 1 : 2));
        sa[n][m] = dot + b + (reg1 == reg2 ? 0.0f : -100.0f);
    }
    __syncthreads();

    int wid = tid >> 5, lid = tid & 31;
    for (int n = wid; n < 49; n += 8) {
        float v1 = sa[n][lid];
        float v2 = (lid < 17) ? sa[n][lid + 32] : -1e30f;
        float mx = warp_max(fmaxf(v1, v2));
        float e1 = __expf(v1 - mx);
        float e2 = (lid < 17) ? __expf(v2 - mx) : 0.0f;
        float s = warp_sum(e1 + e2);
        float inv = 1.0f / s;
        sa[n][lid] = e1 * inv;
        if (lid < 17) sa[n][lid + 32] = e2 * inv;
    }
    __syncthreads();

    // O = P @ V with packed pairs along d
    for (int idx = tid; idx < 49 * 16; idx += 256) {
        int n = idx >> 4, d2 = idx & 15;
        ull o2 = pack2(0.0f, 0.0f);
#pragma unroll 7
        for (int m = 0; m < 49; m++) {
            float a = sa[n][m];
            ull aa = pack2(a, a);
            ull v2 = ((const ull*)sv[m])[d2];
            fma2(o2, aa, v2);
        }
        float x0, x1;
        unpack2(o2, x0, x1);
        size_t oidx = ((size_t)(w * 49 + n)) * C_DIM + h * HDIM + d2 * 2;
        __nv_bfloat162 hp;
        hp.x = __float2bfloat16(x0); hp.y = __float2bfloat16(x1);
        *(__nv_bfloat162*)(oh + oidx) = hp;
    }
}

// ---------------- launch ----------------
extern "C" void kernel_launch(void* const* d_in, const int* in_sizes, int n_in,
                              void* d_out, int out_size) {
    const float* query   = (const float*)d_in[0];
    const float* norm1_g = (const float*)d_in[1];
    const float* norm1_b = (const float*)d_in[2];
    const float* qkv_w   = (const float*)d_in[3];
    const float* qkv_b   = (const float*)d_in[4];
    const float* rpb     = (const float*)d_in[5];
    const float* proj_w  = (const float*)d_in[6];
    const float* proj_b  = (const float*)d_in[7];
    const float* norm2_g = (const float*)d_in[8];
    const float* norm2_b = (const float*)d_in[9];
    const float* fc1_w   = (const float*)d_in[10];
    const float* fc1_b   = (const float*)d_in[11];
    const float* fc2_w   = (const float*)d_in[12];
    const float* fc2_b   = (const float*)d_in[13];
    float* out = (float*)d_out;

    __nv_bfloat16 *xw, *qkvp, *att, *ln2, *hbuf;
    __nv_bfloat16 *wq, *wp, *w1, *w2;
    float *x;
    cudaGetSymbolAddress((void**)&xw, g_xw);
    cudaGetSymbolAddress((void**)&qkvp, g_qkv);
    cudaGetSymbolAddress((void**)&att, g_att);
    cudaGetSymbolAddress((void**)&x, g_x);
    cudaGetSymbolAddress((void**)&ln2, g_ln2);
    cudaGetSymbolAddress((void**)&hbuf, g_h);
    cudaGetSymbolAddress((void**)&wq, g_wqkv);
    cudaGetSymbolAddress((void**)&wp, g_wprj);
    cudaGetSymbolAddress((void**)&w1, g_wfc1);
    cudaGetSymbolAddress((void**)&w2, g_wfc2);

    const int SMEM = NSTAGE * STAGE_BYTES;   // 61440
    cudaFuncSetAttribute(gemm_mma<EPI_BF16>,    cudaFuncAttributeMaxDynamicSharedMemorySize, SMEM);
    cudaFuncSetAttribute(gemm_mma<EPI_GELU>,    cudaFuncAttributeMaxDynamicSharedMemorySize, SMEM);
    cudaFuncSetAttribute(gemm_mma<EPI_SCATTER>, cudaFuncAttributeMaxDynamicSharedMemorySize, SMEM);
    cudaFuncSetAttribute(gemm_mma<EPI_RES>,     cudaFuncAttributeMaxDynamicSharedMemorySize, SMEM);

    wprep_kernel<<<(192 * 576 + 255) / 256, 256>>>(qkv_w,  wq, 192, 576);
    wprep_kernel<<<(192 * 192 + 255) / 256, 256>>>(proj_w, wp, 192, 192);
    wprep_kernel<<<(192 * 768 + 255) / 256, 256>>>(fc1_w,  w1, 192, 768);
    wprep_kernel<<<(768 * 192 + 255) / 256, 256>>>(fc2_w,  w2, 768, 192);

    // 1) LN1 + shift + window partition
    ln_kernel<true><<<M_TOK, 192>>>(query, norm1_g, norm1_b, xw);

    // 2) qkv  [100352,192] x [192,576] -> bf16
    gemm_mma<EPI_BF16><<<dim3(576 / BN, M_TOK / BM), 256, SMEM>>>(
        xw, wq, qkv_b, nullptr, nullptr, qkvp, 192, 576);

    // 3) windowed attention
    attn_kernel<<<2048 * NHEADS, 256>>>(qkvp, rpb, att);

    // 4) proj + window reverse + unshift + residual(query)
    gemm_mma<EPI_SCATTER><<<dim3(192 / BN, M_TOK / BM), 256, SMEM>>>(
        att, wp, proj_b, query, x, nullptr, 192, 192);

    // 5) LN2
    ln_kernel<false><<<M_TOK, 192>>>(x, norm2_g, norm2_b, ln2);

    // 6) fc1 + GELU
    gemm_mma<EPI_GELU><<<dim3(768 / BN, M_TOK / BM), 256, SMEM>>>(
        ln2, w1, fc1_b, nullptr, nullptr, hbuf, 192, 768);

    // 7) fc2 + residual(x) -> out
    gemm_mma<EPI_RES><<<dim3(192 / BN, M_TOK / BM), 256, SMEM>>>(
        hbuf, w2, fc2_b, x, out, nullptr, 768, 192);
}

// round 9
// speedup vs baseline: 1.6575x; 1.0211x over previous
#include <cuda_runtime.h>
#include <cuda_bf16.h>
#include <math.h>
#include <stdint.h>

#define M_TOK   100352
#define C_DIM   192
#define NHEADS  6
#define HDIM    32
#define HIDDEN  768

// GEMM-64 tiling: CTA 128x64, BK=32, 256 thr (8 warps 4x2), warp tile 32x32
#define BM 128
#define BN 64
#define BK 32
#define RPB 80                 // smem row pitch bytes (40 bf16)
#define OFF_A  0
#define OFF_B  (BM*RPB)                 // 10240
#define STAGE_BYTES (BM*RPB + BN*RPB)   // 15360
#define NSTAGE 4

// GEMM-192 tiling: CTA 64x192, BK=32, 256 thr (8 warps 2x4), warp tile 32x48
#define BM2 64
#define BN2 192
#define OFF_B2 (BM2*RPB)                // 5120
#define STAGE2 (BM2*RPB + BN2*RPB)      // 20480

typedef unsigned long long ull;

// ---------------- scratch ----------------
__device__ __nv_bfloat16 g_xw  [(size_t)M_TOK * C_DIM];
__device__ __nv_bfloat16 g_qkv [(size_t)M_TOK * 3 * C_DIM];
__device__ __nv_bfloat16 g_att [(size_t)M_TOK * C_DIM];
__device__ float         g_x   [(size_t)M_TOK * C_DIM];
__device__ __nv_bfloat16 g_ln2 [(size_t)M_TOK * C_DIM];
__device__ __nv_bfloat16 g_h   [(size_t)M_TOK * HIDDEN];
// transposed bf16 weights [N, K]
__device__ __nv_bfloat16 g_wqkv[576 * 192];
__device__ __nv_bfloat16 g_wprj[192 * 192];
__device__ __nv_bfloat16 g_wfc1[768 * 192];
__device__ __nv_bfloat16 g_wfc2[192 * 768];

// ---------------- helpers ----------------
__device__ __forceinline__ uint32_t smem_u32(const void* p) {
    uint32_t a;
    asm("{ .reg .u64 t; cvta.to.shared.u64 t, %1; cvt.u32.u64 %0, t; }" : "=r"(a) : "l"(p));
    return a;
}
__device__ __forceinline__ void cp16(uint32_t sa, const void* g) {
    asm volatile("cp.async.cg.shared.global [%0], [%1], 16;" :: "r"(sa), "l"(g));
}
__device__ __forceinline__ void cp_commit() { asm volatile("cp.async.commit_group;"); }
template <int N>
__device__ __forceinline__ void cp_wait() { asm volatile("cp.async.wait_group %0;" :: "n"(N)); }

__device__ __forceinline__ void ldsm_x4(uint32_t* r, uint32_t addr) {
    asm volatile("ldmatrix.sync.aligned.m8n8.x4.shared.b16 {%0,%1,%2,%3}, [%4];"
        : "=r"(r[0]), "=r"(r[1]), "=r"(r[2]), "=r"(r[3]) : "r"(addr));
}
__device__ __forceinline__ void mma16816(float* c, const uint32_t* a, const uint32_t* b) {
    asm volatile("mma.sync.aligned.m16n8k16.row.col.f32.bf16.bf16.f32 "
        "{%0,%1,%2,%3}, {%4,%5,%6,%7}, {%8,%9}, {%0,%1,%2,%3};"
        : "+f"(c[0]), "+f"(c[1]), "+f"(c[2]), "+f"(c[3])
        : "r"(a[0]), "r"(a[1]), "r"(a[2]), "r"(a[3]), "r"(b[0]), "r"(b[1]));
}
__device__ __forceinline__ void fma2(ull& acc, ull a, ull b) {
    asm("fma.rn.f32x2 %0, %1, %2, %0;" : "+l"(acc) : "l"(a), "l"(b));
}
__device__ __forceinline__ ull pack2(float x, float y) {
    ull r;
    asm("mov.b64 %0, {%1, %2};" : "=l"(r) : "f"(x), "f"(y));
    return r;
}
__device__ __forceinline__ void unpack2(ull v, float& x, float& y) {
    asm("mov.b64 {%0, %1}, %2;" : "=f"(x), "=f"(y) : "l"(v));
}
__device__ __forceinline__ float gelu_exact(float v) {
    return 0.5f * v * (1.0f + erff(v * 0.70710678118654752f));
}
__device__ __forceinline__ float warp_sum(float v) {
#pragma unroll
    for (int o = 16; o > 0; o >>= 1) v += __shfl_xor_sync(0xffffffffu, v, o);
    return v;
}
__device__ __forceinline__ float warp_max(float v) {
#pragma unroll
    for (int o = 16; o > 0; o >>= 1) v = fmaxf(v, __shfl_xor_sync(0xffffffffu, v, o));
    return v;
}
__device__ __forceinline__ int scatter_dst(int row) {
    int w = row / 49, n = row % 49;
    int bb = w >> 8, rr = w & 255;
    int wi = rr >> 4, wj = rr & 15;
    int i = n / 7, j = n % 7;
    int hh = wi * 7 + i + 3; if (hh >= 112) hh -= 112;
    int ww = wj * 7 + j + 3; if (ww >= 112) ww -= 112;
    return bb * 12544 + hh * 112 + ww;
}

// ---------------- combined weight transpose: 4 weights in one launch ----------------
__global__ void wprep_all(const float* __restrict__ Wq, const float* __restrict__ Wp,
                          const float* __restrict__ W1, const float* __restrict__ W2,
                          __nv_bfloat16* __restrict__ Tq, __nv_bfloat16* __restrict__ Tp,
                          __nv_bfloat16* __restrict__ T1, __nv_bfloat16* __restrict__ T2) {
    int i = blockIdx.x * 256 + threadIdx.x;
    // ranges: qkv 110592, proj 36864, fc1 147456, fc2 147456
    if (i < 110592) {
        int k = i / 576, n = i % 576;
        Tq[(size_t)n * 192 + k] = __float2bfloat16(Wq[i]);
    } else if (i < 147456) {
        int j = i - 110592;
        int k = j / 192, n = j % 192;
        Tp[(size_t)n * 192 + k] = __float2bfloat16(Wp[j]);
    } else if (i < 294912) {
        int j = i - 147456;
        int k = j / 768, n = j % 768;
        T1[(size_t)n * 192 + k] = __float2bfloat16(W1[j]);
    } else if (i < 442368) {
        int j = i - 294912;
        int k = j / 192, n = j % 192;
        T2[(size_t)n * 768 + k] = __float2bfloat16(W2[j]);
    }
}

// ---------------- LayerNorm (+ optional shift/window gather) ----------------
template <bool GATHER>
__global__ void ln_kernel(const float* __restrict__ in,
                          const float* __restrict__ gamma, const float* __restrict__ beta,
                          __nv_bfloat16* __restrict__ oh) {
    int t = blockIdx.x, c = threadIdx.x;
    int src = GATHER ? scatter_dst(t) : t;
    float v = in[(size_t)src * C_DIM + c];
    __shared__ float s1[6], s2[6];
    int wid = c >> 5, lid = c & 31;
    float s = warp_sum(v);
    if (lid == 0) s1[wid] = s;
    __syncthreads();
    float mean = (s1[0] + s1[1] + s1[2] + s1[3] + s1[4] + s1[5]) * (1.0f / 192.0f);
    float d = v - mean;
    float sq = warp_sum(d * d);
    if (lid == 0) s2[wid] = sq;
    __syncthreads();
    float var = (s2[0] + s2[1] + s2[2] + s2[3] + s2[4] + s2[5]) * (1.0f / 192.0f);
    float o = d * rsqrtf(var + 1e-5f) * gamma[c] + beta[c];
    oh[(size_t)t * C_DIM + c] = __float2bfloat16(o);
}

enum { EPI_BF16 = 0, EPI_GELU = 1, EPI_SCATTER = 2, EPI_RES = 3 };

// ---------------- GEMM-64: A bf16 x W bf16, CTA 128x64 ----------------
template <int EPI>
__global__ __launch_bounds__(256, 2)
void gemm_mma(const __nv_bfloat16* __restrict__ Aact,
              const __nv_bfloat16* __restrict__ Bw,
              const float* __restrict__ bias, const float* __restrict__ res,
              float* __restrict__ outf, __nv_bfloat16* __restrict__ outb,
              int K, int Nout) {
    extern __shared__ __align__(16) char smem[];
    int tid = threadIdx.x;
    int wid = tid >> 5, lid = tid & 31;
    int wm = wid & 3, wn = wid >> 2;
    int mBase = blockIdx.y * BM;
    int nBase = blockIdx.x * BN;
    uint32_t sb = smem_u32(smem);

    float acc[2][4][4];
#pragma unroll
    for (int a = 0; a < 2; a++)
#pragma unroll
        for (int b = 0; b < 4; b++)
#pragma unroll
            for (int c = 0; c < 4; c++) acc[a][b][c] = 0.0f;

    int nch = K / BK;

    auto issue = [&](int c) {
        uint32_t sbase = sb + (c % NSTAGE) * STAGE_BYTES;
        int k0 = c * BK;
#pragma unroll
        for (int u = 0; u < 3; u++) {
            int ch = tid + u * 256;
            if (ch < 512) {
                int r = ch >> 2, cc = ch & 3;
                cp16(sbase + OFF_A + r * RPB + cc * 16,
                     Aact + (size_t)(mBase + r) * K + k0 + cc * 8);
            } else {
                int q = ch - 512, r = q >> 2, cc = q & 3;
                cp16(sbase + OFF_B + r * RPB + cc * 16,
                     Bw + (size_t)(nBase + r) * K + k0 + cc * 8);
            }
        }
        cp_commit();
    };

    int aRow = wm * 32 + (lid & 7) + ((lid >> 3) & 1) * 8;
    int aKof = (lid >> 4) * 16;
    int bRow = wn * 32 + (lid & 7) + ((lid >> 4) & 1) * 8;
    int bKof = ((lid >> 3) & 1) * 16;

    issue(0);
    if (nch > 1) issue(1);
    if (nch > 2) issue(2);
    for (int c = 0; c < nch; c++) {
        int rem = nch - 1 - c;
        if (c + 3 < nch) issue(c + 3);
        if (rem >= 3)      cp_wait<3>();
        else if (rem == 2) cp_wait<2>();
        else if (rem == 1) cp_wait<1>();
        else               cp_wait<0>();
        __syncthreads();

        uint32_t buf = sb + (c % NSTAGE) * STAGE_BYTES;
#pragma unroll
        for (int kb = 0; kb < 64; kb += 32) {
            uint32_t ahf[2][4], bhf[2][4];
#pragma unroll
            for (int mt = 0; mt < 2; mt++)
                ldsm_x4(ahf[mt], buf + OFF_A + (aRow + mt * 16) * RPB + kb + aKof);
#pragma unroll
            for (int half = 0; half < 2; half++)
                ldsm_x4(bhf[half], buf + OFF_B + (bRow + half * 16) * RPB + kb + bKof);
#pragma unroll
            for (int mt = 0; mt < 2; mt++)
#pragma unroll
                for (int nt = 0; nt < 4; nt++)
                    mma16816(acc[mt][nt], ahf[mt], bhf[nt >> 1] + (nt & 1) * 2);
        }
        __syncthreads();
    }

    int g = lid >> 2, tq = lid & 3;
#pragma unroll
    for (int mt = 0; mt < 2; mt++) {
#pragma unroll
        for (int half = 0; half < 2; half++) {
            int row = mBase + wm * 32 + mt * 16 + g + half * 8;
            int dst = (EPI == EPI_SCATTER) ? scatter_dst(row) : row;
#pragma unroll
            for (int nt = 0; nt < 4; nt++) {
                int col = nBase + wn * 32 + nt * 8 + tq * 2;
                float v0 = acc[mt][nt][half * 2 + 0] + bias[col];
                float v1 = acc[mt][nt][half * 2 + 1] + bias[col + 1];
                if (EPI == EPI_GELU) {
                    v0 = gelu_exact(v0); v1 = gelu_exact(v1);
                }
                if (EPI == EPI_GELU || EPI == EPI_BF16) {
                    __nv_bfloat162 hp;
                    hp.x = __float2bfloat16(v0); hp.y = __float2bfloat16(v1);
                    *(__nv_bfloat162*)(outb + (size_t)row * Nout + col) = hp;
                } else {
                    size_t o = (size_t)dst * Nout + col;
                    float2 rv = *(const float2*)(res + o);
                    float2 w; w.x = v0 + rv.x; w.y = v1 + rv.y;
                    *(float2*)(outf + o) = w;
                }
            }
        }
    }
}

// ---------------- GEMM-192: CTA 64x192, full-N tile (A read once) ----------------
template <int EPI>
__global__ __launch_bounds__(256, 2)
void gemm_mma_n192(const __nv_bfloat16* __restrict__ Aact,
                   const __nv_bfloat16* __restrict__ Bw,
                   const float* __restrict__ bias, const float* __restrict__ res,
                   float* __restrict__ outf, int K) {
    extern __shared__ __align__(16) char smem[];
    const int Nout = 192;
    int tid = threadIdx.x;
    int wid = tid >> 5, lid = tid & 31;
    int wm = wid & 1, wn = wid >> 1;            // 2 M x 4 N warps
    int mBase = blockIdx.y * BM2;
    uint32_t sb = smem_u32(smem);

    float acc[2][6][4];
#pragma unroll
    for (int a = 0; a < 2; a++)
#pragma unroll
        for (int b = 0; b < 6; b++)
#pragma unroll
            for (int c = 0; c < 4; c++) acc[a][b][c] = 0.0f;

    int nch = K / BK;

    auto issue = [&](int c) {
        uint32_t sbase = sb + (c % NSTAGE) * STAGE2;
        int k0 = c * BK;
        // 1024 chunks: [0,256) A (64 rows x 4), [256,1024) B (192 rows x 4)
#pragma unroll
        for (int u = 0; u < 4; u++) {
            int ch = tid + u * 256;
            if (ch < 256) {
                int r = ch >> 2, cc = ch & 3;
                cp16(sbase + r * RPB + cc * 16,
                     Aact + (size_t)(mBase + r) * K + k0 + cc * 8);
            } else {
                int q = ch - 256, r = q >> 2, cc = q & 3;
                cp16(sbase + OFF_B2 + r * RPB + cc * 16,
                     Bw + (size_t)r * K + k0 + cc * 8);
            }
        }
        cp_commit();
    };

    int aRow = wm * 32 + (lid & 7) + ((lid >> 3) & 1) * 8;
    int aKof = (lid >> 4) * 16;
    int bRow = wn * 48 + (lid & 7) + ((lid >> 4) & 1) * 8;
    int bKof = ((lid >> 3) & 1) * 16;

    issue(0);
    if (nch > 1) issue(1);
    if (nch > 2) issue(2);
    for (int c = 0; c < nch; c++) {
        int rem = nch - 1 - c;
        if (c + 3 < nch) issue(c + 3);
        if (rem >= 3)      cp_wait<3>();
        else if (rem == 2) cp_wait<2>();
        else if (rem == 1) cp_wait<1>();
        else               cp_wait<0>();
        __syncthreads();

        uint32_t buf = sb + (c % NSTAGE) * STAGE2;
#pragma unroll
        for (int kb = 0; kb < 64; kb += 32) {
            uint32_t ahf[2][4], bhf[3][4];
#pragma unroll
            for (int mt = 0; mt < 2; mt++)
                ldsm_x4(ahf[mt], buf + (aRow + mt * 16) * RPB + kb + aKof);
#pragma unroll
            for (int nb = 0; nb < 3; nb++)
                ldsm_x4(bhf[nb], buf + OFF_B2 + (bRow + nb * 16) * RPB + kb + bKof);
#pragma unroll
            for (int mt = 0; mt < 2; mt++)
#pragma unroll
                for (int nt = 0; nt < 6; nt++)
                    mma16816(acc[mt][nt], ahf[mt], bhf[nt >> 1] + (nt & 1) * 2);
        }
        __syncthreads();
    }

    int g = lid >> 2, tq = lid & 3;
#pragma unroll
    for (int mt = 0; mt < 2; mt++) {
#pragma unroll
        for (int half = 0; half < 2; half++) {
            int row = mBase + wm * 32 + mt * 16 + g + half * 8;
            int dst = (EPI == EPI_SCATTER) ? scatter_dst(row) : row;
#pragma unroll
            for (int nt = 0; nt < 6; nt++) {
                int col = wn * 48 + nt * 8 + tq * 2;
                float v0 = acc[mt][nt][half * 2 + 0] + bias[col];
                float v1 = acc[mt][nt][half * 2 + 1] + bias[col + 1];
                size_t o = (size_t)dst * Nout + col;
                float2 rv = *(const float2*)(res + o);
                float2 w; w.x = v0 + rv.x; w.y = v1 + rv.y;
                *(float2*)(outf + o) = w;
            }
        }
    }
}

// ---------------- Windowed attention (bf16 qkv, f32x2 math) ----------------
__global__ void attn_kernel(const __nv_bfloat16* __restrict__ qkv,
                            const float* __restrict__ rpb,
                            __nv_bfloat16* __restrict__ oh) {
    int blk = blockIdx.x;
    int w = blk / NHEADS;
    int h = blk - w * NHEADS;

    __shared__ float sq[49][34], sk[49][34], sv[49][34];
    __shared__ float sa[49][49];

    int tid = threadIdx.x;
    const float scale = 0.17677669529663687f;

    for (int idx = tid; idx < 49 * 32; idx += 256) {
        int n = idx >> 5, d = idx & 31;
        size_t base = ((size_t)(w * 49 + n)) * (3 * C_DIM) + h * HDIM + d;
        sq[n][d] = __bfloat162float(qkv[base]) * scale;
        sk[n][d] = __bfloat162float(qkv[base + C_DIM]);
        sv[n][d] = __bfloat162float(qkv[base + 2 * C_DIM]);
    }
    __syncthreads();

    int r = w & 255;
    int wi = r >> 4, wj = r & 15;

    for (int e = tid; e < 49 * 49; e += 256) {
        int n = e / 49, m = e - n * 49;
        const ull* q2 = (const ull*)sq[n];
        const ull* k2 = (const ull*)sk[m];
        ull acc2 = pack2(0.0f, 0.0f);
#pragma unroll
        for (int d = 0; d < 16; d++) fma2(acc2, q2[d], k2[d]);
        float lo, hi;
        unpack2(acc2, lo, hi);
        float dot = lo + hi;
        int i1 = n / 7, j1 = n % 7, i2 = m / 7, j2 = m % 7;
        float b = rpb[((i1 - i2 + 6) * 13 + (j1 - j2 + 6)) * NHEADS + h];
        int hp1 = wi * 7 + i1, wp1 = wj * 7 + j1;
        int hp2 = wi * 7 + i2, wp2 = wj * 7 + j2;
        int reg1 = (hp1 < 105 ? 0 : (hp1 < 109 ? 1 : 2)) * 3 + (wp1 < 105 ? 0 : (wp1 < 109 ? 1 : 2));
        int reg2 = (hp2 < 105 ? 0 : (hp2 < 109 ? 1 : 2)) * 3 + (wp2 < 105 ? 0 : (wp2 < 109 ? 1 : 2));
        sa[n][m] = dot + b + (reg1 == reg2 ? 0.0f : -100.0f);
    }
    __syncthreads();

    int wid = tid >> 5, lid = tid & 31;
    for (int n = wid; n < 49; n += 8) {
        float v1 = sa[n][lid];
        float v2 = (lid < 17) ? sa[n][lid + 32] : -1e30f;
        float mx = warp_max(fmaxf(v1, v2));
        float e1 = __expf(v1 - mx);
        float e2 = (lid < 17) ? __expf(v2 - mx) : 0.0f;
        float s = warp_sum(e1 + e2);
        float inv = 1.0f / s;
        sa[n][lid] = e1 * inv;
        if (lid < 17) sa[n][lid + 32] = e2 * inv;
    }
    __syncthreads();

    for (int idx = tid; idx < 49 * 16; idx += 256) {
        int n = idx >> 4, d2 = idx & 15;
        ull o2 = pack2(0.0f, 0.0f);
#pragma unroll 7
        for (int m = 0; m < 49; m++) {
            float a = sa[n][m];
            ull aa = pack2(a, a);
            ull v2 = ((const ull*)sv[m])[d2];
            fma2(o2, aa, v2);
        }
        float x0, x1;
        unpack2(o2, x0, x1);
        size_t oidx = ((size_t)(w * 49 + n)) * C_DIM + h * HDIM + d2 * 2;
        __nv_bfloat162 hp;
        hp.x = __float2bfloat16(x0); hp.y = __float2bfloat16(x1);
        *(__nv_bfloat162*)(oh + oidx) = hp;
    }
}

// ---------------- launch ----------------
extern "C" void kernel_launch(void* const* d_in, const int* in_sizes, int n_in,
                              void* d_out, int out_size) {
    const float* query   = (const float*)d_in[0];
    const float* norm1_g = (const float*)d_in[1];
    const float* norm1_b = (const float*)d_in[2];
    const float* qkv_w   = (const float*)d_in[3];
    const float* qkv_b   = (const float*)d_in[4];
    const float* rpb     = (const float*)d_in[5];
    const float* proj_w  = (const float*)d_in[6];
    const float* proj_b  = (const float*)d_in[7];
    const float* norm2_g = (const float*)d_in[8];
    const float* norm2_b = (const float*)d_in[9];
    const float* fc1_w   = (const float*)d_in[10];
    const float* fc1_b   = (const float*)d_in[11];
    const float* fc2_w   = (const float*)d_in[12];
    const float* fc2_b   = (const float*)d_in[13];
    float* out = (float*)d_out;

    __nv_bfloat16 *xw, *qkvp, *att, *ln2, *hbuf;
    __nv_bfloat16 *wq, *wp, *w1, *w2;
    float *x;
    cudaGetSymbolAddress((void**)&xw, g_xw);
    cudaGetSymbolAddress((void**)&qkvp, g_qkv);
    cudaGetSymbolAddress((void**)&att, g_att);
    cudaGetSymbolAddress((void**)&x, g_x);
    cudaGetSymbolAddress((void**)&ln2, g_ln2);
    cudaGetSymbolAddress((void**)&hbuf, g_h);
    cudaGetSymbolAddress((void**)&wq, g_wqkv);
    cudaGetSymbolAddress((void**)&wp, g_wprj);
    cudaGetSymbolAddress((void**)&w1, g_wfc1);
    cudaGetSymbolAddress((void**)&w2, g_wfc2);

    const int SMEM  = NSTAGE * STAGE_BYTES;  // 61440
    const int SMEM2 = NSTAGE * STAGE2;       // 81920
    cudaFuncSetAttribute(gemm_mma<EPI_BF16>, cudaFuncAttributeMaxDynamicSharedMemorySize, SMEM);
    cudaFuncSetAttribute(gemm_mma<EPI_GELU>, cudaFuncAttributeMaxDynamicSharedMemorySize, SMEM);
    cudaFuncSetAttribute(gemm_mma_n192<EPI_SCATTER>, cudaFuncAttributeMaxDynamicSharedMemorySize, SMEM2);
    cudaFuncSetAttribute(gemm_mma_n192<EPI_RES>,     cudaFuncAttributeMaxDynamicSharedMemorySize, SMEM2);

    // weight prep (one launch)
    wprep_all<<<(442368 + 255) / 256, 256>>>(qkv_w, proj_w, fc1_w, fc2_w, wq, wp, w1, w2);

    // 1) LN1 + shift + window partition
    ln_kernel<true><<<M_TOK, 192>>>(query, norm1_g, norm1_b, xw);

    // 2) qkv  [100352,192] x [192,576] -> bf16
    gemm_mma<EPI_BF16><<<dim3(576 / BN, M_TOK / BM), 256, SMEM>>>(
        xw, wq, qkv_b, nullptr, nullptr, qkvp, 192, 576);

    // 3) windowed attention
    attn_kernel<<<2048 * NHEADS, 256>>>(qkvp, rpb, att);

    // 4) proj + window reverse + unshift + residual(query)  (full-N tile)
    gemm_mma_n192<EPI_SCATTER><<<dim3(1, M_TOK / BM2), 256, SMEM2>>>(
        att, wp, proj_b, query, x, 192);

    // 5) LN2
    ln_kernel<false><<<M_TOK, 192>>>(x, norm2_g, norm2_b, ln2);

    // 6) fc1 + GELU
    gemm_mma<EPI_GELU><<<dim3(768 / BN, M_TOK / BM), 256, SMEM>>>(
        ln2, w1, fc1_b, nullptr, nullptr, hbuf, 192, 768);

    // 7) fc2 + residual(x) -> out  (full-N tile, A read once)
    gemm_mma_n192<EPI_RES><<<dim3(1, M_TOK / BM2), 256, SMEM2>>>(
        hbuf, w2, fc2_b, x, out, 768);
}

// round 10
// speedup vs baseline: 1.6824x; 1.0150x over previous
#include <cuda_runtime.h>
#include <cuda_bf16.h>
#include <math.h>
#include <stdint.h>

#define M_TOK   100352
#define C_DIM   192
#define NHEADS  6
#define HDIM    32
#define HIDDEN  768

// GEMM-64 tiling: CTA 128x64, BK=32, 256 thr (8 warps 4x2), warp tile 32x32
#define BM 128
#define BN 64
#define BK 32
#define RPB 80                 // smem row pitch bytes (40 bf16)
#define OFF_A  0
#define OFF_B  (BM*RPB)                 // 10240
#define STAGE_BYTES (BM*RPB + BN*RPB)   // 15360
#define NSTAGE 4

// GEMM-192 tiling: CTA 64x192, BK=32, 256 thr (8 warps 2x4), warp tile 32x48
#define BM2 64
#define BN2 192
#define OFF_B2 (BM2*RPB)                // 5120
#define STAGE2 (BM2*RPB + BN2*RPB)      // 20480

typedef unsigned long long ull;

// ---------------- scratch ----------------
__device__ __nv_bfloat16 g_xw  [(size_t)M_TOK * C_DIM];
__device__ __nv_bfloat16 g_qkv [(size_t)M_TOK * 3 * C_DIM];
__device__ __nv_bfloat16 g_att [(size_t)M_TOK * C_DIM];
__device__ float         g_x   [(size_t)M_TOK * C_DIM];
__device__ __nv_bfloat16 g_ln2 [(size_t)M_TOK * C_DIM];
__device__ __nv_bfloat16 g_h   [(size_t)M_TOK * HIDDEN];
// transposed bf16 weights [N, K]
__device__ __nv_bfloat16 g_wqkv[576 * 192];
__device__ __nv_bfloat16 g_wprj[192 * 192];
__device__ __nv_bfloat16 g_wfc1[768 * 192];
__device__ __nv_bfloat16 g_wfc2[192 * 768];

// ---------------- helpers ----------------
__device__ __forceinline__ uint32_t smem_u32(const void* p) {
    uint32_t a;
    asm("{ .reg .u64 t; cvta.to.shared.u64 t, %1; cvt.u32.u64 %0, t; }" : "=r"(a) : "l"(p));
    return a;
}
__device__ __forceinline__ void cp16(uint32_t sa, const void* g) {
    asm volatile("cp.async.cg.shared.global [%0], [%1], 16;" :: "r"(sa), "l"(g));
}
__device__ __forceinline__ void cp_commit() { asm volatile("cp.async.commit_group;"); }
template <int N>
__device__ __forceinline__ void cp_wait() { asm volatile("cp.async.wait_group %0;" :: "n"(N)); }

__device__ __forceinline__ void ldsm_x4(uint32_t* r, uint32_t addr) {
    asm volatile("ldmatrix.sync.aligned.m8n8.x4.shared.b16 {%0,%1,%2,%3}, [%4];"
        : "=r"(r[0]), "=r"(r[1]), "=r"(r[2]), "=r"(r[3]) : "r"(addr));
}
__device__ __forceinline__ void mma16816(float* c, const uint32_t* a, const uint32_t* b) {
    asm volatile("mma.sync.aligned.m16n8k16.row.col.f32.bf16.bf16.f32 "
        "{%0,%1,%2,%3}, {%4,%5,%6,%7}, {%8,%9}, {%0,%1,%2,%3};"
        : "+f"(c[0]), "+f"(c[1]), "+f"(c[2]), "+f"(c[3])
        : "r"(a[0]), "r"(a[1]), "r"(a[2]), "r"(a[3]), "r"(b[0]), "r"(b[1]));
}
__device__ __forceinline__ void fma2(ull& acc, ull a, ull b) {
    asm("fma.rn.f32x2 %0, %1, %2, %0;" : "+l"(acc) : "l"(a), "l"(b));
}
__device__ __forceinline__ ull pack2(float x, float y) {
    ull r;
    asm("mov.b64 %0, {%1, %2};" : "=l"(r) : "f"(x), "f"(y));
    return r;
}
__device__ __forceinline__ void unpack2(ull v, float& x, float& y) {
    asm("mov.b64 {%0, %1}, %2;" : "=f"(x), "=f"(y) : "l"(v));
}
__device__ __forceinline__ float gelu_exact(float v) {
    return 0.5f * v * (1.0f + erff(v * 0.70710678118654752f));
}
__device__ __forceinline__ float warp_sum(float v) {
#pragma unroll
    for (int o = 16; o > 0; o >>= 1) v += __shfl_xor_sync(0xffffffffu, v, o);
    return v;
}
__device__ __forceinline__ float warp_max(float v) {
#pragma unroll
    for (int o = 16; o > 0; o >>= 1) v = fmaxf(v, __shfl_xor_sync(0xffffffffu, v, o));
    return v;
}
__device__ __forceinline__ int scatter_dst(int row) {
    int w = row / 49, n = row % 49;
    int bb = w >> 8, rr = w & 255;
    int wi = rr >> 4, wj = rr & 15;
    int i = n / 7, j = n % 7;
    int hh = wi * 7 + i + 3; if (hh >= 112) hh -= 112;
    int ww = wj * 7 + j + 3; if (ww >= 112) ww -= 112;
    return bb * 12544 + hh * 112 + ww;
}

// ---------------- combined weight transpose ----------------
__global__ void wprep_all(const float* __restrict__ Wq, const float* __restrict__ Wp,
                          const float* __restrict__ W1, const float* __restrict__ W2,
                          __nv_bfloat16* __restrict__ Tq, __nv_bfloat16* __restrict__ Tp,
                          __nv_bfloat16* __restrict__ T1, __nv_bfloat16* __restrict__ T2) {
    int i = blockIdx.x * 256 + threadIdx.x;
    if (i < 110592) {
        int k = i / 576, n = i % 576;
        Tq[(size_t)n * 192 + k] = __float2bfloat16(Wq[i]);
    } else if (i < 147456) {
        int j = i - 110592;
        int k = j / 192, n = j % 192;
        Tp[(size_t)n * 192 + k] = __float2bfloat16(Wp[j]);
    } else if (i < 294912) {
        int j = i - 147456;
        int k = j / 768, n = j % 768;
        T1[(size_t)n * 192 + k] = __float2bfloat16(W1[j]);
    } else if (i < 442368) {
        int j = i - 294912;
        int k = j / 192, n = j % 192;
        T2[(size_t)n * 768 + k] = __float2bfloat16(W2[j]);
    }
}

// ---------------- LayerNorm (+ optional shift/window gather) ----------------
template <bool GATHER>
__global__ void ln_kernel(const float* __restrict__ in,
                          const float* __restrict__ gamma, const float* __restrict__ beta,
                          __nv_bfloat16* __restrict__ oh) {
    int t = blockIdx.x, c = threadIdx.x;
    int src = GATHER ? scatter_dst(t) : t;
    float v = in[(size_t)src * C_DIM + c];
    __shared__ float s1[6], s2[6];
    int wid = c >> 5, lid = c & 31;
    float s = warp_sum(v);
    if (lid == 0) s1[wid] = s;
    __syncthreads();
    float mean = (s1[0] + s1[1] + s1[2] + s1[3] + s1[4] + s1[5]) * (1.0f / 192.0f);
    float d = v - mean;
    float sq = warp_sum(d * d);
    if (lid == 0) s2[wid] = sq;
    __syncthreads();
    float var = (s2[0] + s2[1] + s2[2] + s2[3] + s2[4] + s2[5]) * (1.0f / 192.0f);
    float o = d * rsqrtf(var + 1e-5f) * gamma[c] + beta[c];
    oh[(size_t)t * C_DIM + c] = __float2bfloat16(o);
}

enum { EPI_BF16 = 0, EPI_GELU = 1, EPI_SCATTER = 2, EPI_RES = 3 };

// ---------------- GEMM-64: CTA 128x64 ----------------
template <int EPI>
__global__ __launch_bounds__(256, 2)
void gemm_mma(const __nv_bfloat16* __restrict__ Aact,
              const __nv_bfloat16* __restrict__ Bw,
              const float* __restrict__ bias, const float* __restrict__ res,
              float* __restrict__ outf, __nv_bfloat16* __restrict__ outb,
              int K, int Nout) {
    extern __shared__ __align__(16) char smem[];
    int tid = threadIdx.x;
    int wid = tid >> 5, lid = tid & 31;
    int wm = wid & 3, wn = wid >> 2;
    int mBase = blockIdx.y * BM;
    int nBase = blockIdx.x * BN;
    uint32_t sb = smem_u32(smem);

    float acc[2][4][4];
#pragma unroll
    for (int a = 0; a < 2; a++)
#pragma unroll
        for (int b = 0; b < 4; b++)
#pragma unroll
            for (int c = 0; c < 4; c++) acc[a][b][c] = 0.0f;

    int nch = K / BK;

    auto issue = [&](int c) {
        uint32_t sbase = sb + (c % NSTAGE) * STAGE_BYTES;
        int k0 = c * BK;
#pragma unroll
        for (int u = 0; u < 3; u++) {
            int ch = tid + u * 256;
            if (ch < 512) {
                int r = ch >> 2, cc = ch & 3;
                cp16(sbase + OFF_A + r * RPB + cc * 16,
                     Aact + (size_t)(mBase + r) * K + k0 + cc * 8);
            } else {
                int q = ch - 512, r = q >> 2, cc = q & 3;
                cp16(sbase + OFF_B + r * RPB + cc * 16,
                     Bw + (size_t)(nBase + r) * K + k0 + cc * 8);
            }
        }
        cp_commit();
    };

    int aRow = wm * 32 + (lid & 7) + ((lid >> 3) & 1) * 8;
    int aKof = (lid >> 4) * 16;
    int bRow = wn * 32 + (lid & 7) + ((lid >> 4) & 1) * 8;
    int bKof = ((lid >> 3) & 1) * 16;

    issue(0);
    if (nch > 1) issue(1);
    if (nch > 2) issue(2);
    for (int c = 0; c < nch; c++) {
        int rem = nch - 1 - c;
        if (c + 3 < nch) issue(c + 3);
        if (rem >= 3)      cp_wait<3>();
        else if (rem == 2) cp_wait<2>();
        else if (rem == 1) cp_wait<1>();
        else               cp_wait<0>();
        __syncthreads();

        uint32_t buf = sb + (c % NSTAGE) * STAGE_BYTES;
#pragma unroll
        for (int kb = 0; kb < 64; kb += 32) {
            uint32_t ahf[2][4], bhf[2][4];
#pragma unroll
            for (int mt = 0; mt < 2; mt++)
                ldsm_x4(ahf[mt], buf + OFF_A + (aRow + mt * 16) * RPB + kb + aKof);
#pragma unroll
            for (int half = 0; half < 2; half++)
                ldsm_x4(bhf[half], buf + OFF_B + (bRow + half * 16) * RPB + kb + bKof);
#pragma unroll
            for (int mt = 0; mt < 2; mt++)
#pragma unroll
                for (int nt = 0; nt < 4; nt++)
                    mma16816(acc[mt][nt], ahf[mt], bhf[nt >> 1] + (nt & 1) * 2);
        }
        __syncthreads();
    }

    int g = lid >> 2, tq = lid & 3;
#pragma unroll
    for (int mt = 0; mt < 2; mt++) {
#pragma unroll
        for (int half = 0; half < 2; half++) {
            int row = mBase + wm * 32 + mt * 16 + g + half * 8;
            int dst = (EPI == EPI_SCATTER) ? scatter_dst(row) : row;
#pragma unroll
            for (int nt = 0; nt < 4; nt++) {
                int col = nBase + wn * 32 + nt * 8 + tq * 2;
                float v0 = acc[mt][nt][half * 2 + 0] + bias[col];
                float v1 = acc[mt][nt][half * 2 + 1] + bias[col + 1];
                if (EPI == EPI_GELU) {
                    v0 = gelu_exact(v0); v1 = gelu_exact(v1);
                }
                if (EPI == EPI_GELU || EPI == EPI_BF16) {
                    __nv_bfloat162 hp;
                    hp.x = __float2bfloat16(v0); hp.y = __float2bfloat16(v1);
                    *(__nv_bfloat162*)(outb + (size_t)row * Nout + col) = hp;
                } else {
                    size_t o = (size_t)dst * Nout + col;
                    float2 rv = *(const float2*)(res + o);
                    float2 w; w.x = v0 + rv.x; w.y = v1 + rv.y;
                    *(float2*)(outf + o) = w;
                }
            }
        }
    }
}

// ---------------- GEMM-192: CTA 64x192, full-N tile ----------------
template <int EPI>
__global__ __launch_bounds__(256, 2)
void gemm_mma_n192(const __nv_bfloat16* __restrict__ Aact,
                   const __nv_bfloat16* __restrict__ Bw,
                   const float* __restrict__ bias, const float* __restrict__ res,
                   float* __restrict__ outf, int K) {
    extern __shared__ __align__(16) char smem[];
    const int Nout = 192;
    int tid = threadIdx.x;
    int wid = tid >> 5, lid = tid & 31;
    int wm = wid & 1, wn = wid >> 1;
    int mBase = blockIdx.y * BM2;
    uint32_t sb = smem_u32(smem);

    float acc[2][6][4];
#pragma unroll
    for (int a = 0; a < 2; a++)
#pragma unroll
        for (int b = 0; b < 6; b++)
#pragma unroll
            for (int c = 0; c < 4; c++) acc[a][b][c] = 0.0f;

    int nch = K / BK;

    auto issue = [&](int c) {
        uint32_t sbase = sb + (c % NSTAGE) * STAGE2;
        int k0 = c * BK;
#pragma unroll
        for (int u = 0; u < 4; u++) {
            int ch = tid + u * 256;
            if (ch < 256) {
                int r = ch >> 2, cc = ch & 3;
                cp16(sbase + r * RPB + cc * 16,
                     Aact + (size_t)(mBase + r) * K + k0 + cc * 8);
            } else {
                int q = ch - 256, r = q >> 2, cc = q & 3;
                cp16(sbase + OFF_B2 + r * RPB + cc * 16,
                     Bw + (size_t)r * K + k0 + cc * 8);
            }
        }
        cp_commit();
    };

    int aRow = wm * 32 + (lid & 7) + ((lid >> 3) & 1) * 8;
    int aKof = (lid >> 4) * 16;
    int bRow = wn * 48 + (lid & 7) + ((lid >> 4) & 1) * 8;
    int bKof = ((lid >> 3) & 1) * 16;

    issue(0);
    if (nch > 1) issue(1);
    if (nch > 2) issue(2);
    for (int c = 0; c < nch; c++) {
        int rem = nch - 1 - c;
        if (c + 3 < nch) issue(c + 3);
        if (rem >= 3)      cp_wait<3>();
        else if (rem == 2) cp_wait<2>();
        else if (rem == 1) cp_wait<1>();
        else               cp_wait<0>();
        __syncthreads();

        uint32_t buf = sb + (c % NSTAGE) * STAGE2;
#pragma unroll
        for (int kb = 0; kb < 64; kb += 32) {
            uint32_t ahf[2][4], bhf[3][4];
#pragma unroll
            for (int mt = 0; mt < 2; mt++)
                ldsm_x4(ahf[mt], buf + (aRow + mt * 16) * RPB + kb + aKof);
#pragma unroll
            for (int nb = 0; nb < 3; nb++)
                ldsm_x4(bhf[nb], buf + OFF_B2 + (bRow + nb * 16) * RPB + kb + bKof);
#pragma unroll
            for (int mt = 0; mt < 2; mt++)
#pragma unroll
                for (int nt = 0; nt < 6; nt++)
                    mma16816(acc[mt][nt], ahf[mt], bhf[nt >> 1] + (nt & 1) * 2);
        }
        __syncthreads();
    }

    int g = lid >> 2, tq = lid & 3;
#pragma unroll
    for (int mt = 0; mt < 2; mt++) {
#pragma unroll
        for (int half = 0; half < 2; half++) {
            int row = mBase + wm * 32 + mt * 16 + g + half * 8;
            int dst = (EPI == EPI_SCATTER) ? scatter_dst(row) : row;
#pragma unroll
            for (int nt = 0; nt < 6; nt++) {
                int col = wn * 48 + nt * 8 + tq * 2;
                float v0 = acc[mt][nt][half * 2 + 0] + bias[col];
                float v1 = acc[mt][nt][half * 2 + 1] + bias[col + 1];
                size_t o = (size_t)dst * Nout + col;
                float2 rv = *(const float2*)(res + o);
                float2 w; w.x = v0 + rv.x; w.y = v1 + rv.y;
                *(float2*)(outf + o) = w;
            }
        }
    }
}

// ---------------- Windowed attention: register-blocked, LUT bias/mask ----------------
__global__ void attn_kernel(const __nv_bfloat16* __restrict__ qkv,
                            const float* __restrict__ rpb,
                            __nv_bfloat16* __restrict__ oh) {
    int blk = blockIdx.x;
    int w = blk / NHEADS;
    int h = blk - w * NHEADS;

    __shared__ float sq[49][34], sk[49][34], sv[49][34];
    __shared__ float sa[49][49];
    __shared__ int   Ls[49];      // 13*(n/7)+(n%7)
    __shared__ int   Rs[49];      // shift-mask region id

    int tid = threadIdx.x;
    const float scale = 0.17677669529663687f;

    int r = w & 255;
    int wi = r >> 4, wj = r & 15;

    if (tid < 49) {
        int i = tid / 7, j = tid % 7;
        Ls[tid] = 13 * i + j;
        int hp = wi * 7 + i, wp = wj * 7 + j;
        Rs[tid] = (hp < 105 ? 0 : (hp < 109 ? 1 : 2)) * 3 + (wp < 105 ? 0 : (wp < 109 ? 1 : 2));
    }
    for (int idx = tid; idx < 49 * 32; idx += 256) {
        int n = idx >> 5, d = idx & 31;
        size_t base = ((size_t)(w * 49 + n)) * (3 * C_DIM) + h * HDIM + d;
        sq[n][d] = __bfloat162float(qkv[base]) * scale;
        sk[n][d] = __bfloat162float(qkv[base + C_DIM]);
        sv[n][d] = __bfloat162float(qkv[base + 2 * C_DIM]);
    }
    __syncthreads();

    // ---- S = qk^T + bias + mask : thread owns 2 rows (q in registers), strides m ----
    if (tid < 250) {
        int p = tid / 10, s = tid % 10;
        int n0 = 2 * p, n1 = 2 * p + 1;
        bool has1 = (n1 < 49);
        ull q0[16], q1[16];
        const ull* q0p = (const ull*)sq[n0];
#pragma unroll
        for (int d = 0; d < 16; d++) q0[d] = q0p[d];
        if (has1) {
            const ull* q1p = (const ull*)sq[n1];
#pragma unroll
            for (int d = 0; d < 16; d++) q1[d] = q1p[d];
        }
        int L0 = Ls[n0] + 84, R0 = Rs[n0];
        int L1 = has1 ? (Ls[n1] + 84) : 0, R1 = has1 ? Rs[n1] : 0;

        for (int m = s; m < 49; m += 10) {
            const ull* k2 = (const ull*)sk[m];
            ull a0 = pack2(0.f, 0.f), a1 = pack2(0.f, 0.f);
#pragma unroll
            for (int d = 0; d < 16; d++) {
                ull kv = k2[d];
                fma2(a0, q0[d], kv);
                fma2(a1, q1[d], kv);
            }
            int Lm = Ls[m], Rm = Rs[m];
            float x0, y0;
            unpack2(a0, x0, y0);
            sa[n0][m] = x0 + y0 + rpb[(L0 - Lm) * NHEADS + h] + (R0 == Rm ? 0.0f : -100.0f);
            if (has1) {
                float x1, y1;
                unpack2(a1, x1, y1);
                sa[n1][m] = x1 + y1 + rpb[(L1 - Lm) * NHEADS + h] + (R1 == Rm ? 0.0f : -100.0f);
            }
        }
    }
    __syncthreads();

    // ---- softmax rows ----
    int wid = tid >> 5, lid = tid & 31;
    for (int n = wid; n < 49; n += 8) {
        float v1 = sa[n][lid];
        float v2 = (lid < 17) ? sa[n][lid + 32] : -1e30f;
        float mx = warp_max(fmaxf(v1, v2));
        float e1 = __expf(v1 - mx);
        float e2 = (lid < 17) ? __expf(v2 - mx) : 0.0f;
        float s = warp_sum(e1 + e2);
        float inv = 1.0f / s;
        sa[n][lid] = e1 * inv;
        if (lid < 17) sa[n][lid + 32] = e2 * inv;
    }
    __syncthreads();

    // ---- O = P @ V : thread owns (n, quarter of d), 4 ull accumulators ----
    if (tid < 196) {
        int n = tid >> 2, dq = tid & 3;
        ull acc0 = pack2(0.f, 0.f), acc1 = acc0, acc2 = acc0, acc3 = acc0;
        const float* sar = sa[n];
#pragma unroll 7
        for (int m = 0; m < 49; m++) {
            float a = sar[m];
            ull aa = pack2(a, a);
            const ull* v2 = (const ull*)sv[m] + dq * 4;
            fma2(acc0, aa, v2[0]);
            fma2(acc1, aa, v2[1]);
            fma2(acc2, aa, v2[2]);
            fma2(acc3, aa, v2[3]);
        }
        float f[8];
        unpack2(acc0, f[0], f[1]);
        unpack2(acc1, f[2], f[3]);
        unpack2(acc2, f[4], f[5]);
        unpack2(acc3, f[6], f[7]);
        uint4 outv;
        __nv_bfloat162* op = reinterpret_cast<__nv_bfloat162*>(&outv);
#pragma unroll
        for (int u = 0; u < 4; u++) {
            __nv_bfloat162 hp;
            hp.x = __float2bfloat16(f[2 * u]);
            hp.y = __float2bfloat16(f[2 * u + 1]);
            op[u] = hp;
        }
        size_t oidx = ((size_t)(w * 49 + n)) * C_DIM + h * HDIM + dq * 8;
        *(uint4*)(oh + oidx) = outv;
    }
}

// ---------------- launch ----------------
extern "C" void kernel_launch(void* const* d_in, const int* in_sizes, int n_in,
                              void* d_out, int out_size) {
    const float* query   = (const float*)d_in[0];
    const float* norm1_g = (const float*)d_in[1];
    const float* norm1_b = (const float*)d_in[2];
    const float* qkv_w   = (const float*)d_in[3];
    const float* qkv_b   = (const float*)d_in[4];
    const float* rpb     = (const float*)d_in[5];
    const float* proj_w  = (const float*)d_in[6];
    const float* proj_b  = (const float*)d_in[7];
    const float* norm2_g = (const float*)d_in[8];
    const float* norm2_b = (const float*)d_in[9];
    const float* fc1_w   = (const float*)d_in[10];
    const float* fc1_b   = (const float*)d_in[11];
    const float* fc2_w   = (const float*)d_in[12];
    const float* fc2_b   = (const float*)d_in[13];
    float* out = (float*)d_out;

    __nv_bfloat16 *xw, *qkvp, *att, *ln2, *hbuf;
    __nv_bfloat16 *wq, *wp, *w1, *w2;
    float *x;
    cudaGetSymbolAddress((void**)&xw, g_xw);
    cudaGetSymbolAddress((void**)&qkvp, g_qkv);
    cudaGetSymbolAddress((void**)&att, g_att);
    cudaGetSymbolAddress((void**)&x, g_x);
    cudaGetSymbolAddress((void**)&ln2, g_ln2);
    cudaGetSymbolAddress((void**)&hbuf, g_h);
    cudaGetSymbolAddress((void**)&wq, g_wqkv);
    cudaGetSymbolAddress((void**)&wp, g_wprj);
    cudaGetSymbolAddress((void**)&w1, g_wfc1);
    cudaGetSymbolAddress((void**)&w2, g_wfc2);

    const int SMEM  = NSTAGE * STAGE_BYTES;  // 61440
    const int SMEM2 = NSTAGE * STAGE2;       // 81920
    cudaFuncSetAttribute(gemm_mma<EPI_BF16>, cudaFuncAttributeMaxDynamicSharedMemorySize, SMEM);
    cudaFuncSetAttribute(gemm_mma<EPI_GELU>, cudaFuncAttributeMaxDynamicSharedMemorySize, SMEM);
    cudaFuncSetAttribute(gemm_mma_n192<EPI_SCATTER>, cudaFuncAttributeMaxDynamicSharedMemorySize, SMEM2);
    cudaFuncSetAttribute(gemm_mma_n192<EPI_RES>,     cudaFuncAttributeMaxDynamicSharedMemorySize, SMEM2);

    wprep_all<<<(442368 + 255) / 256, 256>>>(qkv_w, proj_w, fc1_w, fc2_w, wq, wp, w1, w2);

    // 1) LN1 + shift + window partition
    ln_kernel<true><<<M_TOK, 192>>>(query, norm1_g, norm1_b, xw);

    // 2) qkv  [100352,192] x [192,576] -> bf16
    gemm_mma<EPI_BF16><<<dim3(576 / BN, M_TOK / BM), 256, SMEM>>>(
        xw, wq, qkv_b, nullptr, nullptr, qkvp, 192, 576);

    // 3) windowed attention
    attn_kernel<<<2048 * NHEADS, 256>>>(qkvp, rpb, att);

    // 4) proj + window reverse + unshift + residual(query)
    gemm_mma_n192<EPI_SCATTER><<<dim3(1, M_TOK / BM2), 256, SMEM2>>>(
        att, wp, proj_b, query, x, 192);

    // 5) LN2
    ln_kernel<false><<<M_TOK, 192>>>(x, norm2_g, norm2_b, ln2);

    // 6) fc1 + GELU
    gemm_mma<EPI_GELU><<<dim3(768 / BN, M_TOK / BM), 256, SMEM>>>(
        ln2, w1, fc1_b, nullptr, nullptr, hbuf, 192, 768);

    // 7) fc2 + residual(x) -> out
    gemm_mma_n192<EPI_RES><<<dim3(1, M_TOK / BM2), 256, SMEM2>>>(
        hbuf, w2, fc2_b, x, out, 768);
}

// round 11
// speedup vs baseline: 1.9471x; 1.1573x over previous
#include <cuda_runtime.h>
#include <cuda_bf16.h>
#include <math.h>
#include <stdint.h>

#define M_TOK   100352
#define C_DIM   192
#define NHEADS  6
#define HDIM    32
#define HIDDEN  768

// GEMM-64 tiling
#define BM 128
#define BN 64
#define BK 32
#define RPB 80
#define OFF_A  0
#define OFF_B  (BM*RPB)
#define STAGE_BYTES (BM*RPB + BN*RPB)
#define NSTAGE 4
// GEMM-192 tiling
#define BM2 64
#define BN2 192
#define OFF_B2 (BM2*RPB)
#define STAGE2 (BM2*RPB + BN2*RPB)

// attention smem layout (per pair)
#define AQ   0
#define AK   5120
#define AV   10240          // V^T [32][64] pitch 144
#define ASA  14848          // fp32 S [64][64]
#define APB  0              // P bf16 [64][64] pitch 144, overlays AQ/AK
#define PAIR_STRIDE 31232
#define ATTN_SMEM (2*PAIR_STRIDE)   // 62464

typedef unsigned long long ull;

// ---------------- scratch ----------------
__device__ __nv_bfloat16 g_xw  [(size_t)M_TOK * C_DIM];
__device__ __nv_bfloat16 g_qkv [(size_t)M_TOK * 3 * C_DIM];
__device__ __nv_bfloat16 g_att [(size_t)M_TOK * C_DIM];
__device__ float         g_x   [(size_t)M_TOK * C_DIM];
__device__ __nv_bfloat16 g_ln2 [(size_t)M_TOK * C_DIM];
__device__ __nv_bfloat16 g_h   [(size_t)M_TOK * HIDDEN];
__device__ __nv_bfloat16 g_wqkv[576 * 192];
__device__ __nv_bfloat16 g_wprj[192 * 192];
__device__ __nv_bfloat16 g_wfc1[768 * 192];
__device__ __nv_bfloat16 g_wfc2[192 * 768];

// ---------------- helpers ----------------
__device__ __forceinline__ uint32_t smem_u32(const void* p) {
    uint32_t a;
    asm("{ .reg .u64 t; cvta.to.shared.u64 t, %1; cvt.u32.u64 %0, t; }" : "=r"(a) : "l"(p));
    return a;
}
__device__ __forceinline__ void cp16(uint32_t sa, const void* g) {
    asm volatile("cp.async.cg.shared.global [%0], [%1], 16;" :: "r"(sa), "l"(g));
}
__device__ __forceinline__ void cp_commit() { asm volatile("cp.async.commit_group;"); }
template <int N>
__device__ __forceinline__ void cp_wait() { asm volatile("cp.async.wait_group %0;" :: "n"(N)); }

__device__ __forceinline__ void ldsm_x4(uint32_t* r, uint32_t addr) {
    asm volatile("ldmatrix.sync.aligned.m8n8.x4.shared.b16 {%0,%1,%2,%3}, [%4];"
        : "=r"(r[0]), "=r"(r[1]), "=r"(r[2]), "=r"(r[3]) : "r"(addr));
}
__device__ __forceinline__ void mma16816(float* c, const uint32_t* a, const uint32_t* b) {
    asm volatile("mma.sync.aligned.m16n8k16.row.col.f32.bf16.bf16.f32 "
        "{%0,%1,%2,%3}, {%4,%5,%6,%7}, {%8,%9}, {%0,%1,%2,%3};"
        : "+f"(c[0]), "+f"(c[1]), "+f"(c[2]), "+f"(c[3])
        : "r"(a[0]), "r"(a[1]), "r"(a[2]), "r"(a[3]), "r"(b[0]), "r"(b[1]));
}
__device__ __forceinline__ float gelu_exact(float v) {
    return 0.5f * v * (1.0f + erff(v * 0.70710678118654752f));
}
__device__ __forceinline__ float warp_sum(float v) {
#pragma unroll
    for (int o = 16; o > 0; o >>= 1) v += __shfl_xor_sync(0xffffffffu, v, o);
    return v;
}
__device__ __forceinline__ float warp_max(float v) {
#pragma unroll
    for (int o = 16; o > 0; o >>= 1) v = fmaxf(v, __shfl_xor_sync(0xffffffffu, v, o));
    return v;
}
__device__ __forceinline__ int scatter_dst(int row) {
    int w = row / 49, n = row % 49;
    int bb = w >> 8, rr = w & 255;
    int wi = rr >> 4, wj = rr & 15;
    int i = n / 7, j = n % 7;
    int hh = wi * 7 + i + 3; if (hh >= 112) hh -= 112;
    int ww = wj * 7 + j + 3; if (ww >= 112) ww -= 112;
    return bb * 12544 + hh * 112 + ww;
}

// ---------------- combined weight transpose ----------------
__global__ void wprep_all(const float* __restrict__ Wq, const float* __restrict__ Wp,
                          const float* __restrict__ W1, const float* __restrict__ W2,
                          __nv_bfloat16* __restrict__ Tq, __nv_bfloat16* __restrict__ Tp,
                          __nv_bfloat16* __restrict__ T1, __nv_bfloat16* __restrict__ T2) {
    int i = blockIdx.x * 256 + threadIdx.x;
    if (i < 110592) {
        int k = i / 576, n = i % 576;
        Tq[(size_t)n * 192 + k] = __float2bfloat16(Wq[i]);
    } else if (i < 147456) {
        int j = i - 110592;
        int k = j / 192, n = j % 192;
        Tp[(size_t)n * 192 + k] = __float2bfloat16(Wp[j]);
    } else if (i < 294912) {
        int j = i - 147456;
        int k = j / 768, n = j % 768;
        T1[(size_t)n * 192 + k] = __float2bfloat16(W1[j]);
    } else if (i < 442368) {
        int j = i - 294912;
        int k = j / 192, n = j % 192;
        T2[(size_t)n * 768 + k] = __float2bfloat16(W2[j]);
    }
}

// ---------------- LayerNorm (+ optional shift/window gather) ----------------
template <bool GATHER>
__global__ void ln_kernel(const float* __restrict__ in,
                          const float* __restrict__ gamma, const float* __restrict__ beta,
                          __nv_bfloat16* __restrict__ oh) {
    int t = blockIdx.x, c = threadIdx.x;
    int src = GATHER ? scatter_dst(t) : t;
    float v = in[(size_t)src * C_DIM + c];
    __shared__ float s1[6], s2[6];
    int wid = c >> 5, lid = c & 31;
    float s = warp_sum(v);
    if (lid == 0) s1[wid] = s;
    __syncthreads();
    float mean = (s1[0] + s1[1] + s1[2] + s1[3] + s1[4] + s1[5]) * (1.0f / 192.0f);
    float d = v - mean;
    float sq = warp_sum(d * d);
    if (lid == 0) s2[wid] = sq;
    __syncthreads();
    float var = (s2[0] + s2[1] + s2[2] + s2[3] + s2[4] + s2[5]) * (1.0f / 192.0f);
    float o = d * rsqrtf(var + 1e-5f) * gamma[c] + beta[c];
    oh[(size_t)t * C_DIM + c] = __float2bfloat16(o);
}

enum { EPI_BF16 = 0, EPI_GELU = 1, EPI_SCATTER = 2, EPI_RES = 3 };

// ---------------- GEMM-64: CTA 128x64 ----------------
template <int EPI>
__global__ __launch_bounds__(256, 2)
void gemm_mma(const __nv_bfloat16* __restrict__ Aact,
              const __nv_bfloat16* __restrict__ Bw,
              const float* __restrict__ bias, const float* __restrict__ res,
              float* __restrict__ outf, __nv_bfloat16* __restrict__ outb,
              int K, int Nout) {
    extern __shared__ __align__(16) char smem[];
    int tid = threadIdx.x;
    int wid = tid >> 5, lid = tid & 31;
    int wm = wid & 3, wn = wid >> 2;
    int mBase = blockIdx.y * BM;
    int nBase = blockIdx.x * BN;
    uint32_t sb = smem_u32(smem);

    float acc[2][4][4];
#pragma unroll
    for (int a = 0; a < 2; a++)
#pragma unroll
        for (int b = 0; b < 4; b++)
#pragma unroll
            for (int c = 0; c < 4; c++) acc[a][b][c] = 0.0f;

    int nch = K / BK;

    auto issue = [&](int c) {
        uint32_t sbase = sb + (c % NSTAGE) * STAGE_BYTES;
        int k0 = c * BK;
#pragma unroll
        for (int u = 0; u < 3; u++) {
            int ch = tid + u * 256;
            if (ch < 512) {
                int r = ch >> 2, cc = ch & 3;
                cp16(sbase + OFF_A + r * RPB + cc * 16,
                     Aact + (size_t)(mBase + r) * K + k0 + cc * 8);
            } else {
                int q = ch - 512, r = q >> 2, cc = q & 3;
                cp16(sbase + OFF_B + r * RPB + cc * 16,
                     Bw + (size_t)(nBase + r) * K + k0 + cc * 8);
            }
        }
        cp_commit();
    };

    int aRow = wm * 32 + (lid & 7) + ((lid >> 3) & 1) * 8;
    int aKof = (lid >> 4) * 16;
    int bRow = wn * 32 + (lid & 7) + ((lid >> 4) & 1) * 8;
    int bKof = ((lid >> 3) & 1) * 16;

    issue(0);
    if (nch > 1) issue(1);
    if (nch > 2) issue(2);
    for (int c = 0; c < nch; c++) {
        int rem = nch - 1 - c;
        if (c + 3 < nch) issue(c + 3);
        if (rem >= 3)      cp_wait<3>();
        else if (rem == 2) cp_wait<2>();
        else if (rem == 1) cp_wait<1>();
        else               cp_wait<0>();
        __syncthreads();

        uint32_t buf = sb + (c % NSTAGE) * STAGE_BYTES;
#pragma unroll
        for (int kb = 0; kb < 64; kb += 32) {
            uint32_t ahf[2][4], bhf[2][4];
#pragma unroll
            for (int mt = 0; mt < 2; mt++)
                ldsm_x4(ahf[mt], buf + OFF_A + (aRow + mt * 16) * RPB + kb + aKof);
#pragma unroll
            for (int half = 0; half < 2; half++)
                ldsm_x4(bhf[half], buf + OFF_B + (bRow + half * 16) * RPB + kb + bKof);
#pragma unroll
            for (int mt = 0; mt < 2; mt++)
#pragma unroll
                for (int nt = 0; nt < 4; nt++)
                    mma16816(acc[mt][nt], ahf[mt], bhf[nt >> 1] + (nt & 1) * 2);
        }
        __syncthreads();
    }

    int g = lid >> 2, tq = lid & 3;
#pragma unroll
    for (int mt = 0; mt < 2; mt++) {
#pragma unroll
        for (int half = 0; half < 2; half++) {
            int row = mBase + wm * 32 + mt * 16 + g + half * 8;
            int dst = (EPI == EPI_SCATTER) ? scatter_dst(row) : row;
#pragma unroll
            for (int nt = 0; nt < 4; nt++) {
                int col = nBase + wn * 32 + nt * 8 + tq * 2;
                float v0 = acc[mt][nt][half * 2 + 0] + bias[col];
                float v1 = acc[mt][nt][half * 2 + 1] + bias[col + 1];
                if (EPI == EPI_GELU) {
                    v0 = gelu_exact(v0); v1 = gelu_exact(v1);
                }
                if (EPI == EPI_GELU || EPI == EPI_BF16) {
                    __nv_bfloat162 hp;
                    hp.x = __float2bfloat16(v0); hp.y = __float2bfloat16(v1);
                    *(__nv_bfloat162*)(outb + (size_t)row * Nout + col) = hp;
                } else {
                    size_t o = (size_t)dst * Nout + col;
                    float2 rv = *(const float2*)(res + o);
                    float2 w; w.x = v0 + rv.x; w.y = v1 + rv.y;
                    *(float2*)(outf + o) = w;
                }
            }
        }
    }
}

// ---------------- GEMM-192: CTA 64x192, full-N tile ----------------
template <int EPI>
__global__ __launch_bounds__(256, 2)
void gemm_mma_n192(const __nv_bfloat16* __restrict__ Aact,
                   const __nv_bfloat16* __restrict__ Bw,
                   const float* __restrict__ bias, const float* __restrict__ res,
                   float* __restrict__ outf, int K) {
    extern __shared__ __align__(16) char smem[];
    const int Nout = 192;
    int tid = threadIdx.x;
    int wid = tid >> 5, lid = tid & 31;
    int wm = wid & 1, wn = wid >> 1;
    int mBase = blockIdx.y * BM2;
    uint32_t sb = smem_u32(smem);

    float acc[2][6][4];
#pragma unroll
    for (int a = 0; a < 2; a++)
#pragma unroll
        for (int b = 0; b < 6; b++)
#pragma unroll
            for (int c = 0; c < 4; c++) acc[a][b][c] = 0.0f;

    int nch = K / BK;

    auto issue = [&](int c) {
        uint32_t sbase = sb + (c % NSTAGE) * STAGE2;
        int k0 = c * BK;
#pragma unroll
        for (int u = 0; u < 4; u++) {
            int ch = tid + u * 256;
            if (ch < 256) {
                int r = ch >> 2, cc = ch & 3;
                cp16(sbase + r * RPB + cc * 16,
                     Aact + (size_t)(mBase + r) * K + k0 + cc * 8);
            } else {
                int q = ch - 256, r = q >> 2, cc = q & 3;
                cp16(sbase + OFF_B2 + r * RPB + cc * 16,
                     Bw + (size_t)r * K + k0 + cc * 8);
            }
        }
        cp_commit();
    };

    int aRow = wm * 32 + (lid & 7) + ((lid >> 3) & 1) * 8;
    int aKof = (lid >> 4) * 16;
    int bRow = wn * 48 + (lid & 7) + ((lid >> 4) & 1) * 8;
    int bKof = ((lid >> 3) & 1) * 16;

    issue(0);
    if (nch > 1) issue(1);
    if (nch > 2) issue(2);
    for (int c = 0; c < nch; c++) {
        int rem = nch - 1 - c;
        if (c + 3 < nch) issue(c + 3);
        if (rem >= 3)      cp_wait<3>();
        else if (rem == 2) cp_wait<2>();
        else if (rem == 1) cp_wait<1>();
        else               cp_wait<0>();
        __syncthreads();

        uint32_t buf = sb + (c % NSTAGE) * STAGE2;
#pragma unroll
        for (int kb = 0; kb < 64; kb += 32) {
            uint32_t ahf[2][4], bhf[3][4];
#pragma unroll
            for (int mt = 0; mt < 2; mt++)
                ldsm_x4(ahf[mt], buf + (aRow + mt * 16) * RPB + kb + aKof);
#pragma unroll
            for (int nb = 0; nb < 3; nb++)
                ldsm_x4(bhf[nb], buf + OFF_B2 + (bRow + nb * 16) * RPB + kb + bKof);
#pragma unroll
            for (int mt = 0; mt < 2; mt++)
#pragma unroll
                for (int nt = 0; nt < 6; nt++)
                    mma16816(acc[mt][nt], ahf[mt], bhf[nt >> 1] + (nt & 1) * 2);
        }
        __syncthreads();
    }

    int g = lid >> 2, tq = lid & 3;
#pragma unroll
    for (int mt = 0; mt < 2; mt++) {
#pragma unroll
        for (int half = 0; half < 2; half++) {
            int row = mBase + wm * 32 + mt * 16 + g + half * 8;
            int dst = (EPI == EPI_SCATTER) ? scatter_dst(row) : row;
#pragma unroll
            for (int nt = 0; nt < 6; nt++) {
                int col = wn * 48 + nt * 8 + tq * 2;
                float v0 = acc[mt][nt][half * 2 + 0] + bias[col];
                float v1 = acc[mt][nt][half * 2 + 1] + bias[col + 1];
                size_t o = (size_t)dst * Nout + col;
                float2 rv = *(const float2*)(res + o);
                float2 w; w.x = v0 + rv.x; w.y = v1 + rv.y;
                *(float2*)(outf + o) = w;
            }
        }
    }
}

// ---------------- Windowed attention via mma.sync ----------------
// block = 256 thr = 2 (window,head) pairs x 4 warps; padded 64x64x32 / 64x32x64 mma
__global__ __launch_bounds__(256)
void attn_kernel(const __nv_bfloat16* __restrict__ qkv,
                 const float* __restrict__ rpb,
                 __nv_bfloat16* __restrict__ oh) {
    extern __shared__ __align__(16) char smem[];
    __shared__ int Ls[49];
    __shared__ int Rs[2][49];

    int tid = threadIdx.x;
    int wid = tid >> 5, lid = tid & 31;
    int ph = wid >> 2;            // pair in block (0/1)
    int t  = wid & 3;             // warp in pair
    int wtid = tid & 127;
    int pair = blockIdx.x * 2 + ph;
    int w = pair / NHEADS;
    int h = pair - w * NHEADS;

    char* sm = smem + ph * PAIR_STRIDE;
    uint32_t sb = smem_u32(smem) + ph * PAIR_STRIDE;
    const float scale = 0.17677669529663687f;

    int r = w & 255;
    int wi = r >> 4, wj = r & 15;

    if (tid < 49) Ls[tid] = 13 * (tid / 7) + tid % 7;
    if (wtid < 49) {
        int i = wtid / 7, j = wtid % 7;
        int hp = wi * 7 + i, wp = wj * 7 + j;
        Rs[ph][wtid] = (hp < 105 ? 0 : (hp < 109 ? 1 : 2)) * 3 + (wp < 105 ? 0 : (wp < 109 ? 1 : 2));
    }

    // load Q,K (row-major [n][d], pitch 80B) and V^T ([d][m], pitch 144B) — raw bf16 copies
    for (int idx = wtid; idx < 49 * 32; idx += 128) {
        int n = idx >> 5, d = idx & 31;
        size_t base = ((size_t)(w * 49 + n)) * (3 * C_DIM) + h * HDIM + d;
        *(__nv_bfloat16*)(sm + AQ + n * 80 + d * 2) = qkv[base];
        *(__nv_bfloat16*)(sm + AK + n * 80 + d * 2) = qkv[base + C_DIM];
        *(__nv_bfloat16*)(sm + AV + d * 144 + n * 2) = qkv[base + 2 * C_DIM];
    }
    // zero V^T padding columns m=49..63 (P pad cols are zero, but 0*garbage could be NaN)
    for (int idx = wtid; idx < 32 * 15; idx += 128) {
        int d = idx / 15, m = 49 + idx % 15;
        *(__nv_bfloat16*)(sm + AV + d * 144 + m * 2) = __float2bfloat16(0.0f);
    }
    __syncthreads();

    int aRow = t * 16 + (lid & 7) + ((lid >> 3) & 1) * 8;
    int aKof = (lid >> 4) * 16;
    int bRowB = (lid & 7) + ((lid >> 4) & 1) * 8;
    int bKof = ((lid >> 3) & 1) * 16;
    int g = lid >> 2, tq = lid & 3;

    // ---- S = Q K^T (64x64x32) ----
    {
        float acc[8][4];
#pragma unroll
        for (int a = 0; a < 8; a++)
#pragma unroll
            for (int c = 0; c < 4; c++) acc[a][c] = 0.0f;
#pragma unroll
        for (int kb = 0; kb < 64; kb += 32) {
            uint32_t af[4];
            ldsm_x4(af, sb + AQ + aRow * 80 + kb + aKof);
#pragma unroll
            for (int nb = 0; nb < 4; nb++) {
                uint32_t bf[4];
                ldsm_x4(bf, sb + AK + (bRowB + nb * 16) * 80 + kb + bKof);
                mma16816(acc[2 * nb],     af, bf);
                mma16816(acc[2 * nb + 1], af, bf + 2);
            }
        }
        // store with scale + bias + mask
        float* sa = (float*)(sm + ASA);
#pragma unroll
        for (int half = 0; half < 2; half++) {
            int row = t * 16 + g + half * 8;
            int n49 = row < 49 ? row : 48;
            int L0 = Ls[n49] + 84, R0 = Rs[ph][n49];
#pragma unroll
            for (int nt = 0; nt < 8; nt++) {
                int col = nt * 8 + tq * 2;
#pragma unroll
                for (int e = 0; e < 2; e++) {
                    int cc = col + e;
                    int m49 = cc < 49 ? cc : 48;
                    float vs = acc[nt][half * 2 + e] * scale
                             + rpb[(L0 - Ls[m49]) * NHEADS + h]
                             + (R0 == Rs[ph][m49] ? 0.0f : -100.0f);
                    sa[row * 64 + cc] = vs;
                }
            }
        }
    }
    __syncthreads();

    // ---- softmax (rows t, t+4, ... of this pair) ----
    {
        float* sa = (float*)(sm + ASA);
        for (int n = t; n < 49; n += 4) {
            float v1 = sa[n * 64 + lid];
            float v2 = (lid < 17) ? sa[n * 64 + 32 + lid] : -1e30f;
            float mx = warp_max(fmaxf(v1, v2));
            float e1 = __expf(v1 - mx);
            float e2 = (lid < 17) ? __expf(v2 - mx) : 0.0f;
            float s = warp_sum(e1 + e2);
            float inv = 1.0f / s;
            sa[n * 64 + lid] = e1 * inv;
            if (lid < 17) sa[n * 64 + 32 + lid] = e2 * inv;
        }
    }
    __syncthreads();

    // ---- P -> bf16 padded [64][64] pitch 144 (overlays Q/K) ----
    {
        const float* sa = (const float*)(sm + ASA);
        for (int idx = wtid; idx < 64 * 64; idx += 128) {
            int n = idx >> 6, m = idx & 63;
            float pv = 0.0f;
            if (n < 49 && m < 49) pv = sa[n * 64 + m];
            *(__nv_bfloat16*)(sm + APB + n * 144 + m * 2) = __float2bfloat16(pv);
        }
    }
    __syncthreads();

    // ---- O = P V (64x32x64) ----
    {
        float acc[4][4];
#pragma unroll
        for (int a = 0; a < 4; a++)
#pragma unroll
            for (int c = 0; c < 4; c++) acc[a][c] = 0.0f;
#pragma unroll
        for (int ks = 0; ks < 4; ks++) {
            int kb = ks * 32;
            uint32_t af[4];
            ldsm_x4(af, sb + APB + aRow * 144 + kb + aKof);
#pragma unroll
            for (int nb = 0; nb < 2; nb++) {
                uint32_t bf[4];
                ldsm_x4(bf, sb + AV + (bRowB + nb * 16) * 144 + kb + bKof);
                mma16816(acc[2 * nb],     af, bf);
                mma16816(acc[2 * nb + 1], af, bf + 2);
            }
        }
#pragma unroll
        for (int half = 0; half < 2; half++) {
            int row = t * 16 + g + half * 8;
            if (row < 49) {
#pragma unroll
                for (int nt = 0; nt < 4; nt++) {
                    int col = nt * 8 + tq * 2;
                    __nv_bfloat162 hp;
                    hp.x = __float2bfloat16(acc[nt][half * 2 + 0]);
                    hp.y = __float2bfloat16(acc[nt][half * 2 + 1]);
                    size_t o = ((size_t)(w * 49 + row)) * C_DIM + h * HDIM + col;
                    *(__nv_bfloat162*)(oh + o) = hp;
                }
            }
        }
    }
}

// ---------------- launch ----------------
extern "C" void kernel_launch(void* const* d_in, const int* in_sizes, int n_in,
                              void* d_out, int out_size) {
    const float* query   = (const float*)d_in[0];
    const float* norm1_g = (const float*)d_in[1];
    const float* norm1_b = (const float*)d_in[2];
    const float* qkv_w   = (const float*)d_in[3];
    const float* qkv_b   = (const float*)d_in[4];
    const float* rpb     = (const float*)d_in[5];
    const float* proj_w  = (const float*)d_in[6];
    const float* proj_b  = (const float*)d_in[7];
    const float* norm2_g = (const float*)d_in[8];
    const float* norm2_b = (const float*)d_in[9];
    const float* fc1_w   = (const float*)d_in[10];
    const float* fc1_b   = (const float*)d_in[11];
    const float* fc2_w   = (const float*)d_in[12];
    const float* fc2_b   = (const float*)d_in[13];
    float* out = (float*)d_out;

    __nv_bfloat16 *xw, *qkvp, *att, *ln2, *hbuf;
    __nv_bfloat16 *wq, *wp, *w1, *w2;
    float *x;
    cudaGetSymbolAddress((void**)&xw, g_xw);
    cudaGetSymbolAddress((void**)&qkvp, g_qkv);
    cudaGetSymbolAddress((void**)&att, g_att);
    cudaGetSymbolAddress((void**)&x, g_x);
    cudaGetSymbolAddress((void**)&ln2, g_ln2);
    cudaGetSymbolAddress((void**)&hbuf, g_h);
    cudaGetSymbolAddress((void**)&wq, g_wqkv);
    cudaGetSymbolAddress((void**)&wp, g_wprj);
    cudaGetSymbolAddress((void**)&w1, g_wfc1);
    cudaGetSymbolAddress((void**)&w2, g_wfc2);

    const int SMEM  = NSTAGE * STAGE_BYTES;  // 61440
    const int SMEM2 = NSTAGE * STAGE2;       // 81920
    cudaFuncSetAttribute(gemm_mma<EPI_BF16>, cudaFuncAttributeMaxDynamicSharedMemorySize, SMEM);
    cudaFuncSetAttribute(gemm_mma<EPI_GELU>, cudaFuncAttributeMaxDynamicSharedMemorySize, SMEM);
    cudaFuncSetAttribute(gemm_mma_n192<EPI_SCATTER>, cudaFuncAttributeMaxDynamicSharedMemorySize, SMEM2);
    cudaFuncSetAttribute(gemm_mma_n192<EPI_RES>,     cudaFuncAttributeMaxDynamicSharedMemorySize, SMEM2);
    cudaFuncSetAttribute(attn_kernel, cudaFuncAttributeMaxDynamicSharedMemorySize, ATTN_SMEM);

    wprep_all<<<(442368 + 255) / 256, 256>>>(qkv_w, proj_w, fc1_w, fc2_w, wq, wp, w1, w2);

    // 1) LN1 + shift + window partition
    ln_kernel<true><<<M_TOK, 192>>>(query, norm1_g, norm1_b, xw);

    // 2) qkv  [100352,192] x [192,576] -> bf16
    gemm_mma<EPI_BF16><<<dim3(576 / BN, M_TOK / BM), 256, SMEM>>>(
        xw, wq, qkv_b, nullptr, nullptr, qkvp, 192, 576);

    // 3) windowed attention (mma.sync, 2 pairs per block)
    attn_kernel<<<2048 * NHEADS / 2, 256, ATTN_SMEM>>>(qkvp, rpb, att);

    // 4) proj + window reverse + unshift + residual(query)
    gemm_mma_n192<EPI_SCATTER><<<dim3(1, M_TOK / BM2), 256, SMEM2>>>(
        att, wp, proj_b, query, x, 192);

    // 5) LN2
    ln_kernel<false><<<M_TOK, 192>>>(x, norm2_g, norm2_b, ln2);

    // 6) fc1 + GELU
    gemm_mma<EPI_GELU><<<dim3(768 / BN, M_TOK / BM), 256, SMEM>>>(
        ln2, w1, fc1_b, nullptr, nullptr, hbuf, 192, 768);

    // 7) fc2 + residual(x) -> out
    gemm_mma_n192<EPI_RES><<<dim3(1, M_TOK / BM2), 256, SMEM2>>>(
        hbuf, w2, fc2_b, x, out, 768);
}

// round 12
// speedup vs baseline: 2.1609x; 1.1098x over previous
#include <cuda_runtime.h>
#include <cuda_bf16.h>
#include <math.h>
#include <stdint.h>

#define M_TOK   100352
#define C_DIM   192
#define NHEADS  6
#define HDIM    32
#define HIDDEN  768

// GEMM-64 tiling
#define BM 128
#define BN 64
#define BK 32
#define RPB 80
#define OFF_A  0
#define OFF_B  (BM*RPB)
#define STAGE_BYTES (BM*RPB + BN*RPB)
#define NSTAGE 4
// GEMM-192 tiling
#define BM2 64
#define BN2 192
#define OFF_B2 (BM2*RPB)
#define STAGE2 (BM2*RPB + BN2*RPB)

// attention smem layout (per pair)
#define AQ   0              // Q [64][80B]  (49 used)
#define AK   5120           // K [64][80B]
#define AV   10240          // V^T [32][144B]
#define ASA  14848          // fp32 S [49][64]  = 12544
#define APB  0              // P bf16 [64][144B] overlays AQ/AK (9216 <= 10240)
#define PAIR_STRIDE 27392
#define ATTN_SMEM (2*PAIR_STRIDE)   // 54784

typedef unsigned long long ull;

// ---------------- scratch ----------------
__device__ __nv_bfloat16 g_xw  [(size_t)M_TOK * C_DIM];
__device__ __nv_bfloat16 g_qkv [(size_t)M_TOK * 3 * C_DIM];
__device__ __nv_bfloat16 g_att [(size_t)M_TOK * C_DIM];
__device__ float         g_x   [(size_t)M_TOK * C_DIM];
__device__ __nv_bfloat16 g_ln2 [(size_t)M_TOK * C_DIM];
__device__ __nv_bfloat16 g_h   [(size_t)M_TOK * HIDDEN];
__device__ __nv_bfloat16 g_wqkv[576 * 192];
__device__ __nv_bfloat16 g_wprj[192 * 192];
__device__ __nv_bfloat16 g_wfc1[768 * 192];
__device__ __nv_bfloat16 g_wfc2[192 * 768];

// ---------------- helpers ----------------
__device__ __forceinline__ uint32_t smem_u32(const void* p) {
    uint32_t a;
    asm("{ .reg .u64 t; cvta.to.shared.u64 t, %1; cvt.u32.u64 %0, t; }" : "=r"(a) : "l"(p));
    return a;
}
__device__ __forceinline__ void cp16(uint32_t sa, const void* g) {
    asm volatile("cp.async.cg.shared.global [%0], [%1], 16;" :: "r"(sa), "l"(g));
}
__device__ __forceinline__ void cp_commit() { asm volatile("cp.async.commit_group;"); }
template <int N>
__device__ __forceinline__ void cp_wait() { asm volatile("cp.async.wait_group %0;" :: "n"(N)); }

__device__ __forceinline__ void ldsm_x4(uint32_t* r, uint32_t addr) {
    asm volatile("ldmatrix.sync.aligned.m8n8.x4.shared.b16 {%0,%1,%2,%3}, [%4];"
        : "=r"(r[0]), "=r"(r[1]), "=r"(r[2]), "=r"(r[3]) : "r"(addr));
}
__device__ __forceinline__ void mma16816(float* c, const uint32_t* a, const uint32_t* b) {
    asm volatile("mma.sync.aligned.m16n8k16.row.col.f32.bf16.bf16.f32 "
        "{%0,%1,%2,%3}, {%4,%5,%6,%7}, {%8,%9}, {%0,%1,%2,%3};"
        : "+f"(c[0]), "+f"(c[1]), "+f"(c[2]), "+f"(c[3])
        : "r"(a[0]), "r"(a[1]), "r"(a[2]), "r"(a[3]), "r"(b[0]), "r"(b[1]));
}
__device__ __forceinline__ float gelu_exact(float v) {
    return 0.5f * v * (1.0f + erff(v * 0.70710678118654752f));
}
__device__ __forceinline__ float warp_sum(float v) {
#pragma unroll
    for (int o = 16; o > 0; o >>= 1) v += __shfl_xor_sync(0xffffffffu, v, o);
    return v;
}
__device__ __forceinline__ float warp_max(float v) {
#pragma unroll
    for (int o = 16; o > 0; o >>= 1) v = fmaxf(v, __shfl_xor_sync(0xffffffffu, v, o));
    return v;
}
__device__ __forceinline__ int scatter_dst(int row) {
    int w = row / 49, n = row % 49;
    int bb = w >> 8, rr = w & 255;
    int wi = rr >> 4, wj = rr & 15;
    int i = n / 7, j = n % 7;
    int hh = wi * 7 + i + 3; if (hh >= 112) hh -= 112;
    int ww = wj * 7 + j + 3; if (ww >= 112) ww -= 112;
    return bb * 12544 + hh * 112 + ww;
}

// ---------------- combined weight transpose ----------------
__global__ void wprep_all(const float* __restrict__ Wq, const float* __restrict__ Wp,
                          const float* __restrict__ W1, const float* __restrict__ W2,
                          __nv_bfloat16* __restrict__ Tq, __nv_bfloat16* __restrict__ Tp,
                          __nv_bfloat16* __restrict__ T1, __nv_bfloat16* __restrict__ T2) {
    int i = blockIdx.x * 256 + threadIdx.x;
    if (i < 110592) {
        int k = i / 576, n = i % 576;
        Tq[(size_t)n * 192 + k] = __float2bfloat16(Wq[i]);
    } else if (i < 147456) {
        int j = i - 110592;
        int k = j / 192, n = j % 192;
        Tp[(size_t)n * 192 + k] = __float2bfloat16(Wp[j]);
    } else if (i < 294912) {
        int j = i - 147456;
        int k = j / 768, n = j % 768;
        T1[(size_t)n * 192 + k] = __float2bfloat16(W1[j]);
    } else if (i < 442368) {
        int j = i - 294912;
        int k = j / 192, n = j % 192;
        T2[(size_t)n * 768 + k] = __float2bfloat16(W2[j]);
    }
}

// ---------------- LayerNorm (+ optional shift/window gather) ----------------
template <bool GATHER>
__global__ void ln_kernel(const float* __restrict__ in,
                          const float* __restrict__ gamma, const float* __restrict__ beta,
                          __nv_bfloat16* __restrict__ oh) {
    int t = blockIdx.x, c = threadIdx.x;
    int src = GATHER ? scatter_dst(t) : t;
    float v = in[(size_t)src * C_DIM + c];
    __shared__ float s1[6], s2[6];
    int wid = c >> 5, lid = c & 31;
    float s = warp_sum(v);
    if (lid == 0) s1[wid] = s;
    __syncthreads();
    float mean = (s1[0] + s1[1] + s1[2] + s1[3] + s1[4] + s1[5]) * (1.0f / 192.0f);
    float d = v - mean;
    float sq = warp_sum(d * d);
    if (lid == 0) s2[wid] = sq;
    __syncthreads();
    float var = (s2[0] + s2[1] + s2[2] + s2[3] + s2[4] + s2[5]) * (1.0f / 192.0f);
    float o = d * rsqrtf(var + 1e-5f) * gamma[c] + beta[c];
    oh[(size_t)t * C_DIM + c] = __float2bfloat16(o);
}

enum { EPI_BF16 = 0, EPI_GELU = 1, EPI_SCATTER = 2, EPI_RES = 3 };

// ---------------- GEMM-64: CTA 128x64 ----------------
template <int EPI>
__global__ __launch_bounds__(256, 2)
void gemm_mma(const __nv_bfloat16* __restrict__ Aact,
              const __nv_bfloat16* __restrict__ Bw,
              const float* __restrict__ bias, const float* __restrict__ res,
              float* __restrict__ outf, __nv_bfloat16* __restrict__ outb,
              int K, int Nout) {
    extern __shared__ __align__(16) char smem[];
    int tid = threadIdx.x;
    int wid = tid >> 5, lid = tid & 31;
    int wm = wid & 3, wn = wid >> 2;
    int mBase = blockIdx.y * BM;
    int nBase = blockIdx.x * BN;
    uint32_t sb = smem_u32(smem);

    float acc[2][4][4];
#pragma unroll
    for (int a = 0; a < 2; a++)
#pragma unroll
        for (int b = 0; b < 4; b++)
#pragma unroll
            for (int c = 0; c < 4; c++) acc[a][b][c] = 0.0f;

    int nch = K / BK;

    auto issue = [&](int c) {
        uint32_t sbase = sb + (c % NSTAGE) * STAGE_BYTES;
        int k0 = c * BK;
#pragma unroll
        for (int u = 0; u < 3; u++) {
            int ch = tid + u * 256;
            if (ch < 512) {
                int r = ch >> 2, cc = ch & 3;
                cp16(sbase + OFF_A + r * RPB + cc * 16,
                     Aact + (size_t)(mBase + r) * K + k0 + cc * 8);
            } else {
                int q = ch - 512, r = q >> 2, cc = q & 3;
                cp16(sbase + OFF_B + r * RPB + cc * 16,
                     Bw + (size_t)(nBase + r) * K + k0 + cc * 8);
            }
        }
        cp_commit();
    };

    int aRow = wm * 32 + (lid & 7) + ((lid >> 3) & 1) * 8;
    int aKof = (lid >> 4) * 16;
    int bRow = wn * 32 + (lid & 7) + ((lid >> 4) & 1) * 8;
    int bKof = ((lid >> 3) & 1) * 16;

    issue(0);
    if (nch > 1) issue(1);
    if (nch > 2) issue(2);
    for (int c = 0; c < nch; c++) {
        int rem = nch - 1 - c;
        if (c + 3 < nch) issue(c + 3);
        if (rem >= 3)      cp_wait<3>();
        else if (rem == 2) cp_wait<2>();
        else if (rem == 1) cp_wait<1>();
        else               cp_wait<0>();
        __syncthreads();

        uint32_t buf = sb + (c % NSTAGE) * STAGE_BYTES;
#pragma unroll
        for (int kb = 0; kb < 64; kb += 32) {
            uint32_t ahf[2][4], bhf[2][4];
#pragma unroll
            for (int mt = 0; mt < 2; mt++)
                ldsm_x4(ahf[mt], buf + OFF_A + (aRow + mt * 16) * RPB + kb + aKof);
#pragma unroll
            for (int half = 0; half < 2; half++)
                ldsm_x4(bhf[half], buf + OFF_B + (bRow + half * 16) * RPB + kb + bKof);
#pragma unroll
            for (int mt = 0; mt < 2; mt++)
#pragma unroll
                for (int nt = 0; nt < 4; nt++)
                    mma16816(acc[mt][nt], ahf[mt], bhf[nt >> 1] + (nt & 1) * 2);
        }
        __syncthreads();
    }

    int g = lid >> 2, tq = lid & 3;
#pragma unroll
    for (int mt = 0; mt < 2; mt++) {
#pragma unroll
        for (int half = 0; half < 2; half++) {
            int row = mBase + wm * 32 + mt * 16 + g + half * 8;
            int dst = (EPI == EPI_SCATTER) ? scatter_dst(row) : row;
#pragma unroll
            for (int nt = 0; nt < 4; nt++) {
                int col = nBase + wn * 32 + nt * 8 + tq * 2;
                float v0 = acc[mt][nt][half * 2 + 0] + bias[col];
                float v1 = acc[mt][nt][half * 2 + 1] + bias[col + 1];
                if (EPI == EPI_GELU) {
                    v0 = gelu_exact(v0); v1 = gelu_exact(v1);
                }
                if (EPI == EPI_GELU || EPI == EPI_BF16) {
                    __nv_bfloat162 hp;
                    hp.x = __float2bfloat16(v0); hp.y = __float2bfloat16(v1);
                    *(__nv_bfloat162*)(outb + (size_t)row * Nout + col) = hp;
                } else {
                    size_t o = (size_t)dst * Nout + col;
                    float2 rv = *(const float2*)(res + o);
                    float2 w; w.x = v0 + rv.x; w.y = v1 + rv.y;
                    *(float2*)(outf + o) = w;
                }
            }
        }
    }
}

// ---------------- GEMM-192: CTA 64x192, full-N tile ----------------
template <int EPI>
__global__ __launch_bounds__(256, 2)
void gemm_mma_n192(const __nv_bfloat16* __restrict__ Aact,
                   const __nv_bfloat16* __restrict__ Bw,
                   const float* __restrict__ bias, const float* __restrict__ res,
                   float* __restrict__ outf, int K) {
    extern __shared__ __align__(16) char smem[];
    const int Nout = 192;
    int tid = threadIdx.x;
    int wid = tid >> 5, lid = tid & 31;
    int wm = wid & 1, wn = wid >> 1;
    int mBase = blockIdx.y * BM2;
    uint32_t sb = smem_u32(smem);

    float acc[2][6][4];
#pragma unroll
    for (int a = 0; a < 2; a++)
#pragma unroll
        for (int b = 0; b < 6; b++)
#pragma unroll
            for (int c = 0; c < 4; c++) acc[a][b][c] = 0.0f;

    int nch = K / BK;

    auto issue = [&](int c) {
        uint32_t sbase = sb + (c % NSTAGE) * STAGE2;
        int k0 = c * BK;
#pragma unroll
        for (int u = 0; u < 4; u++) {
            int ch = tid + u * 256;
            if (ch < 256) {
                int r = ch >> 2, cc = ch & 3;
                cp16(sbase + r * RPB + cc * 16,
                     Aact + (size_t)(mBase + r) * K + k0 + cc * 8);
            } else {
                int q = ch - 256, r = q >> 2, cc = q & 3;
                cp16(sbase + OFF_B2 + r * RPB + cc * 16,
                     Bw + (size_t)r * K + k0 + cc * 8);
            }
        }
        cp_commit();
    };

    int aRow = wm * 32 + (lid & 7) + ((lid >> 3) & 1) * 8;
    int aKof = (lid >> 4) * 16;
    int bRow = wn * 48 + (lid & 7) + ((lid >> 4) & 1) * 8;
    int bKof = ((lid >> 3) & 1) * 16;

    issue(0);
    if (nch > 1) issue(1);
    if (nch > 2) issue(2);
    for (int c = 0; c < nch; c++) {
        int rem = nch - 1 - c;
        if (c + 3 < nch) issue(c + 3);
        if (rem >= 3)      cp_wait<3>();
        else if (rem == 2) cp_wait<2>();
        else if (rem == 1) cp_wait<1>();
        else               cp_wait<0>();
        __syncthreads();

        uint32_t buf = sb + (c % NSTAGE) * STAGE2;
#pragma unroll
        for (int kb = 0; kb < 64; kb += 32) {
            uint32_t ahf[2][4], bhf[3][4];
#pragma unroll
            for (int mt = 0; mt < 2; mt++)
                ldsm_x4(ahf[mt], buf + (aRow + mt * 16) * RPB + kb + aKof);
#pragma unroll
            for (int nb = 0; nb < 3; nb++)
                ldsm_x4(bhf[nb], buf + OFF_B2 + (bRow + nb * 16) * RPB + kb + bKof);
#pragma unroll
            for (int mt = 0; mt < 2; mt++)
#pragma unroll
                for (int nt = 0; nt < 6; nt++)
                    mma16816(acc[mt][nt], ahf[mt], bhf[nt >> 1] + (nt & 1) * 2);
        }
        __syncthreads();
    }

    int g = lid >> 2, tq = lid & 3;
#pragma unroll
    for (int mt = 0; mt < 2; mt++) {
#pragma unroll
        for (int half = 0; half < 2; half++) {
            int row = mBase + wm * 32 + mt * 16 + g + half * 8;
            int dst = (EPI == EPI_SCATTER) ? scatter_dst(row) : row;
#pragma unroll
            for (int nt = 0; nt < 6; nt++) {
                int col = wn * 48 + nt * 8 + tq * 2;
                float v0 = acc[mt][nt][half * 2 + 0] + bias[col];
                float v1 = acc[mt][nt][half * 2 + 1] + bias[col + 1];
                size_t o = (size_t)dst * Nout + col;
                float2 rv = *(const float2*)(res + o);
                float2 w; w.x = v0 + rv.x; w.y = v1 + rv.y;
                *(float2*)(outf + o) = w;
            }
        }
    }
}

// ---------------- Windowed attention via mma.sync (vectorized IO, fused P) ----------------
// block = 256 thr = 2 (window,head) pairs x 4 warps
__global__ __launch_bounds__(256)
void attn_kernel(const __nv_bfloat16* __restrict__ qkv,
                 const float* __restrict__ rpb,
                 __nv_bfloat16* __restrict__ oh) {
    extern __shared__ __align__(16) char smem[];
    __shared__ int Ls[49];
    __shared__ int Rs[2][49];

    int tid = threadIdx.x;
    int wid = tid >> 5, lid = tid & 31;
    int ph = wid >> 2;            // pair in block (0/1)
    int t  = wid & 3;             // warp in pair
    int wtid = tid & 127;
    int pair = blockIdx.x * 2 + ph;
    int w = pair / NHEADS;
    int h = pair - w * NHEADS;

    char* sm = smem + ph * PAIR_STRIDE;
    uint32_t sb = smem_u32(smem) + ph * PAIR_STRIDE;
    const float scale = 0.17677669529663687f;

    int r = w & 255;
    int wi = r >> 4, wj = r & 15;

    if (tid < 49) Ls[tid] = 13 * (tid / 7) + tid % 7;
    if (wtid < 49) {
        int i = wtid / 7, j = wtid % 7;
        int hp = wi * 7 + i, wp = wj * 7 + j;
        Rs[ph][wtid] = (hp < 105 ? 0 : (hp < 109 ? 1 : 2)) * 3 + (wp < 105 ? 0 : (wp < 109 ? 1 : 2));
    }

    // vectorized loads: 196 chunks (49 rows x 4 x uint4). Q/K stored uint4; V scattered to V^T.
    for (int idx = wtid; idx < 196; idx += 128) {
        int n = idx >> 2, c = idx & 3;
        size_t base = ((size_t)(w * 49 + n)) * (3 * C_DIM) + h * HDIM + c * 8;
        uint4 qv = *(const uint4*)(qkv + base);
        uint4 kv = *(const uint4*)(qkv + base + C_DIM);
        uint4 vv = *(const uint4*)(qkv + base + 2 * C_DIM);
        *(uint4*)(sm + AQ + n * 80 + c * 16) = qv;
        *(uint4*)(sm + AK + n * 80 + c * 16) = kv;
        const __nv_bfloat16* vp = reinterpret_cast<const __nv_bfloat16*>(&vv);
#pragma unroll
        for (int e = 0; e < 8; e++)
            *(__nv_bfloat16*)(sm + AV + (c * 8 + e) * 144 + n * 2) = vp[e];
    }
    // zero V^T padding cols m=49..63
    for (int idx = wtid; idx < 32 * 15; idx += 128) {
        int d = idx / 15, m = 49 + idx % 15;
        *(__nv_bfloat16*)(sm + AV + d * 144 + m * 2) = __float2bfloat16(0.0f);
    }
    __syncthreads();

    int aRow = t * 16 + (lid & 7) + ((lid >> 3) & 1) * 8;
    int aKof = (lid >> 4) * 16;
    int bRowB = (lid & 7) + ((lid >> 4) & 1) * 8;
    int bKof = ((lid >> 3) & 1) * 16;
    int g = lid >> 2, tq = lid & 3;

    // ---- S = Q K^T (64x64x32) -> fp32 S[49][64] with scale+bias+mask ----
    {
        float acc[8][4];
#pragma unroll
        for (int a = 0; a < 8; a++)
#pragma unroll
            for (int c = 0; c < 4; c++) acc[a][c] = 0.0f;
#pragma unroll
        for (int kb = 0; kb < 64; kb += 32) {
            uint32_t af[4];
            ldsm_x4(af, sb + AQ + aRow * 80 + kb + aKof);
#pragma unroll
            for (int nb = 0; nb < 4; nb++) {
                uint32_t bf[4];
                ldsm_x4(bf, sb + AK + (bRowB + nb * 16) * 80 + kb + bKof);
                mma16816(acc[2 * nb],     af, bf);
                mma16816(acc[2 * nb + 1], af, bf + 2);
            }
        }
        float* sa = (float*)(sm + ASA);
#pragma unroll
        for (int half = 0; half < 2; half++) {
            int row = t * 16 + g + half * 8;
            if (row < 49) {
                int L0 = Ls[row] + 84, R0 = Rs[ph][row];
#pragma unroll
                for (int nt = 0; nt < 8; nt++) {
                    int col = nt * 8 + tq * 2;
                    if (col < 49) {
#pragma unroll
                        for (int e = 0; e < 2; e++) {
                            int cc = col + e;
                            if (cc < 49) {
                                float vs = acc[nt][half * 2 + e] * scale
                                         + rpb[(L0 - Ls[cc]) * NHEADS + h]
                                         + (R0 == Rs[ph][cc] ? 0.0f : -100.0f);
                                sa[row * 64 + cc] = vs;
                            }
                        }
                    }
                }
            }
        }
    }
    __syncthreads();

    // ---- softmax rows; write normalized bf16 P directly into APB ----
    {
        float* sa = (float*)(sm + ASA);
        char* pb = sm + APB;
        for (int n = t; n < 49; n += 4) {
            float v1 = sa[n * 64 + lid];
            float v2 = (lid < 17) ? sa[n * 64 + 32 + lid] : -1e30f;
            float mx = warp_max(fmaxf(v1, v2));
            float e1 = __expf(v1 - mx);
            float e2 = (lid < 17) ? __expf(v2 - mx) : 0.0f;
            float s = warp_sum(e1 + e2);
            float inv = 1.0f / s;
            *(__nv_bfloat16*)(pb + n * 144 + lid * 2) = __float2bfloat16(e1 * inv);
            *(__nv_bfloat16*)(pb + n * 144 + (lid + 32) * 2) =
                __float2bfloat16(lid < 17 ? e2 * inv : 0.0f);
        }
        // zero P padding rows n=49..63 (first 128 bytes = 64 cols)
        for (int idx = wtid; idx < 120; idx += 128) {
            int n = 49 + (idx >> 3), c = idx & 7;
            *(uint4*)(pb + n * 144 + c * 16) = make_uint4(0, 0, 0, 0);
        }
    }
    __syncthreads();

    // ---- O = P V (64x32x64) ----
    {
        float acc[4][4];
#pragma unroll
        for (int a = 0; a < 4; a++)
#pragma unroll
            for (int c = 0; c < 4; c++) acc[a][c] = 0.0f;
#pragma unroll
        for (int ks = 0; ks < 4; ks++) {
            int kb = ks * 32;
            uint32_t af[4];
            ldsm_x4(af, sb + APB + aRow * 144 + kb + aKof);
#pragma unroll
            for (int nb = 0; nb < 2; nb++) {
                uint32_t bf[4];
                ldsm_x4(bf, sb + AV + (bRowB + nb * 16) * 144 + kb + bKof);
                mma16816(acc[2 * nb],     af, bf);
                mma16816(acc[2 * nb + 1], af, bf + 2);
            }
        }
#pragma unroll
        for (int half = 0; half < 2; half++) {
            int row = t * 16 + g + half * 8;
            if (row < 49) {
#pragma unroll
                for (int nt = 0; nt < 4; nt++) {
                    int col = nt * 8 + tq * 2;
                    __nv_bfloat162 hp;
                    hp.x = __float2bfloat16(acc[nt][half * 2 + 0]);
                    hp.y = __float2bfloat16(acc[nt][half * 2 + 1]);
                    size_t o = ((size_t)(w * 49 + row)) * C_DIM + h * HDIM + col;
                    *(__nv_bfloat162*)(oh + o) = hp;
                }
            }
        }
    }
}

// ---------------- launch ----------------
extern "C" void kernel_launch(void* const* d_in, const int* in_sizes, int n_in,
                              void* d_out, int out_size) {
    const float* query   = (const float*)d_in[0];
    const float* norm1_g = (const float*)d_in[1];
    const float* norm1_b = (const float*)d_in[2];
    const float* qkv_w   = (const float*)d_in[3];
    const float* qkv_b   = (const float*)d_in[4];
    const float* rpb     = (const float*)d_in[5];
    const float* proj_w  = (const float*)d_in[6];
    const float* proj_b  = (const float*)d_in[7];
    const float* norm2_g = (const float*)d_in[8];
    const float* norm2_b = (const float*)d_in[9];
    const float* fc1_w   = (const float*)d_in[10];
    const float* fc1_b   = (const float*)d_in[11];
    const float* fc2_w   = (const float*)d_in[12];
    const float* fc2_b   = (const float*)d_in[13];
    float* out = (float*)d_out;

    __nv_bfloat16 *xw, *qkvp, *att, *ln2, *hbuf;
    __nv_bfloat16 *wq, *wp, *w1, *w2;
    float *x;
    cudaGetSymbolAddress((void**)&xw, g_xw);
    cudaGetSymbolAddress((void**)&qkvp, g_qkv);
    cudaGetSymbolAddress((void**)&att, g_att);
    cudaGetSymbolAddress((void**)&x, g_x);
    cudaGetSymbolAddress((void**)&ln2, g_ln2);
    cudaGetSymbolAddress((void**)&hbuf, g_h);
    cudaGetSymbolAddress((void**)&wq, g_wqkv);
    cudaGetSymbolAddress((void**)&wp, g_wprj);
    cudaGetSymbolAddress((void**)&w1, g_wfc1);
    cudaGetSymbolAddress((void**)&w2, g_wfc2);

    const int SMEM  = NSTAGE * STAGE_BYTES;  // 61440
    const int SMEM2 = NSTAGE * STAGE2;       // 81920
    cudaFuncSetAttribute(gemm_mma<EPI_BF16>, cudaFuncAttributeMaxDynamicSharedMemorySize, SMEM);
    cudaFuncSetAttribute(gemm_mma<EPI_GELU>, cudaFuncAttributeMaxDynamicSharedMemorySize, SMEM);
    cudaFuncSetAttribute(gemm_mma_n192<EPI_SCATTER>, cudaFuncAttributeMaxDynamicSharedMemorySize, SMEM2);
    cudaFuncSetAttribute(gemm_mma_n192<EPI_RES>,     cudaFuncAttributeMaxDynamicSharedMemorySize, SMEM2);
    cudaFuncSetAttribute(attn_kernel, cudaFuncAttributeMaxDynamicSharedMemorySize, ATTN_SMEM);

    wprep_all<<<(442368 + 255) / 256, 256>>>(qkv_w, proj_w, fc1_w, fc2_w, wq, wp, w1, w2);

    // 1) LN1 + shift + window partition
    ln_kernel<true><<<M_TOK, 192>>>(query, norm1_g, norm1_b, xw);

    // 2) qkv  [100352,192] x [192,576] -> bf16
    gemm_mma<EPI_BF16><<<dim3(576 / BN, M_TOK / BM), 256, SMEM>>>(
        xw, wq, qkv_b, nullptr, nullptr, qkvp, 192, 576);

    // 3) windowed attention (mma.sync, 2 pairs per block)
    attn_kernel<<<2048 * NHEADS / 2, 256, ATTN_SMEM>>>(qkvp, rpb, att);

    // 4) proj + window reverse + unshift + residual(query)
    gemm_mma_n192<EPI_SCATTER><<<dim3(1, M_TOK / BM2), 256, SMEM2>>>(
        att, wp, proj_b, query, x, 192);

    // 5) LN2
    ln_kernel<false><<<M_TOK, 192>>>(x, norm2_g, norm2_b, ln2);

    // 6) fc1 + GELU
    gemm_mma<EPI_GELU><<<dim3(768 / BN, M_TOK / BM), 256, SMEM>>>(
        ln2, w1, fc1_b, nullptr, nullptr, hbuf, 192, 768);

    // 7) fc2 + residual(x) -> out
    gemm_mma_n192<EPI_RES><<<dim3(1, M_TOK / BM2), 256, SMEM2>>>(
        hbuf, w2, fc2_b, x, out, 768);
}

// round 13
// speedup vs baseline: 2.3380x; 1.0819x over previous
#include <cuda_runtime.h>
#include <cuda_bf16.h>
#include <math.h>
#include <stdint.h>

#define M_TOK   100352
#define C_DIM   192
#define NHEADS  6
#define HDIM    32
#define HIDDEN  768

// GEMM-64 tiling
#define BM 128
#define BN 64
#define BK 32
#define RPB 80
#define OFF_A  0
#define OFF_B  (BM*RPB)
#define STAGE_BYTES (BM*RPB + BN*RPB)
#define NSTAGE 4
// GEMM-192 tiling
#define BM2 64
#define BN2 192
#define OFF_B2 (BM2*RPB)
#define STAGE2 (BM2*RPB + BN2*RPB)

// attention smem layout (per pair)
#define AQ   0              // Q [64][80B]
#define AK   5120           // K [64][80B]
#define AV   10240          // V [64][80B] row-major (trans-ldsm for PV)
#define ASA  15360          // fp32 S [49][64] = 12544
#define APB  0              // P bf16 [64][144B] overlays AQ/AK (9216 <= 10240)
#define PAIR_STRIDE 27904
#define ATTN_SMEM (2*PAIR_STRIDE)   // 55808

typedef unsigned long long ull;

// ---------------- scratch ----------------
__device__ __nv_bfloat16 g_xw  [(size_t)M_TOK * C_DIM];
__device__ __nv_bfloat16 g_qkv [(size_t)M_TOK * 3 * C_DIM];
__device__ __nv_bfloat16 g_att [(size_t)M_TOK * C_DIM];
__device__ float         g_x   [(size_t)M_TOK * C_DIM];
__device__ __nv_bfloat16 g_ln2 [(size_t)M_TOK * C_DIM];
__device__ __nv_bfloat16 g_h   [(size_t)M_TOK * HIDDEN];
__device__ __nv_bfloat16 g_wqkv[576 * 192];
__device__ __nv_bfloat16 g_wprj[192 * 192];
__device__ __nv_bfloat16 g_wfc1[768 * 192];
__device__ __nv_bfloat16 g_wfc2[192 * 768];

// ---------------- helpers ----------------
__device__ __forceinline__ uint32_t smem_u32(const void* p) {
    uint32_t a;
    asm("{ .reg .u64 t; cvta.to.shared.u64 t, %1; cvt.u32.u64 %0, t; }" : "=r"(a) : "l"(p));
    return a;
}
__device__ __forceinline__ void cp16(uint32_t sa, const void* g) {
    asm volatile("cp.async.cg.shared.global [%0], [%1], 16;" :: "r"(sa), "l"(g));
}
__device__ __forceinline__ void cp_commit() { asm volatile("cp.async.commit_group;"); }
template <int N>
__device__ __forceinline__ void cp_wait() { asm volatile("cp.async.wait_group %0;" :: "n"(N)); }

__device__ __forceinline__ void ldsm_x4(uint32_t* r, uint32_t addr) {
    asm volatile("ldmatrix.sync.aligned.m8n8.x4.shared.b16 {%0,%1,%2,%3}, [%4];"
        : "=r"(r[0]), "=r"(r[1]), "=r"(r[2]), "=r"(r[3]) : "r"(addr));
}
__device__ __forceinline__ void ldsm_x4_t(uint32_t* r, uint32_t addr) {
    asm volatile("ldmatrix.sync.aligned.m8n8.x4.trans.shared.b16 {%0,%1,%2,%3}, [%4];"
        : "=r"(r[0]), "=r"(r[1]), "=r"(r[2]), "=r"(r[3]) : "r"(addr));
}
__device__ __forceinline__ void mma16816(float* c, const uint32_t* a, const uint32_t* b) {
    asm volatile("mma.sync.aligned.m16n8k16.row.col.f32.bf16.bf16.f32 "
        "{%0,%1,%2,%3}, {%4,%5,%6,%7}, {%8,%9}, {%0,%1,%2,%3};"
        : "+f"(c[0]), "+f"(c[1]), "+f"(c[2]), "+f"(c[3])
        : "r"(a[0]), "r"(a[1]), "r"(a[2]), "r"(a[3]), "r"(b[0]), "r"(b[1]));
}
__device__ __forceinline__ float gelu_exact(float v) {
    return 0.5f * v * (1.0f + erff(v * 0.70710678118654752f));
}
__device__ __forceinline__ float warp_sum(float v) {
#pragma unroll
    for (int o = 16; o > 0; o >>= 1) v += __shfl_xor_sync(0xffffffffu, v, o);
    return v;
}
__device__ __forceinline__ float warp_max(float v) {
#pragma unroll
    for (int o = 16; o > 0; o >>= 1) v = fmaxf(v, __shfl_xor_sync(0xffffffffu, v, o));
    return v;
}
__device__ __forceinline__ int scatter_dst(int row) {
    int w = row / 49, n = row % 49;
    int bb = w >> 8, rr = w & 255;
    int wi = rr >> 4, wj = rr & 15;
    int i = n / 7, j = n % 7;
    int hh = wi * 7 + i + 3; if (hh >= 112) hh -= 112;
    int ww = wj * 7 + j + 3; if (ww >= 112) ww -= 112;
    return bb * 12544 + hh * 112 + ww;
}

// ---------------- combined weight transpose ----------------
__global__ void wprep_all(const float* __restrict__ Wq, const float* __restrict__ Wp,
                          const float* __restrict__ W1, const float* __restrict__ W2,
                          __nv_bfloat16* __restrict__ Tq, __nv_bfloat16* __restrict__ Tp,
                          __nv_bfloat16* __restrict__ T1, __nv_bfloat16* __restrict__ T2) {
    int i = blockIdx.x * 256 + threadIdx.x;
    if (i < 110592) {
        int k = i / 576, n = i % 576;
        Tq[(size_t)n * 192 + k] = __float2bfloat16(Wq[i]);
    } else if (i < 147456) {
        int j = i - 110592;
        int k = j / 192, n = j % 192;
        Tp[(size_t)n * 192 + k] = __float2bfloat16(Wp[j]);
    } else if (i < 294912) {
        int j = i - 147456;
        int k = j / 768, n = j % 768;
        T1[(size_t)n * 192 + k] = __float2bfloat16(W1[j]);
    } else if (i < 442368) {
        int j = i - 294912;
        int k = j / 192, n = j % 192;
        T2[(size_t)n * 768 + k] = __float2bfloat16(W2[j]);
    }
}

// ---------------- LayerNorm (gather variant, for LN1 only) ----------------
template <bool GATHER>
__global__ void ln_kernel(const float* __restrict__ in,
                          const float* __restrict__ gamma, const float* __restrict__ beta,
                          __nv_bfloat16* __restrict__ oh) {
    int t = blockIdx.x, c = threadIdx.x;
    int src = GATHER ? scatter_dst(t) : t;
    float v = in[(size_t)src * C_DIM + c];
    __shared__ float s1[6], s2[6];
    int wid = c >> 5, lid = c & 31;
    float s = warp_sum(v);
    if (lid == 0) s1[wid] = s;
    __syncthreads();
    float mean = (s1[0] + s1[1] + s1[2] + s1[3] + s1[4] + s1[5]) * (1.0f / 192.0f);
    float d = v - mean;
    float sq = warp_sum(d * d);
    if (lid == 0) s2[wid] = sq;
    __syncthreads();
    float var = (s2[0] + s2[1] + s2[2] + s2[3] + s2[4] + s2[5]) * (1.0f / 192.0f);
    float o = d * rsqrtf(var + 1e-5f) * gamma[c] + beta[c];
    oh[(size_t)t * C_DIM + c] = __float2bfloat16(o);
}

enum { EPI_BF16 = 0, EPI_GELU = 1, EPI_SCATTER = 2, EPI_RES = 3 };

// ---------------- GEMM-64: CTA 128x64 ----------------
template <int EPI>
__global__ __launch_bounds__(256, 2)
void gemm_mma(const __nv_bfloat16* __restrict__ Aact,
              const __nv_bfloat16* __restrict__ Bw,
              const float* __restrict__ bias, const float* __restrict__ res,
              float* __restrict__ outf, __nv_bfloat16* __restrict__ outb,
              int K, int Nout) {
    extern __shared__ __align__(16) char smem[];
    int tid = threadIdx.x;
    int wid = tid >> 5, lid = tid & 31;
    int wm = wid & 3, wn = wid >> 2;
    int mBase = blockIdx.y * BM;
    int nBase = blockIdx.x * BN;
    uint32_t sb = smem_u32(smem);

    float acc[2][4][4];
#pragma unroll
    for (int a = 0; a < 2; a++)
#pragma unroll
        for (int b = 0; b < 4; b++)
#pragma unroll
            for (int c = 0; c < 4; c++) acc[a][b][c] = 0.0f;

    int nch = K / BK;

    auto issue = [&](int c) {
        uint32_t sbase = sb + (c % NSTAGE) * STAGE_BYTES;
        int k0 = c * BK;
#pragma unroll
        for (int u = 0; u < 3; u++) {
            int ch = tid + u * 256;
            if (ch < 512) {
                int r = ch >> 2, cc = ch & 3;
                cp16(sbase + OFF_A + r * RPB + cc * 16,
                     Aact + (size_t)(mBase + r) * K + k0 + cc * 8);
            } else {
                int q = ch - 512, r = q >> 2, cc = q & 3;
                cp16(sbase + OFF_B + r * RPB + cc * 16,
                     Bw + (size_t)(nBase + r) * K + k0 + cc * 8);
            }
        }
        cp_commit();
    };

    int aRow = wm * 32 + (lid & 7) + ((lid >> 3) & 1) * 8;
    int aKof = (lid >> 4) * 16;
    int bRow = wn * 32 + (lid & 7) + ((lid >> 4) & 1) * 8;
    int bKof = ((lid >> 3) & 1) * 16;

    issue(0);
    if (nch > 1) issue(1);
    if (nch > 2) issue(2);
    for (int c = 0; c < nch; c++) {
        int rem = nch - 1 - c;
        if (c + 3 < nch) issue(c + 3);
        if (rem >= 3)      cp_wait<3>();
        else if (rem == 2) cp_wait<2>();
        else if (rem == 1) cp_wait<1>();
        else               cp_wait<0>();
        __syncthreads();

        uint32_t buf = sb + (c % NSTAGE) * STAGE_BYTES;
#pragma unroll
        for (int kb = 0; kb < 64; kb += 32) {
            uint32_t ahf[2][4], bhf[2][4];
#pragma unroll
            for (int mt = 0; mt < 2; mt++)
                ldsm_x4(ahf[mt], buf + OFF_A + (aRow + mt * 16) * RPB + kb + aKof);
#pragma unroll
            for (int half = 0; half < 2; half++)
                ldsm_x4(bhf[half], buf + OFF_B + (bRow + half * 16) * RPB + kb + bKof);
#pragma unroll
            for (int mt = 0; mt < 2; mt++)
#pragma unroll
                for (int nt = 0; nt < 4; nt++)
                    mma16816(acc[mt][nt], ahf[mt], bhf[nt >> 1] + (nt & 1) * 2);
        }
        __syncthreads();
    }

    int g = lid >> 2, tq = lid & 3;
#pragma unroll
    for (int mt = 0; mt < 2; mt++) {
#pragma unroll
        for (int half = 0; half < 2; half++) {
            int row = mBase + wm * 32 + mt * 16 + g + half * 8;
            int dst = (EPI == EPI_SCATTER) ? scatter_dst(row) : row;
#pragma unroll
            for (int nt = 0; nt < 4; nt++) {
                int col = nBase + wn * 32 + nt * 8 + tq * 2;
                float v0 = acc[mt][nt][half * 2 + 0] + bias[col];
                float v1 = acc[mt][nt][half * 2 + 1] + bias[col + 1];
                if (EPI == EPI_GELU) {
                    v0 = gelu_exact(v0); v1 = gelu_exact(v1);
                }
                if (EPI == EPI_GELU || EPI == EPI_BF16) {
                    __nv_bfloat162 hp;
                    hp.x = __float2bfloat16(v0); hp.y = __float2bfloat16(v1);
                    *(__nv_bfloat162*)(outb + (size_t)row * Nout + col) = hp;
                } else {
                    size_t o = (size_t)dst * Nout + col;
                    float2 rv = *(const float2*)(res + o);
                    float2 w; w.x = v0 + rv.x; w.y = v1 + rv.y;
                    *(float2*)(outf + o) = w;
                }
            }
        }
    }
}

// ---------------- GEMM-192: CTA 64x192, full-N (fc2: EPI_RES) ----------------
template <int EPI>
__global__ __launch_bounds__(256, 2)
void gemm_mma_n192(const __nv_bfloat16* __restrict__ Aact,
                   const __nv_bfloat16* __restrict__ Bw,
                   const float* __restrict__ bias, const float* __restrict__ res,
                   float* __restrict__ outf, int K) {
    extern __shared__ __align__(16) char smem[];
    const int Nout = 192;
    int tid = threadIdx.x;
    int wid = tid >> 5, lid = tid & 31;
    int wm = wid & 1, wn = wid >> 1;
    int mBase = blockIdx.y * BM2;
    uint32_t sb = smem_u32(smem);

    float acc[2][6][4];
#pragma unroll
    for (int a = 0; a < 2; a++)
#pragma unroll
        for (int b = 0; b < 6; b++)
#pragma unroll
            for (int c = 0; c < 4; c++) acc[a][b][c] = 0.0f;

    int nch = K / BK;

    auto issue = [&](int c) {
        uint32_t sbase = sb + (c % NSTAGE) * STAGE2;
        int k0 = c * BK;
#pragma unroll
        for (int u = 0; u < 4; u++) {
            int ch = tid + u * 256;
            if (ch < 256) {
                int r = ch >> 2, cc = ch & 3;
                cp16(sbase + r * RPB + cc * 16,
                     Aact + (size_t)(mBase + r) * K + k0 + cc * 8);
            } else {
                int q = ch - 256, r = q >> 2, cc = q & 3;
                cp16(sbase + OFF_B2 + r * RPB + cc * 16,
                     Bw + (size_t)r * K + k0 + cc * 8);
            }
        }
        cp_commit();
    };

    int aRow = wm * 32 + (lid & 7) + ((lid >> 3) & 1) * 8;
    int aKof = (lid >> 4) * 16;
    int bRow = wn * 48 + (lid & 7) + ((lid >> 4) & 1) * 8;
    int bKof = ((lid >> 3) & 1) * 16;

    issue(0);
    if (nch > 1) issue(1);
    if (nch > 2) issue(2);
    for (int c = 0; c < nch; c++) {
        int rem = nch - 1 - c;
        if (c + 3 < nch) issue(c + 3);
        if (rem >= 3)      cp_wait<3>();
        else if (rem == 2) cp_wait<2>();
        else if (rem == 1) cp_wait<1>();
        else               cp_wait<0>();
        __syncthreads();

        uint32_t buf = sb + (c % NSTAGE) * STAGE2;
#pragma unroll
        for (int kb = 0; kb < 64; kb += 32) {
            uint32_t ahf[2][4], bhf[3][4];
#pragma unroll
            for (int mt = 0; mt < 2; mt++)
                ldsm_x4(ahf[mt], buf + (aRow + mt * 16) * RPB + kb + aKof);
#pragma unroll
            for (int nb = 0; nb < 3; nb++)
                ldsm_x4(bhf[nb], buf + OFF_B2 + (bRow + nb * 16) * RPB + kb + bKof);
#pragma unroll
            for (int mt = 0; mt < 2; mt++)
#pragma unroll
                for (int nt = 0; nt < 6; nt++)
                    mma16816(acc[mt][nt], ahf[mt], bhf[nt >> 1] + (nt & 1) * 2);
        }
        __syncthreads();
    }

    int g = lid >> 2, tq = lid & 3;
#pragma unroll
    for (int mt = 0; mt < 2; mt++) {
#pragma unroll
        for (int half = 0; half < 2; half++) {
            int row = mBase + wm * 32 + mt * 16 + g + half * 8;
            int dst = (EPI == EPI_SCATTER) ? scatter_dst(row) : row;
#pragma unroll
            for (int nt = 0; nt < 6; nt++) {
                int col = wn * 48 + nt * 8 + tq * 2;
                float v0 = acc[mt][nt][half * 2 + 0] + bias[col];
                float v1 = acc[mt][nt][half * 2 + 1] + bias[col + 1];
                size_t o = (size_t)dst * Nout + col;
                float2 rv = *(const float2*)(res + o);
                float2 w; w.x = v0 + rv.x; w.y = v1 + rv.y;
                *(float2*)(outf + o) = w;
            }
        }
    }
}

// ---------------- proj GEMM + scatter + residual + fused LN2 ----------------
__global__ __launch_bounds__(256, 2)
void gemm_proj_ln(const __nv_bfloat16* __restrict__ Aact,
                  const __nv_bfloat16* __restrict__ Bw,
                  const float* __restrict__ bias, const float* __restrict__ res,
                  float* __restrict__ outx, __nv_bfloat16* __restrict__ outln,
                  const float* __restrict__ gamma, const float* __restrict__ beta,
                  int K) {
    extern __shared__ __align__(16) char smem[];
    const int Nout = 192;
    int tid = threadIdx.x;
    int wid = tid >> 5, lid = tid & 31;
    int wm = wid & 1, wn = wid >> 1;
    int mBase = blockIdx.y * BM2;
    uint32_t sb = smem_u32(smem);

    float acc[2][6][4];
#pragma unroll
    for (int a = 0; a < 2; a++)
#pragma unroll
        for (int b = 0; b < 6; b++)
#pragma unroll
            for (int c = 0; c < 4; c++) acc[a][b][c] = 0.0f;

    int nch = K / BK;

    auto issue = [&](int c) {
        uint32_t sbase = sb + (c % NSTAGE) * STAGE2;
        int k0 = c * BK;
#pragma unroll
        for (int u = 0; u < 4; u++) {
            int ch = tid + u * 256;
            if (ch < 256) {
                int r = ch >> 2, cc = ch & 3;
                cp16(sbase + r * RPB + cc * 16,
                     Aact + (size_t)(mBase + r) * K + k0 + cc * 8);
            } else {
                int q = ch - 256, r = q >> 2, cc = q & 3;
                cp16(sbase + OFF_B2 + r * RPB + cc * 16,
                     Bw + (size_t)r * K + k0 + cc * 8);
            }
        }
        cp_commit();
    };

    int aRow = wm * 32 + (lid & 7) + ((lid >> 3) & 1) * 8;
    int aKof = (lid >> 4) * 16;
    int bRow = wn * 48 + (lid & 7) + ((lid >> 4) & 1) * 8;
    int bKof = ((lid >> 3) & 1) * 16;

    issue(0);
    if (nch > 1) issue(1);
    if (nch > 2) issue(2);
    for (int c = 0; c < nch; c++) {
        int rem = nch - 1 - c;
        if (c + 3 < nch) issue(c + 3);
        if (rem >= 3)      cp_wait<3>();
        else if (rem == 2) cp_wait<2>();
        else if (rem == 1) cp_wait<1>();
        else               cp_wait<0>();
        __syncthreads();

        uint32_t buf = sb + (c % NSTAGE) * STAGE2;
#pragma unroll
        for (int kb = 0; kb < 64; kb += 32) {
            uint32_t ahf[2][4], bhf[3][4];
#pragma unroll
            for (int mt = 0; mt < 2; mt++)
                ldsm_x4(ahf[mt], buf + (aRow + mt * 16) * RPB + kb + aKof);
#pragma unroll
            for (int nb = 0; nb < 3; nb++)
                ldsm_x4(bhf[nb], buf + OFF_B2 + (bRow + nb * 16) * RPB + kb + bKof);
#pragma unroll
            for (int mt = 0; mt < 2; mt++)
#pragma unroll
                for (int nt = 0; nt < 6; nt++)
                    mma16816(acc[mt][nt], ahf[mt], bhf[nt >> 1] + (nt & 1) * 2);
        }
        __syncthreads();
    }

    // ---- epilogue: x = acc + bias + residual; write x; fused LN -> outln ----
    int g = lid >> 2, tq = lid & 3;
    int dsts[2][2];
    float psum[2][2], psq[2][2];
#pragma unroll
    for (int mt = 0; mt < 2; mt++) {
#pragma unroll
        for (int half = 0; half < 2; half++) {
            int row = mBase + wm * 32 + mt * 16 + g + half * 8;
            int dst = scatter_dst(row);
            dsts[mt][half] = dst;
            float s = 0.0f, sq = 0.0f;
#pragma unroll
            for (int nt = 0; nt < 6; nt++) {
                int col = wn * 48 + nt * 8 + tq * 2;
                size_t o = (size_t)dst * Nout + col;
                float2 rv = *(const float2*)(res + o);
                float v0 = acc[mt][nt][half * 2 + 0] + bias[col] + rv.x;
                float v1 = acc[mt][nt][half * 2 + 1] + bias[col + 1] + rv.y;
                acc[mt][nt][half * 2 + 0] = v0;
                acc[mt][nt][half * 2 + 1] = v1;
                float2 w; w.x = v0; w.y = v1;
                *(float2*)(outx + o) = w;
                s += v0 + v1;
                sq += v0 * v0 + v1 * v1;
            }
            // reduce over tq quad (4 lanes share the row within this warp)
            s  += __shfl_xor_sync(0xffffffffu, s, 1);
            s  += __shfl_xor_sync(0xffffffffu, s, 2);
            sq += __shfl_xor_sync(0xffffffffu, sq, 1);
            sq += __shfl_xor_sync(0xffffffffu, sq, 2);
            psum[mt][half] = s;
            psq[mt][half] = sq;
        }
    }
    // cross-warp (4 wn warps per row) partial exchange via smem
    float2* part = (float2*)smem;   // [64 rows][4 wn]
    __syncthreads();
#pragma unroll
    for (int mt = 0; mt < 2; mt++)
#pragma unroll
        for (int half = 0; half < 2; half++) {
            int rloc = wm * 32 + mt * 16 + g + half * 8;
            if (tq == 0) part[rloc * 4 + wn] = make_float2(psum[mt][half], psq[mt][half]);
        }
    __syncthreads();
#pragma unroll
    for (int mt = 0; mt < 2; mt++) {
#pragma unroll
        for (int half = 0; half < 2; half++) {
            int rloc = wm * 32 + mt * 16 + g + half * 8;
            float2 p0 = part[rloc * 4 + 0], p1 = part[rloc * 4 + 1];
            float2 p2 = part[rloc * 4 + 2], p3 = part[rloc * 4 + 3];
            float s = p0.x + p1.x + p2.x + p3.x;
            float sq = p0.y + p1.y + p2.y + p3.y;
            float mean = s * (1.0f / 192.0f);
            float var = sq * (1.0f / 192.0f) - mean * mean;
            float rstd = rsqrtf(var + 1e-5f);
            int dst = dsts[mt][half];
#pragma unroll
            for (int nt = 0; nt < 6; nt++) {
                int col = wn * 48 + nt * 8 + tq * 2;
                float v0 = (acc[mt][nt][half * 2 + 0] - mean) * rstd * gamma[col] + beta[col];
                float v1 = (acc[mt][nt][half * 2 + 1] - mean) * rstd * gamma[col + 1] + beta[col + 1];
                __nv_bfloat162 hp;
                hp.x = __float2bfloat16(v0); hp.y = __float2bfloat16(v1);
                *(__nv_bfloat162*)(outln + (size_t)dst * Nout + col) = hp;
            }
        }
    }
}

// ---------------- Windowed attention (mma.sync, trans-ldsm V, vectorized IO) ----------------
__global__ __launch_bounds__(256)
void attn_kernel(const __nv_bfloat16* __restrict__ qkv,
                 const float* __restrict__ rpb,
                 __nv_bfloat16* __restrict__ oh) {
    extern __shared__ __align__(16) char smem[];
    __shared__ int Ls[49];
    __shared__ int Rs[2][49];

    int tid = threadIdx.x;
    int wid = tid >> 5, lid = tid & 31;
    int ph = wid >> 2;
    int t  = wid & 3;
    int wtid = tid & 127;
    int pair = blockIdx.x * 2 + ph;
    int w = pair / NHEADS;
    int h = pair - w * NHEADS;

    char* sm = smem + ph * PAIR_STRIDE;
    uint32_t sb = smem_u32(smem) + ph * PAIR_STRIDE;
    const float scale = 0.17677669529663687f;

    int r = w & 255;
    int wi = r >> 4, wj = r & 15;

    if (tid < 49) Ls[tid] = 13 * (tid / 7) + tid % 7;
    if (wtid < 49) {
        int i = wtid / 7, j = wtid % 7;
        int hp = wi * 7 + i, wp = wj * 7 + j;
        Rs[ph][wtid] = (hp < 105 ? 0 : (hp < 109 ? 1 : 2)) * 3 + (wp < 105 ? 0 : (wp < 109 ? 1 : 2));
    }

    // vectorized loads: Q,K,V all row-major [n][d] pitch 80, uint4 stores
    for (int idx = wtid; idx < 196; idx += 128) {
        int n = idx >> 2, c = idx & 3;
        size_t base = ((size_t)(w * 49 + n)) * (3 * C_DIM) + h * HDIM + c * 8;
        *(uint4*)(sm + AQ + n * 80 + c * 16) = *(const uint4*)(qkv + base);
        *(uint4*)(sm + AK + n * 80 + c * 16) = *(const uint4*)(qkv + base + C_DIM);
        *(uint4*)(sm + AV + n * 80 + c * 16) = *(const uint4*)(qkv + base + 2 * C_DIM);
    }
    // zero V rows m=49..63 (P pad cols are 0 but 0*NaN = NaN)
    for (int idx = wtid; idx < 60; idx += 128) {
        int n = 49 + idx / 4, c = idx & 3;
        *(uint4*)(sm + AV + n * 80 + c * 16) = make_uint4(0, 0, 0, 0);
    }
    __syncthreads();

    int aRow = t * 16 + (lid & 7) + ((lid >> 3) & 1) * 8;
    int aKof = (lid >> 4) * 16;
    int bRowB = (lid & 7) + ((lid >> 4) & 1) * 8;
    int bKof = ((lid >> 3) & 1) * 16;
    // trans-ldsm lane mapping for V [m][d]: row = k(m) index, col-byte = d half
    int vRow = (lid & 7) + ((lid >> 3) & 1) * 8;
    int vCol = ((lid >> 4) & 1) * 16;
    int g = lid >> 2, tq = lid & 3;

    // ---- S = Q K^T (64x64x32) ----
    {
        float acc[8][4];
#pragma unroll
        for (int a = 0; a < 8; a++)
#pragma unroll
            for (int c = 0; c < 4; c++) acc[a][c] = 0.0f;
#pragma unroll
        for (int kb = 0; kb < 64; kb += 32) {
            uint32_t af[4];
            ldsm_x4(af, sb + AQ + aRow * 80 + kb + aKof);
#pragma unroll
            for (int nb = 0; nb < 4; nb++) {
                uint32_t bf[4];
                ldsm_x4(bf, sb + AK + (bRowB + nb * 16) * 80 + kb + bKof);
                mma16816(acc[2 * nb],     af, bf);
                mma16816(acc[2 * nb + 1], af, bf + 2);
            }
        }
        float* sa = (float*)(sm + ASA);
#pragma unroll
        for (int half = 0; half < 2; half++) {
            int row = t * 16 + g + half * 8;
            if (row < 49) {
                int L0 = Ls[row] + 84, R0 = Rs[ph][row];
#pragma unroll
                for (int nt = 0; nt < 8; nt++) {
                    int col = nt * 8 + tq * 2;
                    if (col < 49) {
#pragma unroll
                        for (int e = 0; e < 2; e++) {
                            int cc = col + e;
                            if (cc < 49) {
                                float vs = acc[nt][half * 2 + e] * scale
                                         + rpb[(L0 - Ls[cc]) * NHEADS + h]
                                         + (R0 == Rs[ph][cc] ? 0.0f : -100.0f);
                                sa[row * 64 + cc] = vs;
                            }
                        }
                    }
                }
            }
        }
    }
    __syncthreads();

    // ---- softmax rows; normalized bf16 P directly into APB ----
    {
        float* sa = (float*)(sm + ASA);
        char* pb = sm + APB;
        for (int n = t; n < 49; n += 4) {
            float v1 = sa[n * 64 + lid];
            float v2 = (lid < 17) ? sa[n * 64 + 32 + lid] : -1e30f;
            float mx = warp_max(fmaxf(v1, v2));
            float e1 = __expf(v1 - mx);
            float e2 = (lid < 17) ? __expf(v2 - mx) : 0.0f;
            float s = warp_sum(e1 + e2);
            float inv = 1.0f / s;
            *(__nv_bfloat16*)(pb + n * 144 + lid * 2) = __float2bfloat16(e1 * inv);
            *(__nv_bfloat16*)(pb + n * 144 + (lid + 32) * 2) =
                __float2bfloat16(lid < 17 ? e2 * inv : 0.0f);
        }
        for (int idx = wtid; idx < 120; idx += 128) {
            int n = 49 + (idx >> 3), c = idx & 7;
            *(uint4*)(pb + n * 144 + c * 16) = make_uint4(0, 0, 0, 0);
        }
    }
    __syncthreads();

    // ---- O = P V (64x32x64), V via trans-ldsm from row-major [m][d] ----
    {
        float acc[4][4];
#pragma unroll
        for (int a = 0; a < 4; a++)
#pragma unroll
            for (int c = 0; c < 4; c++) acc[a][c] = 0.0f;
#pragma unroll
        for (int ks = 0; ks < 4; ks++) {
            int kb = ks * 32;
            uint32_t af[4];
            ldsm_x4(af, sb + APB + aRow * 144 + kb + aKof);
            uint32_t bf0[4], bf1[4];
            uint32_t vbase = sb + AV + (ks * 16 + vRow) * 80 + vCol;
            ldsm_x4_t(bf0, vbase);          // d 0..15
            ldsm_x4_t(bf1, vbase + 32);     // d 16..31
            mma16816(acc[0], af, bf0);
            mma16816(acc[1], af, bf0 + 2);
            mma16816(acc[2], af, bf1);
            mma16816(acc[3], af, bf1 + 2);
        }
#pragma unroll
        for (int half = 0; half < 2; half++) {
            int row = t * 16 + g + half * 8;
            if (row < 49) {
#pragma unroll
                for (int nt = 0; nt < 4; nt++) {
                    int col = nt * 8 + tq * 2;
                    __nv_bfloat162 hp;
                    hp.x = __float2bfloat16(acc[nt][half * 2 + 0]);
                    hp.y = __float2bfloat16(acc[nt][half * 2 + 1]);
                    size_t o = ((size_t)(w * 49 + row)) * C_DIM + h * HDIM + col;
                    *(__nv_bfloat162*)(oh + o) = hp;
                }
            }
        }
    }
}

// ---------------- launch ----------------
extern "C" void kernel_launch(void* const* d_in, const int* in_sizes, int n_in,
                              void* d_out, int out_size) {
    const float* query   = (const float*)d_in[0];
    const float* norm1_g = (const float*)d_in[1];
    const float* norm1_b = (const float*)d_in[2];
    const float* qkv_w   = (const float*)d_in[3];
    const float* qkv_b   = (const float*)d_in[4];
    const float* rpb     = (const float*)d_in[5];
    const float* proj_w  = (const float*)d_in[6];
    const float* proj_b  = (const float*)d_in[7];
    const float* norm2_g = (const float*)d_in[8];
    const float* norm2_b = (const float*)d_in[9];
    const float* fc1_w   = (const float*)d_in[10];
    const float* fc1_b   = (const float*)d_in[11];
    const float* fc2_w   = (const float*)d_in[12];
    const float* fc2_b   = (const float*)d_in[13];
    float* out = (float*)d_out;

    __nv_bfloat16 *xw, *qkvp, *att, *ln2, *hbuf;
    __nv_bfloat16 *wq, *wp, *w1, *w2;
    float *x;
    cudaGetSymbolAddress((void**)&xw, g_xw);
    cudaGetSymbolAddress((void**)&qkvp, g_qkv);
    cudaGetSymbolAddress((void**)&att, g_att);
    cudaGetSymbolAddress((void**)&x, g_x);
    cudaGetSymbolAddress((void**)&ln2, g_ln2);
    cudaGetSymbolAddress((void**)&hbuf, g_h);
    cudaGetSymbolAddress((void**)&wq, g_wqkv);
    cudaGetSymbolAddress((void**)&wp, g_wprj);
    cudaGetSymbolAddress((void**)&w1, g_wfc1);
    cudaGetSymbolAddress((void**)&w2, g_wfc2);

    const int SMEM  = NSTAGE * STAGE_BYTES;  // 61440
    const int SMEM2 = NSTAGE * STAGE2;       // 81920
    cudaFuncSetAttribute(gemm_mma<EPI_BF16>, cudaFuncAttributeMaxDynamicSharedMemorySize, SMEM);
    cudaFuncSetAttribute(gemm_mma<EPI_GELU>, cudaFuncAttributeMaxDynamicSharedMemorySize, SMEM);
    cudaFuncSetAttribute(gemm_proj_ln,       cudaFuncAttributeMaxDynamicSharedMemorySize, SMEM2);
    cudaFuncSetAttribute(gemm_mma_n192<EPI_RES>, cudaFuncAttributeMaxDynamicSharedMemorySize, SMEM2);
    cudaFuncSetAttribute(attn_kernel, cudaFuncAttributeMaxDynamicSharedMemorySize, ATTN_SMEM);

    wprep_all<<<(442368 + 255) / 256, 256>>>(qkv_w, proj_w, fc1_w, fc2_w, wq, wp, w1, w2);

    // 1) LN1 + shift + window partition
    ln_kernel<true><<<M_TOK, 192>>>(query, norm1_g, norm1_b, xw);

    // 2) qkv  [100352,192] x [192,576] -> bf16
    gemm_mma<EPI_BF16><<<dim3(576 / BN, M_TOK / BM), 256, SMEM>>>(
        xw, wq, qkv_b, nullptr, nullptr, qkvp, 192, 576);

    // 3) windowed attention
    attn_kernel<<<2048 * NHEADS / 2, 256, ATTN_SMEM>>>(qkvp, rpb, att);

    // 4) proj + window reverse + unshift + residual(query) + fused LN2
    gemm_proj_ln<<<dim3(1, M_TOK / BM2), 256, SMEM2>>>(
        att, wp, proj_b, query, x, ln2, norm2_g, norm2_b, 192);

    // 5) fc1 + GELU
    gemm_mma<EPI_GELU><<<dim3(768 / BN, M_TOK / BM), 256, SMEM>>>(
        ln2, w1, fc1_b, nullptr, nullptr, hbuf, 192, 768);

    // 6) fc2 + residual(x) -> out
    gemm_mma_n192<EPI_RES><<<dim3(1, M_TOK / BM2), 256, SMEM2>>>(
        hbuf, w2, fc2_b, x, out, 768);
}